// round 5
// baseline (speedup 1.0000x reference)
#include <cuda_runtime.h>
#include <cuda_bf16.h>
#include <math.h>
#include <stdint.h>

#define NB   2048
#define NT   60
#define NDL  100
#define ND   512
#define NH   256

// ---------------- scratch (device globals) ----------------
__device__ float g_h0[NB * ND];
__device__ float g_stats[2 * ND];
__device__ float g_h[NB * ND];
__device__ float g_gates[2][NB * 3 * NH];          // x@Wih^T + bih (fp32)
__device__ float g_sf[2][2][NB * NH];              // fp32 GRU state [dir][pingpong]
__device__ __nv_bfloat16 g_shh[2][2][NB * NH];     // bf16 hi copy of state
__device__ __nv_bfloat16 g_shl[2][2][NB * NH];     // bf16 lo copy of state
__device__ __nv_bfloat16 g_whh[2][3 * NH * NH];    // Whh split hi
__device__ __nv_bfloat16 g_whl[2][3 * NH * NH];    // Whh split lo
__device__ __nv_bfloat16 g_w1h[NH * 2 * NH];       // attn_W1 split hi
__device__ __nv_bfloat16 g_w1l[NH * 2 * NH];       // attn_W1 split lo
__device__ float g_gru[NB * NT * 2 * NH];          // concat(gf,gb) fp32 [B,T,512]
__device__ __nv_bfloat16 g_gruh[NB * NT * 2 * NH]; // gru out bf16 hi
__device__ __nv_bfloat16 g_grul[NB * NT * 2 * NH]; // gru out bf16 lo
__device__ float g_s[NB * NT];
__device__ float g_c[NB * 2 * NH];
__device__ int   g_bar[NT];                        // per-step grid barrier slots

__device__ __forceinline__ void bsplit(float v, __nv_bfloat16& h, __nv_bfloat16& l) {
    h = __float2bfloat16(v);
    l = __float2bfloat16(v - __bfloat162float(h));
}

__device__ __forceinline__ void mma16816(float& d0, float& d1, float& d2, float& d3,
    uint32_t a0, uint32_t a1, uint32_t a2, uint32_t a3, uint32_t b0, uint32_t b1)
{
    asm volatile("mma.sync.aligned.m16n8k16.row.col.f32.bf16.bf16.f32 "
                 "{%0,%1,%2,%3},{%4,%5,%6,%7},{%8,%9},{%0,%1,%2,%3};"
                 : "+f"(d0), "+f"(d1), "+f"(d2), "+f"(d3)
                 : "r"(a0), "r"(a1), "r"(a2), "r"(a3), "r"(b0), "r"(b1));
}

// swizzled smem index: stride 64, XOR 8-col blocks by (row&7). Conflict-free.
__device__ __forceinline__ int swzidx(int r, int c) {
    return r * 64 + ((((c >> 3) ^ (r & 7)) << 3) | (c & 7));
}

// ---------------- prep: split weights, zero barrier ------------------------------
__global__ void __launch_bounds__(256) prep_split(
    const float* __restrict__ Whh_f, const float* __restrict__ Whh_b,
    const float* __restrict__ W1)
{
    int i = blockIdx.x * 256 + threadIdx.x;        // 0 .. 3*NH*NH-1 (196608)
    bsplit(Whh_f[i], g_whh[0][i], g_whl[0][i]);
    bsplit(Whh_b[i], g_whh[1][i], g_whl[1][i]);
    if (i < NH * 2 * NH) bsplit(W1[i], g_w1h[i], g_w1l[i]);
    if (i < NT) g_bar[i] = 0;
}

// ---------------- generic fp32 tiled GEMM (fc + gate precompute) -----------------
__global__ void __launch_bounds__(256) gemm_bias(
    const float* __restrict__ A, const float* __restrict__ Bw,
    const float* __restrict__ bias, float* __restrict__ C,
    int M, int N, int K)
{
    __shared__ float As[16][65];
    __shared__ float Bs[16][65];
    int tid = threadIdx.x;
    int tx = tid & 15, ty = tid >> 4;
    int m0 = blockIdx.y * 64, n0 = blockIdx.x * 64;
    float acc[4][4] = {};
    for (int k0 = 0; k0 < K; k0 += 16) {
        #pragma unroll
        for (int i = 0; i < 4; i++) {
            int lin = tid + i * 256;
            int m = lin >> 4, k = lin & 15;
            As[k][m] = (k0 + k < K) ? A[(m0 + m) * K + k0 + k] : 0.f;
        }
        #pragma unroll
        for (int i = 0; i < 4; i++) {
            int lin = tid + i * 256;
            int n = lin >> 4, k = lin & 15;
            Bs[k][n] = (k0 + k < K) ? Bw[(n0 + n) * K + k0 + k] : 0.f;
        }
        __syncthreads();
        #pragma unroll
        for (int kk = 0; kk < 16; kk++) {
            float a[4], b[4];
            #pragma unroll
            for (int i = 0; i < 4; i++) a[i] = As[kk][ty * 4 + i];
            #pragma unroll
            for (int j = 0; j < 4; j++) b[j] = Bs[kk][tx * 4 + j];
            #pragma unroll
            for (int i = 0; i < 4; i++)
                #pragma unroll
                for (int j = 0; j < 4; j++) acc[i][j] += a[i] * b[j];
        }
        __syncthreads();
    }
    #pragma unroll
    for (int i = 0; i < 4; i++) {
        int m = m0 + ty * 4 + i;
        #pragma unroll
        for (int j = 0; j < 4; j++) {
            int n = n0 + tx * 4 + j;
            C[m * N + n] = acc[i][j] + bias[n];
        }
    }
}

// ---------------- batchnorm ------------------------------------------------------
__global__ void __launch_bounds__(256) bn_stats()
{
    int c = blockIdx.x;
    float s = 0.f, s2 = 0.f;
    for (int r = threadIdx.x; r < NB; r += 256) {
        float v = g_h0[r * ND + c];
        s += v; s2 += v * v;
    }
    __shared__ float sh[256], sh2[256];
    sh[threadIdx.x] = s; sh2[threadIdx.x] = s2;
    __syncthreads();
    for (int o = 128; o > 0; o >>= 1) {
        if (threadIdx.x < o) {
            sh[threadIdx.x]  += sh[threadIdx.x + o];
            sh2[threadIdx.x] += sh2[threadIdx.x + o];
        }
        __syncthreads();
    }
    if (threadIdx.x == 0) {
        float mu = sh[0] / (float)NB;
        g_stats[c] = mu;
        g_stats[ND + c] = sh2[0] / (float)NB - mu * mu;
    }
}

__global__ void __launch_bounds__(256) bn_apply(
    const float* __restrict__ bn_g, const float* __restrict__ bn_b)
{
    int i = blockIdx.x * 256 + threadIdx.x;
    int c = i & (ND - 1);
    float mu = g_stats[c], var = g_stats[ND + c];
    float v = (g_h0[i] - mu) * rsqrtf(var + 1e-5f) * bn_g[c] + bn_b[c];
    g_h[i] = (v >= 0.f) ? v : 0.2f * v;
}

// ---------------- MMA inner block (shared by all phases) -------------------------
__device__ __forceinline__ void mma_block(
    const __nv_bfloat16* __restrict__ As, const __nv_bfloat16* __restrict__ Bs,
    float acc[4][6][4], int wm, int wj, int gID, int tig)
{
    #pragma unroll
    for (int kk = 0; kk < 4; kk++) {
        uint32_t afr[4][4], bfr[6][2];
        const int s0 = kk * 2, s1 = kk * 2 + 1;
        #pragma unroll
        for (int mt = 0; mt < 4; mt++) {
            const int r = wm * 64 + mt * 16 + gID;
            const int x0 = (((s0 ^ (r & 7)) << 3) | (tig * 2));
            const int x1 = (((s1 ^ (r & 7)) << 3) | (tig * 2));
            afr[mt][0] = *(const uint32_t*)(As + r * 64 + x0);
            afr[mt][1] = *(const uint32_t*)(As + (r + 8) * 64 + x0);
            afr[mt][2] = *(const uint32_t*)(As + r * 64 + x1);
            afr[mt][3] = *(const uint32_t*)(As + (r + 8) * 64 + x1);
        }
        #pragma unroll
        for (int g = 0; g < 3; g++)
            #pragma unroll
            for (int jn = 0; jn < 2; jn++) {
                const int r = g * 64 + wj * 16 + jn * 8 + gID;
                const int x0 = (((s0 ^ (r & 7)) << 3) | (tig * 2));
                const int x1 = (((s1 ^ (r & 7)) << 3) | (tig * 2));
                bfr[g * 2 + jn][0] = *(const uint32_t*)(Bs + r * 64 + x0);
                bfr[g * 2 + jn][1] = *(const uint32_t*)(Bs + r * 64 + x1);
            }
        #pragma unroll
        for (int mt = 0; mt < 4; mt++)
            #pragma unroll
            for (int nt = 0; nt < 6; nt++)
                mma16816(acc[mt][nt][0], acc[mt][nt][1],
                         acc[mt][nt][2], acc[mt][nt][3],
                         afr[mt][0], afr[mt][1], afr[mt][2], afr[mt][3],
                         bfr[nt][0], bfr[nt][1]);
    }
}

// ---------------- persistent GRU: all 60 steps in one launch ---------------------
// 128 blocks (1/SM, co-resident by smem). Whh hi/lo resident in smem.
#define SLAB (192 * 64)
__global__ void __launch_bounds__(256) gru_persist(
    const float* __restrict__ bhh_f, const float* __restrict__ bhh_b)
{
    extern __shared__ __nv_bfloat16 smem[];
    __nv_bfloat16* Bsh = smem;                 // 4 slabs x 192 x 64
    __nv_bfloat16* Bsl = smem + 4 * SLAB;
    __nv_bfloat16* As  = smem + 8 * SLAB;      // 128 x 64

    const int bid = blockIdx.x;
    const int dir = bid >> 6;
    const int sub = bid & 63;
    const int j0 = (sub & 3) * 64;
    const int m0 = (sub >> 2) * 128;

    const float* bhh = dir ? bhh_b : bhh_f;
    const float* gin = g_gates[dir];
    const __nv_bfloat16* __restrict__ wh = g_whh[dir];
    const __nv_bfloat16* __restrict__ wl = g_whl[dir];

    const int tid = threadIdx.x;
    const int warp = tid >> 5, lane = tid & 31;
    const int wm = warp >> 2, wj = warp & 3;
    const int gID = lane >> 2, tig = lane & 3;

    // load Whh hi/lo into smem once (swizzled, slab-major)
    #pragma unroll
    for (int i = 0; i < 24; i++) {
        int u = tid + 256 * i;                 // 6144 uint4 per copy
        int r = u >> 5;                        // row 0..191
        int c = (u & 31) * 8;                  // col 0..255
        int slab = c >> 6, cs = c & 63;
        int g = r >> 6, j = j0 + (r & 63);
        *(uint4*)&Bsh[slab * SLAB + swzidx(r, cs)] =
            *(const uint4*)&wh[(g * NH + j) * NH + c];
        *(uint4*)&Bsl[slab * SLAB + swzidx(r, cs)] =
            *(const uint4*)&wl[(g * NH + j) * NH + c];
    }
    __syncthreads();

    for (int t = 0; t < NT; t++) {
        const int src = t & 1, dst = src ^ 1;
        const float* __restrict__ sfs = g_sf[dir][src];
        const __nv_bfloat16* __restrict__ hh = g_shh[dir][src];
        const __nv_bfloat16* __restrict__ hl = g_shl[dir][src];

        float acc[4][6][4];
        #pragma unroll
        for (int a = 0; a < 4; a++)
            #pragma unroll
            for (int b = 0; b < 6; b++)
                #pragma unroll
                for (int q = 0; q < 4; q++) acc[a][b][q] = 0.f;

        if (t > 0) {
            for (int ksl = 0; ksl < 4; ksl++) {
                const int ks = ksl * 64;
                __syncthreads();               // As readers of prev phase done
                #pragma unroll
                for (int i = 0; i < 4; i++) {  // As = hh slab
                    int u = tid + 256 * i;
                    int r = u >> 3, c = (u & 7) * 8;
                    *(uint4*)&As[swzidx(r, c)] =
                        *(const uint4*)&hh[(m0 + r) * NH + ks + c];
                }
                __syncthreads();
                mma_block(As, Bsl + ksl * SLAB, acc, wm, wj, gID, tig);  // hh*wl
                mma_block(As, Bsh + ksl * SLAB, acc, wm, wj, gID, tig);  // hh*wh
                __syncthreads();
                #pragma unroll
                for (int i = 0; i < 4; i++) {  // As = hl slab
                    int u = tid + 256 * i;
                    int r = u >> 3, c = (u & 7) * 8;
                    *(uint4*)&As[swzidx(r, c)] =
                        *(const uint4*)&hl[(m0 + r) * NH + ks + c];
                }
                __syncthreads();
                mma_block(As, Bsh + ksl * SLAB, acc, wm, wj, gID, tig);  // hl*wh
            }
        }

        // epilogue: gates -> h update -> state + outputs
        const int tt = dir ? (NT - 1 - t) : t;
        float* sfd = g_sf[dir][dst];
        __nv_bfloat16* dh = g_shh[dir][dst];
        __nv_bfloat16* dl = g_shl[dir][dst];
        #pragma unroll
        for (int mt = 0; mt < 4; mt++)
            #pragma unroll
            for (int part = 0; part < 2; part++) {
                const int m = m0 + wm * 64 + mt * 16 + gID + part * 8;
                #pragma unroll
                for (int jn = 0; jn < 2; jn++) {
                    const int jg = j0 + wj * 16 + jn * 8 + tig * 2;
                    #pragma unroll
                    for (int cc = 0; cc < 2; cc++) {
                        const int j = jg + cc;
                        float ghr = acc[mt][jn][part * 2 + cc]     + bhh[j];
                        float ghz = acc[mt][2 + jn][part * 2 + cc] + bhh[NH + j];
                        float ghn = acc[mt][4 + jn][part * 2 + cc] + bhh[2 * NH + j];
                        const float* gp = gin + m * 3 * NH + j;
                        float r  = 1.f / (1.f + expf(-(gp[0] + ghr)));
                        float zz = 1.f / (1.f + expf(-(gp[NH] + ghz)));
                        float nn = tanhf(gp[2 * NH] + r * ghn);
                        float hold = (t == 0) ? 0.f : sfs[m * NH + j];
                        float hn = (1.f - zz) * nn + zz * hold;
                        sfd[m * NH + j] = hn;
                        __nv_bfloat16 bh, bl;
                        bsplit(hn, bh, bl);
                        dh[m * NH + j] = bh;
                        dl[m * NH + j] = bl;
                        const int go = (m * NT + tt) * (2 * NH) + dir * NH + j;
                        g_gru[go]  = hn;
                        g_gruh[go] = bh;
                        g_grul[go] = bl;
                    }
                }
            }

        // grid-wide barrier between steps (skip after the last)
        if (t < NT - 1) {
            __syncthreads();
            if (tid == 0) {
                __threadfence();
                atomicAdd(&g_bar[t], 1);
                while (*(volatile int*)&g_bar[t] < 128) { }
                __threadfence();
            }
            __syncthreads();
        }
    }
}

// ---------------- attention scores via bf16-split MMA ----------------------------
__global__ void __launch_bounds__(256) attn_mma(
    const float* __restrict__ b1, const float* __restrict__ W2)
{
    __shared__ __nv_bfloat16 As[64 * 72];
    __shared__ __nv_bfloat16 Bs[256 * 72];
    __shared__ float red[64];

    const int tid = threadIdx.x;
    const int m0 = blockIdx.x * 64;
    const int warp = tid >> 5, lane = tid & 31;
    const int wm = warp >> 2, wj = warp & 3;
    const int gID = lane >> 2, tig = lane & 3;
    if (tid < 64) red[tid] = 0.f;

    float acc[2][8][4];
    #pragma unroll
    for (int a = 0; a < 2; a++)
        #pragma unroll
        for (int b = 0; b < 8; b++)
            #pragma unroll
            for (int q = 0; q < 4; q++) acc[a][b][q] = 0.f;

    for (int it = 0; it < 24; it++) {
        const int ks = (it / 3) * 64;
        const int ph = it % 3;
        const bool loadA = (ph != 1);
        const bool loadB = (ph != 2);
        const __nv_bfloat16* __restrict__ asrc = (ph == 2) ? g_grul : g_gruh;
        const __nv_bfloat16* __restrict__ bsrc = (ph == 0) ? g_w1l : g_w1h;
        if (it > 0) __syncthreads();
        if (loadA) {
            #pragma unroll
            for (int i = 0; i < 2; i++) {
                int u = tid + 256 * i;
                int r = u >> 3, c = (u & 7) << 3;
                *(uint4*)&As[r * 72 + c] =
                    *(const uint4*)&asrc[(m0 + r) * 512 + ks + c];
            }
        }
        if (loadB) {
            #pragma unroll
            for (int i = 0; i < 8; i++) {
                int u = tid + 256 * i;
                int r = u >> 3, c = (u & 7) << 3;
                *(uint4*)&Bs[r * 72 + c] =
                    *(const uint4*)&bsrc[r * 512 + ks + c];
            }
        }
        __syncthreads();
        #pragma unroll
        for (int kk = 0; kk < 4; kk++) {
            const int kb = kk * 16 + tig * 2;
            uint32_t afr[2][4], bfr[8][2];
            #pragma unroll
            for (int mt = 0; mt < 2; mt++) {
                const __nv_bfloat16* p = As + (wm * 32 + mt * 16 + gID) * 72 + kb;
                afr[mt][0] = *(const uint32_t*)p;
                afr[mt][1] = *(const uint32_t*)(p + 8 * 72);
                afr[mt][2] = *(const uint32_t*)(p + 8);
                afr[mt][3] = *(const uint32_t*)(p + 8 * 72 + 8);
            }
            #pragma unroll
            for (int nt = 0; nt < 8; nt++) {
                const __nv_bfloat16* p = Bs + (wj * 64 + nt * 8 + gID) * 72 + kb;
                bfr[nt][0] = *(const uint32_t*)p;
                bfr[nt][1] = *(const uint32_t*)(p + 8);
            }
            #pragma unroll
            for (int mt = 0; mt < 2; mt++)
                #pragma unroll
                for (int nt = 0; nt < 8; nt++)
                    mma16816(acc[mt][nt][0], acc[mt][nt][1],
                             acc[mt][nt][2], acc[mt][nt][3],
                             afr[mt][0], afr[mt][1], afr[mt][2], afr[mt][3],
                             bfr[nt][0], bfr[nt][1]);
        }
    }

    #pragma unroll
    for (int mt = 0; mt < 2; mt++)
        #pragma unroll
        for (int part = 0; part < 2; part++) {
            float s = 0.f;
            #pragma unroll
            for (int nt = 0; nt < 8; nt++)
                #pragma unroll
                for (int cc = 0; cc < 2; cc++) {
                    int n = wj * 64 + nt * 8 + tig * 2 + cc;
                    s += tanhf(acc[mt][nt][part * 2 + cc] + b1[n]) * W2[n];
                }
            s += __shfl_xor_sync(0xffffffffu, s, 1);
            s += __shfl_xor_sync(0xffffffffu, s, 2);
            if (tig == 0)
                atomicAdd(&red[wm * 32 + mt * 16 + gID + part * 8], s);
        }
    __syncthreads();
    if (tid < 64) g_s[m0 + tid] = red[tid];
}

// ---------------- softmax over time + context vector -----------------------------
__global__ void __launch_bounds__(256) softmax_ctx()
{
    int b = blockIdx.x;
    __shared__ float w[NT];
    int tid = threadIdx.x;
    if (tid == 0) {
        float mx = -1e30f;
        for (int t = 0; t < NT; t++) {
            float v = g_s[b * NT + t];
            if (v > mx) mx = v;
            w[t] = v;
        }
        float s = 0.f;
        for (int t = 0; t < NT; t++) { w[t] = expf(w[t] - mx); s += w[t]; }
        float inv = 1.f / s;
        for (int t = 0; t < NT; t++) w[t] *= inv;
    }
    __syncthreads();
    for (int d = tid; d < 2 * NH; d += 256) {
        float s = 0.f;
        for (int t = 0; t < NT; t++)
            s += w[t] * g_gru[(b * NT + t) * (2 * NH) + d];
        g_c[b * 2 * NH + d] = s;
    }
}

// ---------------- joint head + forward kinematics --------------------------------
__global__ void __launch_bounds__(256) joints_fk(
    const float* __restrict__ jW, const float* __restrict__ jb,
    float* __restrict__ out)
{
    int w = blockIdx.x * 8 + (threadIdx.x >> 5);
    int lane = threadIdx.x & 31;
    if (w >= NB * NT) return;
    int b = w / NT;
    const float* row  = &g_gru[w * 512];
    const float* crow = &g_c[b * 512];
    float p[6] = {};
    #pragma unroll
    for (int k = 0; k < 16; k++) {
        int d = lane + k * 32;
        float x = row[d] + crow[d];
        #pragma unroll
        for (int j = 0; j < 6; j++) p[j] += x * jW[j * 512 + d];
    }
    #pragma unroll
    for (int o = 16; o > 0; o >>= 1)
        #pragma unroll
        for (int j = 0; j < 6; j++) p[j] += __shfl_xor_sync(0xffffffffu, p[j], o);
    if (lane != 0) return;

    const float LO[6] = {-3.1416f, -1.5708f, -3.1416f, -2.6f, -1.5708f, -1.2f};
    const float UP[6] = { 3.1416f,  1.5708f,  3.1416f,  0.1f,  1.5708f,  1.2f};
    float th[6];
    #pragma unroll
    for (int j = 0; j < 6; j++)
        th[j] = (p[j] + jb[j]) * (UP[j] - LO[j]) + LO[j];

    float c0[3] = {1.f, 0.f, 0.f}, c1[3] = {0.f, 1.f, 0.f}, c2[3] = {0.f, 0.f, 1.f};
    float px = 0.f, py = 0.f, pz = 0.10f;
    float sh2x = 0.f, sh2y = 0.f, sh2z = 0.10f;

    float c, s, tmp;
    c = cosf(th[0]); s = sinf(th[0]);
    #pragma unroll
    for (int i = 0; i < 3; i++) { tmp = c*c0[i] + s*c1[i]; c1[i] = c*c1[i] - s*c0[i]; c0[i] = tmp; }
    c = cosf(th[1]); s = sinf(th[1]);
    #pragma unroll
    for (int i = 0; i < 3; i++) { tmp = c*c1[i] + s*c2[i]; c2[i] = c*c2[i] - s*c1[i]; c1[i] = tmp; }
    c = cosf(th[2]); s = sinf(th[2]);
    #pragma unroll
    for (int i = 0; i < 3; i++) { tmp = c*c0[i] - s*c2[i]; c2[i] = c*c2[i] + s*c0[i]; c0[i] = tmp; }
    px -= 0.25f * c1[0]; py -= 0.25f * c1[1]; pz -= 0.25f * c1[2];
    float fax = px, fay = py, faz = pz;
    c = cosf(th[3]); s = sinf(th[3]);
    #pragma unroll
    for (int i = 0; i < 3; i++) { tmp = c*c1[i] + s*c2[i]; c2[i] = c*c2[i] - s*c1[i]; c1[i] = tmp; }
    c = cosf(th[4]); s = sinf(th[4]);
    #pragma unroll
    for (int i = 0; i < 3; i++) { tmp = c*c0[i] - s*c2[i]; c2[i] = c*c2[i] + s*c0[i]; c0[i] = tmp; }
    px -= 0.25f * c1[0]; py -= 0.25f * c1[1]; pz -= 0.25f * c1[2];
    float wx = px, wy = py, wz = pz;
    c = cosf(th[5]); s = sinf(th[5]);
    #pragma unroll
    for (int i = 0; i < 3; i++) { tmp = c*c1[i] + s*c2[i]; c2[i] = c*c2[i] - s*c1[i]; c1[i] = tmp; }

    float f1x = wx - 0.08f*c1[0] + 0.02f*c2[0];
    float f1y = wy - 0.08f*c1[1] + 0.02f*c2[1];
    float f1z = wz - 0.08f*c1[2] + 0.02f*c2[2];
    float f4x = wx - 0.08f*c1[0] - 0.02f*c2[0];
    float f4y = wy - 0.08f*c1[1] - 0.02f*c2[1];
    float f4z = wz - 0.08f*c1[2] - 0.02f*c2[2];

    float d1x = sh2x - fax, d1y = sh2y - fay, d1z = sh2z - faz;
    float d2x = wx - fax,   d2y = wy - fay,   d2z = wz - faz;
    float bodyL = 0.5f * (sqrtf(d1x*d1x + d1y*d1y + d1z*d1z)
                        + sqrtf(d2x*d2x + d2y*d2y + d2z*d2z));
    float inv = 1.f / bodyL;

    float* o = out + (long)w * 9;
    o[0] = (wx  - sh2x) * inv; o[1] = (wy  - sh2y) * inv; o[2] = (wz  - sh2z) * inv;
    o[3] = (f1x - sh2x) * inv; o[4] = (f1y - sh2y) * inv; o[5] = (f1z - sh2z) * inv;
    o[6] = (f4x - sh2x) * inv; o[7] = (f4y - sh2y) * inv; o[8] = (f4z - sh2z) * inv;
}

// ---------------- host launcher ---------------------------------------------------
extern "C" void kernel_launch(void* const* d_in, const int* in_sizes, int n_in,
                              void* d_out, int out_size)
{
    const float* z       = (const float*)d_in[0];
    const float* W_fc    = (const float*)d_in[1];
    const float* b_fc    = (const float*)d_in[2];
    const float* bn_g    = (const float*)d_in[3];
    const float* bn_b    = (const float*)d_in[4];
    const float* Wih_f   = (const float*)d_in[5];
    const float* Whh_f   = (const float*)d_in[6];
    const float* bih_f   = (const float*)d_in[7];
    const float* bhh_f   = (const float*)d_in[8];
    const float* Wih_b   = (const float*)d_in[9];
    const float* Whh_b   = (const float*)d_in[10];
    const float* bih_b   = (const float*)d_in[11];
    const float* bhh_b   = (const float*)d_in[12];
    const float* attn_W1 = (const float*)d_in[13];
    const float* attn_b1 = (const float*)d_in[14];
    const float* attn_W2 = (const float*)d_in[15];
    const float* joint_W = (const float*)d_in[16];
    const float* joint_b = (const float*)d_in[17];
    float* out = (float*)d_out;

    void *p_h0, *p_h, *p_gates;
    cudaGetSymbolAddress(&p_h0, g_h0);
    cudaGetSymbolAddress(&p_h, g_h);
    cudaGetSymbolAddress(&p_gates, g_gates);
    float* f_h0 = (float*)p_h0;
    float* f_h = (float*)p_h;
    float* f_gates = (float*)p_gates;

    static int smem_set = 0;
    const int gru_smem = (8 * SLAB + 128 * 64) * 2;   // 212992 bytes
    if (!smem_set) {
        cudaFuncSetAttribute(gru_persist,
            cudaFuncAttributeMaxDynamicSharedMemorySize, gru_smem);
        smem_set = 1;
    }

    // 0) split weights + zero barrier
    prep_split<<<3 * NH * NH / 256, 256>>>(Whh_f, Whh_b, attn_W1);
    // 1) fc
    gemm_bias<<<dim3(ND / 64, NB / 64), 256>>>(z, W_fc, b_fc, f_h0, NB, ND, NDL);
    // 2-3) batchnorm + leaky relu
    bn_stats<<<ND, 256>>>();
    bn_apply<<<NB * ND / 256, 256>>>(bn_g, bn_b);
    // 4) input-gate precompute
    gemm_bias<<<dim3(3 * NH / 64, NB / 64), 256>>>(f_h, Wih_f, bih_f, f_gates,               NB, 3 * NH, ND);
    gemm_bias<<<dim3(3 * NH / 64, NB / 64), 256>>>(f_h, Wih_b, bih_b, f_gates + NB * 3 * NH, NB, 3 * NH, ND);
    // 5) GRU recurrence: persistent kernel, weights in smem, grid barrier per step
    gru_persist<<<128, 256, gru_smem>>>(bhh_f, bhh_b);
    // 6) attention scores (tensor cores)
    attn_mma<<<NB * NT / 64, 256>>>(attn_b1, attn_W2);
    // 7) softmax + context
    softmax_ctx<<<NB, 256>>>();
    // 8) joint head + FK
    joints_fk<<<NB * NT / 8, 256>>>(joint_W, joint_b, out);
}

// round 6
// speedup vs baseline: 1.3102x; 1.3102x over previous
#include <cuda_runtime.h>
#include <cuda_bf16.h>
#include <math.h>
#include <stdint.h>

#define NB   2048
#define NT   60
#define NDL  100
#define ND   512
#define NH   256

// ---------------- scratch (device globals) ----------------
__device__ float g_h0[NB * ND];
__device__ float g_stats[2 * ND];
__device__ float g_h[NB * ND];
__device__ float g_gates[2][NB * 3 * NH];          // x@Wih^T + bih (fp32)
__device__ float g_sf[2][2][NB * NH];              // fp32 GRU state [dir][pingpong]
__device__ __nv_bfloat16 g_shh[2][2][NB * NH];     // bf16 hi copy of state
__device__ __nv_bfloat16 g_shl[2][2][NB * NH];     // bf16 lo copy of state
__device__ __nv_bfloat16 g_whh[2][3 * NH * NH];    // Whh split hi
__device__ __nv_bfloat16 g_whl[2][3 * NH * NH];    // Whh split lo
__device__ __nv_bfloat16 g_w1h[NH * 2 * NH];       // attn_W1 split hi
__device__ __nv_bfloat16 g_w1l[NH * 2 * NH];       // attn_W1 split lo
__device__ float g_gru[NB * NT * 2 * NH];          // concat(gf,gb) fp32 [B,T,512]
__device__ __nv_bfloat16 g_gruh[NB * NT * 2 * NH]; // gru out bf16 hi
__device__ __nv_bfloat16 g_grul[NB * NT * 2 * NH]; // gru out bf16 lo
__device__ float g_s[NB * NT];
__device__ float g_c[NB * 2 * NH];
__device__ int   g_bar[NT];                        // per-step grid barrier slots

__device__ __forceinline__ void bsplit(float v, __nv_bfloat16& h, __nv_bfloat16& l) {
    h = __float2bfloat16(v);
    l = __float2bfloat16(v - __bfloat162float(h));
}

__device__ __forceinline__ void mma16816(float& d0, float& d1, float& d2, float& d3,
    uint32_t a0, uint32_t a1, uint32_t a2, uint32_t a3, uint32_t b0, uint32_t b1)
{
    asm volatile("mma.sync.aligned.m16n8k16.row.col.f32.bf16.bf16.f32 "
                 "{%0,%1,%2,%3},{%4,%5,%6,%7},{%8,%9},{%0,%1,%2,%3};"
                 : "+f"(d0), "+f"(d1), "+f"(d2), "+f"(d3)
                 : "r"(a0), "r"(a1), "r"(a2), "r"(a3), "r"(b0), "r"(b1));
}

__device__ __forceinline__ void cpasync16(void* sdst, const void* gsrc) {
    uint32_t s = (uint32_t)__cvta_generic_to_shared(sdst);
    asm volatile("cp.async.cg.shared.global [%0], [%1], 16;" :: "r"(s), "l"(gsrc));
}
#define CP_COMMIT() asm volatile("cp.async.commit_group;")
#define CP_WAIT0()  asm volatile("cp.async.wait_group 0;")

__device__ __forceinline__ float fsig(float x) {
    return __fdividef(1.f, 1.f + __expf(-x));
}
__device__ __forceinline__ float ftanh_exp(float x) {   // accurate-ish fast tanh
    return 1.f - __fdividef(2.f, __expf(2.f * x) + 1.f);
}
__device__ __forceinline__ float ftanh_hw(float x) {    // MUFU.TANH (attn only)
    float r;
    asm("tanh.approx.f32 %0, %1;" : "=f"(r) : "f"(x));
    return r;
}

// swizzled smem index: stride 64, XOR 8-col blocks by (row&7). Conflict-free.
__device__ __forceinline__ int swzidx(int r, int c) {
    return r * 64 + ((((c >> 3) ^ (r & 7)) << 3) | (c & 7));
}

// ---------------- prep: split weights, zero barrier ------------------------------
__global__ void __launch_bounds__(256) prep_split(
    const float* __restrict__ Whh_f, const float* __restrict__ Whh_b,
    const float* __restrict__ W1)
{
    int i = blockIdx.x * 256 + threadIdx.x;
    bsplit(Whh_f[i], g_whh[0][i], g_whl[0][i]);
    bsplit(Whh_b[i], g_whh[1][i], g_whl[1][i]);
    if (i < NH * 2 * NH) bsplit(W1[i], g_w1h[i], g_w1l[i]);
    if (i < NT) g_bar[i] = 0;
}

// ---------------- generic fp32 tiled GEMM (fc) -----------------------------------
__global__ void __launch_bounds__(256) gemm_bias(
    const float* __restrict__ A, const float* __restrict__ Bw,
    const float* __restrict__ bias, float* __restrict__ C,
    int M, int N, int K)
{
    __shared__ float As[16][65];
    __shared__ float Bs[16][65];
    int tid = threadIdx.x;
    int tx = tid & 15, ty = tid >> 4;
    int m0 = blockIdx.y * 64, n0 = blockIdx.x * 64;
    float acc[4][4] = {};
    for (int k0 = 0; k0 < K; k0 += 16) {
        #pragma unroll
        for (int i = 0; i < 4; i++) {
            int lin = tid + i * 256;
            int m = lin >> 4, k = lin & 15;
            As[k][m] = (k0 + k < K) ? A[(m0 + m) * K + k0 + k] : 0.f;
        }
        #pragma unroll
        for (int i = 0; i < 4; i++) {
            int lin = tid + i * 256;
            int n = lin >> 4, k = lin & 15;
            Bs[k][n] = (k0 + k < K) ? Bw[(n0 + n) * K + k0 + k] : 0.f;
        }
        __syncthreads();
        #pragma unroll
        for (int kk = 0; kk < 16; kk++) {
            float a[4], b[4];
            #pragma unroll
            for (int i = 0; i < 4; i++) a[i] = As[kk][ty * 4 + i];
            #pragma unroll
            for (int j = 0; j < 4; j++) b[j] = Bs[kk][tx * 4 + j];
            #pragma unroll
            for (int i = 0; i < 4; i++)
                #pragma unroll
                for (int j = 0; j < 4; j++) acc[i][j] += a[i] * b[j];
        }
        __syncthreads();
    }
    #pragma unroll
    for (int i = 0; i < 4; i++) {
        int m = m0 + ty * 4 + i;
        #pragma unroll
        for (int j = 0; j < 4; j++) {
            int n = n0 + tx * 4 + j;
            C[m * N + n] = acc[i][j] + bias[n];
        }
    }
}

// ---- dual-direction gate GEMM: z selects (Wih_f|Wih_b), one launch -------------
__global__ void __launch_bounds__(256) gemm_gates(
    const float* __restrict__ A,
    const float* __restrict__ Wf, const float* __restrict__ bf,
    const float* __restrict__ Wb, const float* __restrict__ bb)
{
    const float* Bw   = blockIdx.z ? Wb : Wf;
    const float* bias = blockIdx.z ? bb : bf;
    float* C = g_gates[blockIdx.z];
    const int M = NB, N = 3 * NH, K = ND;
    __shared__ float As[16][65];
    __shared__ float Bs[16][65];
    int tid = threadIdx.x;
    int tx = tid & 15, ty = tid >> 4;
    int m0 = blockIdx.y * 64, n0 = blockIdx.x * 64;
    float acc[4][4] = {};
    for (int k0 = 0; k0 < K; k0 += 16) {
        #pragma unroll
        for (int i = 0; i < 4; i++) {
            int lin = tid + i * 256;
            int m = lin >> 4, k = lin & 15;
            As[k][m] = A[(m0 + m) * K + k0 + k];
        }
        #pragma unroll
        for (int i = 0; i < 4; i++) {
            int lin = tid + i * 256;
            int n = lin >> 4, k = lin & 15;
            Bs[k][n] = Bw[(n0 + n) * K + k0 + k];
        }
        __syncthreads();
        #pragma unroll
        for (int kk = 0; kk < 16; kk++) {
            float a[4], b[4];
            #pragma unroll
            for (int i = 0; i < 4; i++) a[i] = As[kk][ty * 4 + i];
            #pragma unroll
            for (int j = 0; j < 4; j++) b[j] = Bs[kk][tx * 4 + j];
            #pragma unroll
            for (int i = 0; i < 4; i++)
                #pragma unroll
                for (int j = 0; j < 4; j++) acc[i][j] += a[i] * b[j];
        }
        __syncthreads();
    }
    #pragma unroll
    for (int i = 0; i < 4; i++) {
        int m = m0 + ty * 4 + i;
        #pragma unroll
        for (int j = 0; j < 4; j++) {
            int n = n0 + tx * 4 + j;
            C[m * N + n] = acc[i][j] + bias[n];
        }
    }
}

// ---------------- batchnorm ------------------------------------------------------
__global__ void __launch_bounds__(256) bn_stats()
{
    int c = blockIdx.x;
    float s = 0.f, s2 = 0.f;
    for (int r = threadIdx.x; r < NB; r += 256) {
        float v = g_h0[r * ND + c];
        s += v; s2 += v * v;
    }
    __shared__ float sh[256], sh2[256];
    sh[threadIdx.x] = s; sh2[threadIdx.x] = s2;
    __syncthreads();
    for (int o = 128; o > 0; o >>= 1) {
        if (threadIdx.x < o) {
            sh[threadIdx.x]  += sh[threadIdx.x + o];
            sh2[threadIdx.x] += sh2[threadIdx.x + o];
        }
        __syncthreads();
    }
    if (threadIdx.x == 0) {
        float mu = sh[0] / (float)NB;
        g_stats[c] = mu;
        g_stats[ND + c] = sh2[0] / (float)NB - mu * mu;
    }
}

__global__ void __launch_bounds__(256) bn_apply(
    const float* __restrict__ bn_g, const float* __restrict__ bn_b)
{
    int i = blockIdx.x * 256 + threadIdx.x;
    int c = i & (ND - 1);
    float mu = g_stats[c], var = g_stats[ND + c];
    float v = (g_h0[i] - mu) * rsqrtf(var + 1e-5f) * bn_g[c] + bn_b[c];
    g_h[i] = (v >= 0.f) ? v : 0.2f * v;
}

// ---------------- MMA inner block ------------------------------------------------
__device__ __forceinline__ void mma_block(
    const __nv_bfloat16* __restrict__ As, const __nv_bfloat16* __restrict__ Bs,
    float acc[4][6][4], int wm, int wj, int gID, int tig)
{
    #pragma unroll
    for (int kk = 0; kk < 4; kk++) {
        uint32_t afr[4][4], bfr[6][2];
        const int s0 = kk * 2, s1 = kk * 2 + 1;
        #pragma unroll
        for (int mt = 0; mt < 4; mt++) {
            const int r = wm * 64 + mt * 16 + gID;
            const int x0 = (((s0 ^ (r & 7)) << 3) | (tig * 2));
            const int x1 = (((s1 ^ (r & 7)) << 3) | (tig * 2));
            afr[mt][0] = *(const uint32_t*)(As + r * 64 + x0);
            afr[mt][1] = *(const uint32_t*)(As + (r + 8) * 64 + x0);
            afr[mt][2] = *(const uint32_t*)(As + r * 64 + x1);
            afr[mt][3] = *(const uint32_t*)(As + (r + 8) * 64 + x1);
        }
        #pragma unroll
        for (int g = 0; g < 3; g++)
            #pragma unroll
            for (int jn = 0; jn < 2; jn++) {
                const int r = g * 64 + wj * 16 + jn * 8 + gID;
                const int x0 = (((s0 ^ (r & 7)) << 3) | (tig * 2));
                const int x1 = (((s1 ^ (r & 7)) << 3) | (tig * 2));
                bfr[g * 2 + jn][0] = *(const uint32_t*)(Bs + r * 64 + x0);
                bfr[g * 2 + jn][1] = *(const uint32_t*)(Bs + r * 64 + x1);
            }
        #pragma unroll
        for (int mt = 0; mt < 4; mt++)
            #pragma unroll
            for (int nt = 0; nt < 6; nt++)
                mma16816(acc[mt][nt][0], acc[mt][nt][1],
                         acc[mt][nt][2], acc[mt][nt][3],
                         afr[mt][0], afr[mt][1], afr[mt][2], afr[mt][3],
                         bfr[nt][0], bfr[nt][1]);
    }
}

// ---------------- persistent GRU -------------------------------------------------
#define SLAB (192 * 64)
#define ATILE (128 * 64)
__global__ void __launch_bounds__(256) gru_persist(
    const float* __restrict__ bhh_f, const float* __restrict__ bhh_b)
{
    extern __shared__ __nv_bfloat16 smem[];
    __nv_bfloat16* Bsh = smem;                 // 4 slabs x 192 x 64
    __nv_bfloat16* Bsl = smem + 4 * SLAB;
    __nv_bfloat16* A0  = smem + 8 * SLAB;      // double-buffered state slabs
    __nv_bfloat16* A1  = A0 + ATILE;

    const int bid = blockIdx.x;
    const int dir = bid >> 6;
    const int sub = bid & 63;
    const int j0 = (sub & 3) * 64;
    const int m0 = (sub >> 2) * 128;

    const float* bhh = dir ? bhh_b : bhh_f;
    const float* gin = g_gates[dir];
    const __nv_bfloat16* __restrict__ wh = g_whh[dir];
    const __nv_bfloat16* __restrict__ wl = g_whl[dir];

    const int tid = threadIdx.x;
    const int warp = tid >> 5, lane = tid & 31;
    const int wm = warp >> 2, wj = warp & 3;
    const int gID = lane >> 2, tig = lane & 3;

    // per-thread A-load coords (4 x 16B chunks)
    int lr[4], lc[4];
    #pragma unroll
    for (int i = 0; i < 4; i++) {
        int u = tid + 256 * i;
        lr[i] = u >> 3; lc[i] = (u & 7) * 8;
    }

    // load Whh hi/lo into smem once
    #pragma unroll
    for (int i = 0; i < 24; i++) {
        int u = tid + 256 * i;
        int r = u >> 5;
        int c = (u & 31) * 8;
        int slab = c >> 6, cs = c & 63;
        int g = r >> 6, j = j0 + (r & 63);
        *(uint4*)&Bsh[slab * SLAB + swzidx(r, cs)] =
            *(const uint4*)&wh[(g * NH + j) * NH + c];
        *(uint4*)&Bsl[slab * SLAB + swzidx(r, cs)] =
            *(const uint4*)&wl[(g * NH + j) * NH + c];
    }
    __syncthreads();

    for (int t = 0; t < NT; t++) {
        const int src = t & 1, dst = src ^ 1;
        const float* __restrict__ sfs = g_sf[dir][src];
        const __nv_bfloat16* __restrict__ hh = g_shh[dir][src];
        const __nv_bfloat16* __restrict__ hl = g_shl[dir][src];

        float acc[4][6][4];
        #pragma unroll
        for (int a = 0; a < 4; a++)
            #pragma unroll
            for (int b = 0; b < 6; b++)
                #pragma unroll
                for (int q = 0; q < 4; q++) acc[a][b][q] = 0.f;

        if (t > 0) {
            // prefetch hh slab 0
            #pragma unroll
            for (int i = 0; i < 4; i++)
                cpasync16(&A0[swzidx(lr[i], lc[i])], &hh[(m0 + lr[i]) * NH + lc[i]]);
            CP_COMMIT();
            for (int ksl = 0; ksl < 4; ksl++) {
                const int ks = ksl * 64;
                CP_WAIT0(); __syncthreads();           // hh@A0 ready, A1 mma done
                #pragma unroll
                for (int i = 0; i < 4; i++)            // hl -> A1 (overlaps mma)
                    cpasync16(&A1[swzidx(lr[i], lc[i])],
                              &hl[(m0 + lr[i]) * NH + ks + lc[i]]);
                CP_COMMIT();
                mma_block(A0, Bsl + ksl * SLAB, acc, wm, wj, gID, tig);  // hh*wl
                mma_block(A0, Bsh + ksl * SLAB, acc, wm, wj, gID, tig);  // hh*wh
                CP_WAIT0(); __syncthreads();           // hl ready, A0 mma done
                if (ksl < 3) {
                    #pragma unroll
                    for (int i = 0; i < 4; i++)        // next hh -> A0 (overlaps)
                        cpasync16(&A0[swzidx(lr[i], lc[i])],
                                  &hh[(m0 + lr[i]) * NH + ks + 64 + lc[i]]);
                    CP_COMMIT();
                }
                mma_block(A1, Bsh + ksl * SLAB, acc, wm, wj, gID, tig);  // hl*wh
            }
        }

        // epilogue: gates -> h update -> state + outputs (fast math)
        const int tt = dir ? (NT - 1 - t) : t;
        float* sfd = g_sf[dir][dst];
        __nv_bfloat16* dh = g_shh[dir][dst];
        __nv_bfloat16* dl = g_shl[dir][dst];
        #pragma unroll
        for (int mt = 0; mt < 4; mt++)
            #pragma unroll
            for (int part = 0; part < 2; part++) {
                const int m = m0 + wm * 64 + mt * 16 + gID + part * 8;
                #pragma unroll
                for (int jn = 0; jn < 2; jn++) {
                    const int jg = j0 + wj * 16 + jn * 8 + tig * 2;
                    #pragma unroll
                    for (int cc = 0; cc < 2; cc++) {
                        const int j = jg + cc;
                        float ghr = acc[mt][jn][part * 2 + cc]     + bhh[j];
                        float ghz = acc[mt][2 + jn][part * 2 + cc] + bhh[NH + j];
                        float ghn = acc[mt][4 + jn][part * 2 + cc] + bhh[2 * NH + j];
                        const float* gp = gin + m * 3 * NH + j;
                        float r  = fsig(gp[0] + ghr);
                        float zz = fsig(gp[NH] + ghz);
                        float nn = ftanh_exp(gp[2 * NH] + r * ghn);
                        float hold = (t == 0) ? 0.f : sfs[m * NH + j];
                        float hn = (1.f - zz) * nn + zz * hold;
                        sfd[m * NH + j] = hn;
                        __nv_bfloat16 bh, bl;
                        bsplit(hn, bh, bl);
                        dh[m * NH + j] = bh;
                        dl[m * NH + j] = bl;
                        const int go = (m * NT + tt) * (2 * NH) + dir * NH + j;
                        g_gru[go]  = hn;
                        g_gruh[go] = bh;
                        g_grul[go] = bl;
                    }
                }
            }

        if (t < NT - 1) {
            __syncthreads();
            if (tid == 0) {
                __threadfence();
                atomicAdd(&g_bar[t], 1);
                while (*(volatile int*)&g_bar[t] < 128) { }
                __threadfence();
            }
            __syncthreads();
        }
    }
}

// ---------------- attention scores via bf16-split MMA ----------------------------
__global__ void __launch_bounds__(256) attn_mma(
    const float* __restrict__ b1, const float* __restrict__ W2)
{
    __shared__ __nv_bfloat16 As[64 * 72];
    __shared__ __nv_bfloat16 Bs[256 * 72];
    __shared__ float red[64];

    const int tid = threadIdx.x;
    const int m0 = blockIdx.x * 64;
    const int warp = tid >> 5, lane = tid & 31;
    const int wm = warp >> 2, wj = warp & 3;
    const int gID = lane >> 2, tig = lane & 3;
    if (tid < 64) red[tid] = 0.f;

    float acc[2][8][4];
    #pragma unroll
    for (int a = 0; a < 2; a++)
        #pragma unroll
        for (int b = 0; b < 8; b++)
            #pragma unroll
            for (int q = 0; q < 4; q++) acc[a][b][q] = 0.f;

    for (int it = 0; it < 24; it++) {
        const int ks = (it / 3) * 64;
        const int ph = it % 3;
        const bool loadA = (ph != 1);
        const bool loadB = (ph != 2);
        const __nv_bfloat16* __restrict__ asrc = (ph == 2) ? g_grul : g_gruh;
        const __nv_bfloat16* __restrict__ bsrc = (ph == 0) ? g_w1l : g_w1h;
        if (it > 0) __syncthreads();
        if (loadA) {
            #pragma unroll
            for (int i = 0; i < 2; i++) {
                int u = tid + 256 * i;
                int r = u >> 3, c = (u & 7) << 3;
                *(uint4*)&As[r * 72 + c] =
                    *(const uint4*)&asrc[(m0 + r) * 512 + ks + c];
            }
        }
        if (loadB) {
            #pragma unroll
            for (int i = 0; i < 8; i++) {
                int u = tid + 256 * i;
                int r = u >> 3, c = (u & 7) << 3;
                *(uint4*)&Bs[r * 72 + c] =
                    *(const uint4*)&bsrc[r * 512 + ks + c];
            }
        }
        __syncthreads();
        #pragma unroll
        for (int kk = 0; kk < 4; kk++) {
            const int kb = kk * 16 + tig * 2;
            uint32_t afr[2][4], bfr[8][2];
            #pragma unroll
            for (int mt = 0; mt < 2; mt++) {
                const __nv_bfloat16* p = As + (wm * 32 + mt * 16 + gID) * 72 + kb;
                afr[mt][0] = *(const uint32_t*)p;
                afr[mt][1] = *(const uint32_t*)(p + 8 * 72);
                afr[mt][2] = *(const uint32_t*)(p + 8);
                afr[mt][3] = *(const uint32_t*)(p + 8 * 72 + 8);
            }
            #pragma unroll
            for (int nt = 0; nt < 8; nt++) {
                const __nv_bfloat16* p = Bs + (wj * 64 + nt * 8 + gID) * 72 + kb;
                bfr[nt][0] = *(const uint32_t*)p;
                bfr[nt][1] = *(const uint32_t*)(p + 8);
            }
            #pragma unroll
            for (int mt = 0; mt < 2; mt++)
                #pragma unroll
                for (int nt = 0; nt < 8; nt++)
                    mma16816(acc[mt][nt][0], acc[mt][nt][1],
                             acc[mt][nt][2], acc[mt][nt][3],
                             afr[mt][0], afr[mt][1], afr[mt][2], afr[mt][3],
                             bfr[nt][0], bfr[nt][1]);
        }
    }

    #pragma unroll
    for (int mt = 0; mt < 2; mt++)
        #pragma unroll
        for (int part = 0; part < 2; part++) {
            float s = 0.f;
            #pragma unroll
            for (int nt = 0; nt < 8; nt++)
                #pragma unroll
                for (int cc = 0; cc < 2; cc++) {
                    int n = wj * 64 + nt * 8 + tig * 2 + cc;
                    s += ftanh_hw(acc[mt][nt][part * 2 + cc] + b1[n]) * W2[n];
                }
            s += __shfl_xor_sync(0xffffffffu, s, 1);
            s += __shfl_xor_sync(0xffffffffu, s, 2);
            if (tig == 0)
                atomicAdd(&red[wm * 32 + mt * 16 + gID + part * 8], s);
        }
    __syncthreads();
    if (tid < 64) g_s[m0 + tid] = red[tid];
}

// ---------------- softmax over time + context vector -----------------------------
__global__ void __launch_bounds__(256) softmax_ctx()
{
    int b = blockIdx.x;
    __shared__ float w[NT];
    int tid = threadIdx.x;
    if (tid == 0) {
        float mx = -1e30f;
        for (int t = 0; t < NT; t++) {
            float v = g_s[b * NT + t];
            if (v > mx) mx = v;
            w[t] = v;
        }
        float s = 0.f;
        for (int t = 0; t < NT; t++) { w[t] = __expf(w[t] - mx); s += w[t]; }
        float inv = __fdividef(1.f, s);
        for (int t = 0; t < NT; t++) w[t] *= inv;
    }
    __syncthreads();
    for (int d = tid; d < 2 * NH; d += 256) {
        float s = 0.f;
        for (int t = 0; t < NT; t++)
            s += w[t] * g_gru[(b * NT + t) * (2 * NH) + d];
        g_c[b * 2 * NH + d] = s;
    }
}

// ---------------- joint head + forward kinematics --------------------------------
__global__ void __launch_bounds__(256) joints_fk(
    const float* __restrict__ jW, const float* __restrict__ jb,
    float* __restrict__ out)
{
    int w = blockIdx.x * 8 + (threadIdx.x >> 5);
    int lane = threadIdx.x & 31;
    if (w >= NB * NT) return;
    int b = w / NT;
    const float* row  = &g_gru[w * 512];
    const float* crow = &g_c[b * 512];
    float p[6] = {};
    #pragma unroll
    for (int k = 0; k < 16; k++) {
        int d = lane + k * 32;
        float x = row[d] + crow[d];
        #pragma unroll
        for (int j = 0; j < 6; j++) p[j] += x * jW[j * 512 + d];
    }
    #pragma unroll
    for (int o = 16; o > 0; o >>= 1)
        #pragma unroll
        for (int j = 0; j < 6; j++) p[j] += __shfl_xor_sync(0xffffffffu, p[j], o);
    if (lane != 0) return;

    const float LO[6] = {-3.1416f, -1.5708f, -3.1416f, -2.6f, -1.5708f, -1.2f};
    const float UP[6] = { 3.1416f,  1.5708f,  3.1416f,  0.1f,  1.5708f,  1.2f};
    float th[6];
    #pragma unroll
    for (int j = 0; j < 6; j++)
        th[j] = (p[j] + jb[j]) * (UP[j] - LO[j]) + LO[j];

    float c0[3] = {1.f, 0.f, 0.f}, c1[3] = {0.f, 1.f, 0.f}, c2[3] = {0.f, 0.f, 1.f};
    float px = 0.f, py = 0.f, pz = 0.10f;
    float sh2x = 0.f, sh2y = 0.f, sh2z = 0.10f;

    float c, s, tmp;
    c = cosf(th[0]); s = sinf(th[0]);
    #pragma unroll
    for (int i = 0; i < 3; i++) { tmp = c*c0[i] + s*c1[i]; c1[i] = c*c1[i] - s*c0[i]; c0[i] = tmp; }
    c = cosf(th[1]); s = sinf(th[1]);
    #pragma unroll
    for (int i = 0; i < 3; i++) { tmp = c*c1[i] + s*c2[i]; c2[i] = c*c2[i] - s*c1[i]; c1[i] = tmp; }
    c = cosf(th[2]); s = sinf(th[2]);
    #pragma unroll
    for (int i = 0; i < 3; i++) { tmp = c*c0[i] - s*c2[i]; c2[i] = c*c2[i] + s*c0[i]; c0[i] = tmp; }
    px -= 0.25f * c1[0]; py -= 0.25f * c1[1]; pz -= 0.25f * c1[2];
    float fax = px, fay = py, faz = pz;
    c = cosf(th[3]); s = sinf(th[3]);
    #pragma unroll
    for (int i = 0; i < 3; i++) { tmp = c*c1[i] + s*c2[i]; c2[i] = c*c2[i] - s*c1[i]; c1[i] = tmp; }
    c = cosf(th[4]); s = sinf(th[4]);
    #pragma unroll
    for (int i = 0; i < 3; i++) { tmp = c*c0[i] - s*c2[i]; c2[i] = c*c2[i] + s*c0[i]; c0[i] = tmp; }
    px -= 0.25f * c1[0]; py -= 0.25f * c1[1]; pz -= 0.25f * c1[2];
    float wx = px, wy = py, wz = pz;
    c = cosf(th[5]); s = sinf(th[5]);
    #pragma unroll
    for (int i = 0; i < 3; i++) { tmp = c*c1[i] + s*c2[i]; c2[i] = c*c2[i] - s*c1[i]; c1[i] = tmp; }

    float f1x = wx - 0.08f*c1[0] + 0.02f*c2[0];
    float f1y = wy - 0.08f*c1[1] + 0.02f*c2[1];
    float f1z = wz - 0.08f*c1[2] + 0.02f*c2[2];
    float f4x = wx - 0.08f*c1[0] - 0.02f*c2[0];
    float f4y = wy - 0.08f*c1[1] - 0.02f*c2[1];
    float f4z = wz - 0.08f*c1[2] - 0.02f*c2[2];

    float d1x = sh2x - fax, d1y = sh2y - fay, d1z = sh2z - faz;
    float d2x = wx - fax,   d2y = wy - fay,   d2z = wz - faz;
    float bodyL = 0.5f * (sqrtf(d1x*d1x + d1y*d1y + d1z*d1z)
                        + sqrtf(d2x*d2x + d2y*d2y + d2z*d2z));
    float inv = 1.f / bodyL;

    float* o = out + (long)w * 9;
    o[0] = (wx  - sh2x) * inv; o[1] = (wy  - sh2y) * inv; o[2] = (wz  - sh2z) * inv;
    o[3] = (f1x - sh2x) * inv; o[4] = (f1y - sh2y) * inv; o[5] = (f1z - sh2z) * inv;
    o[6] = (f4x - sh2x) * inv; o[7] = (f4y - sh2y) * inv; o[8] = (f4z - sh2z) * inv;
}

// ---------------- host launcher ---------------------------------------------------
extern "C" void kernel_launch(void* const* d_in, const int* in_sizes, int n_in,
                              void* d_out, int out_size)
{
    const float* z       = (const float*)d_in[0];
    const float* W_fc    = (const float*)d_in[1];
    const float* b_fc    = (const float*)d_in[2];
    const float* bn_g    = (const float*)d_in[3];
    const float* bn_b    = (const float*)d_in[4];
    const float* Wih_f   = (const float*)d_in[5];
    const float* Whh_f   = (const float*)d_in[6];
    const float* bih_f   = (const float*)d_in[7];
    const float* bhh_f   = (const float*)d_in[8];
    const float* Wih_b   = (const float*)d_in[9];
    const float* Whh_b   = (const float*)d_in[10];
    const float* bih_b   = (const float*)d_in[11];
    const float* bhh_b   = (const float*)d_in[12];
    const float* attn_W1 = (const float*)d_in[13];
    const float* attn_b1 = (const float*)d_in[14];
    const float* attn_W2 = (const float*)d_in[15];
    const float* joint_W = (const float*)d_in[16];
    const float* joint_b = (const float*)d_in[17];
    float* out = (float*)d_out;

    void *p_h0, *p_h;
    cudaGetSymbolAddress(&p_h0, g_h0);
    cudaGetSymbolAddress(&p_h, g_h);
    float* f_h0 = (float*)p_h0;
    float* f_h = (float*)p_h;

    static int smem_set = 0;
    const int gru_smem = (8 * SLAB + 2 * ATILE) * 2;   // 229376 bytes
    if (!smem_set) {
        cudaFuncSetAttribute(gru_persist,
            cudaFuncAttributeMaxDynamicSharedMemorySize, gru_smem);
        smem_set = 1;
    }

    // 1) split weights + zero barrier
    prep_split<<<3 * NH * NH / 256, 256>>>(Whh_f, Whh_b, attn_W1);
    // 2) fc
    gemm_bias<<<dim3(ND / 64, NB / 64), 256>>>(z, W_fc, b_fc, f_h0, NB, ND, NDL);
    // 3-4) batchnorm + leaky relu
    bn_stats<<<ND, 256>>>();
    bn_apply<<<NB * ND / 256, 256>>>(bn_g, bn_b);
    // 5) input-gate precompute, both dirs in one launch
    gemm_gates<<<dim3(3 * NH / 64, NB / 64, 2), 256>>>(f_h, Wih_f, bih_f, Wih_b, bih_b);
    // 6) GRU recurrence (persistent; this is launch #6 -> ncu capture slot)
    gru_persist<<<128, 256, gru_smem>>>(bhh_f, bhh_b);
    // 7) attention scores
    attn_mma<<<NB * NT / 64, 256>>>(attn_b1, attn_W2);
    // 8) softmax + context
    softmax_ctx<<<NB, 256>>>();
    // 9) joint head + FK
    joints_fk<<<NB * NT / 8, 256>>>(joint_W, joint_b, out);
}

// round 7
// speedup vs baseline: 1.3132x; 1.0023x over previous
#include <cuda_runtime.h>
#include <cuda_bf16.h>
#include <math.h>
#include <stdint.h>

#define NB   2048
#define NT   60
#define NDL  100
#define ND   512
#define NH   256

// ---------------- scratch (device globals) ----------------
__device__ float g_h0[NB * ND];
__device__ float g_stats[2 * ND];
__device__ float g_gates[2][NB * 3 * NH];          // x@Wih^T + bih (fp32)
__device__ float g_sf[2][2][NB * NH];              // fp32 GRU state [dir][pingpong]
__device__ __nv_bfloat16 g_shh[2][2][NB * NH];     // bf16 hi copy of state
__device__ __nv_bfloat16 g_shl[2][2][NB * NH];     // bf16 lo copy of state
__device__ __nv_bfloat16 g_whh[2][3 * NH * NH];    // Whh split hi
__device__ __nv_bfloat16 g_whl[2][3 * NH * NH];    // Whh split lo
__device__ __nv_bfloat16 g_w1h[NH * 2 * NH];       // attn_W1 split hi
__device__ __nv_bfloat16 g_w1l[NH * 2 * NH];       // attn_W1 split lo
__device__ float g_gru[NB * NT * 2 * NH];          // concat(gf,gb) fp32 [B,T,512]
__device__ __nv_bfloat16 g_gruh[NB * NT * 2 * NH]; // gru out bf16 hi
__device__ __nv_bfloat16 g_grul[NB * NT * 2 * NH]; // gru out bf16 lo
__device__ float g_s[NB * NT];
__device__ float g_c[NB * 2 * NH];
__device__ int   g_sync[2 * 16 * NT];              // group flags [dir][mtile][t]

__device__ __forceinline__ void bsplit(float v, __nv_bfloat16& h, __nv_bfloat16& l) {
    h = __float2bfloat16(v);
    l = __float2bfloat16(v - __bfloat162float(h));
}

__device__ __forceinline__ void mma16816(float& d0, float& d1, float& d2, float& d3,
    uint32_t a0, uint32_t a1, uint32_t a2, uint32_t a3, uint32_t b0, uint32_t b1)
{
    asm volatile("mma.sync.aligned.m16n8k16.row.col.f32.bf16.bf16.f32 "
                 "{%0,%1,%2,%3},{%4,%5,%6,%7},{%8,%9},{%0,%1,%2,%3};"
                 : "+f"(d0), "+f"(d1), "+f"(d2), "+f"(d3)
                 : "r"(a0), "r"(a1), "r"(a2), "r"(a3), "r"(b0), "r"(b1));
}

__device__ __forceinline__ void cpasync16(void* sdst, const void* gsrc) {
    uint32_t s = (uint32_t)__cvta_generic_to_shared(sdst);
    asm volatile("cp.async.cg.shared.global [%0], [%1], 16;" :: "r"(s), "l"(gsrc));
}
#define CP_COMMIT() asm volatile("cp.async.commit_group;")
#define CP_WAIT0()  asm volatile("cp.async.wait_group 0;")

__device__ __forceinline__ float ftanh_hw(float x) {    // MUFU.TANH
    float r;
    asm("tanh.approx.f32 %0, %1;" : "=f"(r) : "f"(x));
    return r;
}
__device__ __forceinline__ float fsig_hw(float x) {     // 0.5*tanh(x/2)+0.5
    return fmaf(ftanh_hw(0.5f * x), 0.5f, 0.5f);
}

// swizzled smem index: stride 64, XOR 8-col blocks by (row&7). Conflict-free.
__device__ __forceinline__ int swzidx(int r, int c) {
    return r * 64 + ((((c >> 3) ^ (r & 7)) << 3) | (c & 7));
}

// ---------------- fused fc GEMM + weight split + flag reset ----------------------
// blocks [0,256): fc GEMM tiles. blocks [256,1024): bf16 splits + sync reset.
__global__ void __launch_bounds__(256) fc_prep(
    const float* __restrict__ z, const float* __restrict__ W_fc,
    const float* __restrict__ b_fc,
    const float* __restrict__ Whh_f, const float* __restrict__ Whh_b,
    const float* __restrict__ W1)
{
    __shared__ float As[16][65];
    __shared__ float Bs[16][65];
    if (blockIdx.x < 256) {
        const int M = NB, N = ND, K = NDL;
        int tid = threadIdx.x;
        int tx = tid & 15, ty = tid >> 4;
        int m0 = (blockIdx.x >> 3) * 64, n0 = (blockIdx.x & 7) * 64;
        float acc[4][4] = {};
        for (int k0 = 0; k0 < K; k0 += 16) {
            #pragma unroll
            for (int i = 0; i < 4; i++) {
                int lin = tid + i * 256;
                int m = lin >> 4, k = lin & 15;
                As[k][m] = (k0 + k < K) ? z[(m0 + m) * K + k0 + k] : 0.f;
            }
            #pragma unroll
            for (int i = 0; i < 4; i++) {
                int lin = tid + i * 256;
                int n = lin >> 4, k = lin & 15;
                Bs[k][n] = (k0 + k < K) ? W_fc[(n0 + n) * K + k0 + k] : 0.f;
            }
            __syncthreads();
            #pragma unroll
            for (int kk = 0; kk < 16; kk++) {
                float a[4], b[4];
                #pragma unroll
                for (int i = 0; i < 4; i++) a[i] = As[kk][ty * 4 + i];
                #pragma unroll
                for (int j = 0; j < 4; j++) b[j] = Bs[kk][tx * 4 + j];
                #pragma unroll
                for (int i = 0; i < 4; i++)
                    #pragma unroll
                    for (int j = 0; j < 4; j++) acc[i][j] += a[i] * b[j];
            }
            __syncthreads();
        }
        #pragma unroll
        for (int i = 0; i < 4; i++) {
            int m = m0 + ty * 4 + i;
            #pragma unroll
            for (int j = 0; j < 4; j++) {
                int n = n0 + tx * 4 + j;
                g_h0[m * N + n] = acc[i][j] + b_fc[n];
            }
        }
    } else {
        int i = (blockIdx.x - 256) * 256 + threadIdx.x;   // 0 .. 196607
        bsplit(Whh_f[i], g_whh[0][i], g_whl[0][i]);
        bsplit(Whh_b[i], g_whh[1][i], g_whl[1][i]);
        if (i < NH * 2 * NH) bsplit(W1[i], g_w1h[i], g_w1l[i]);
        if (i < 2 * 16 * NT) g_sync[i] = 0;
    }
}

// ---------------- batchnorm stats -------------------------------------------------
__global__ void __launch_bounds__(256) bn_stats()
{
    int c = blockIdx.x;
    float s = 0.f, s2 = 0.f;
    for (int r = threadIdx.x; r < NB; r += 256) {
        float v = g_h0[r * ND + c];
        s += v; s2 += v * v;
    }
    __shared__ float sh[256], sh2[256];
    sh[threadIdx.x] = s; sh2[threadIdx.x] = s2;
    __syncthreads();
    for (int o = 128; o > 0; o >>= 1) {
        if (threadIdx.x < o) {
            sh[threadIdx.x]  += sh[threadIdx.x + o];
            sh2[threadIdx.x] += sh2[threadIdx.x + o];
        }
        __syncthreads();
    }
    if (threadIdx.x == 0) {
        float mu = sh[0] / (float)NB;
        g_stats[c] = mu;
        g_stats[ND + c] = sh2[0] / (float)NB - mu * mu;
    }
}

// ---- gate GEMM with fused BatchNorm+LeakyReLU on the A operand ------------------
// C[dir] = lrelu(bn(g_h0)) @ Wih^T + bih.  z selects direction.
__global__ void __launch_bounds__(256) gemm_gates_bn(
    const float* __restrict__ Wf, const float* __restrict__ bf,
    const float* __restrict__ Wb, const float* __restrict__ bb,
    const float* __restrict__ bn_g, const float* __restrict__ bn_b)
{
    const float* Bw   = blockIdx.z ? Wb : Wf;
    const float* bias = blockIdx.z ? bb : bf;
    float* C = g_gates[blockIdx.z];
    const int N = 3 * NH, K = ND;
    __shared__ float As[16][65];
    __shared__ float Bs[16][65];
    int tid = threadIdx.x;
    int tx = tid & 15, ty = tid >> 4;
    int m0 = blockIdx.y * 64, n0 = blockIdx.x * 64;
    float acc[4][4] = {};
    for (int k0 = 0; k0 < K; k0 += 16) {
        {   // A-load with BN+lrelu; column c fixed per thread
            const int k = tid & 15;
            const int c = k0 + k;
            const float mu = g_stats[c], var = g_stats[ND + c];
            const float scale = rsqrtf(var + 1e-5f) * bn_g[c];
            const float shift = bn_b[c] - mu * scale;
            #pragma unroll
            for (int i = 0; i < 4; i++) {
                int m = (tid >> 4) + i * 16;
                float v = g_h0[(m0 + m) * K + c] * scale + shift;
                As[k][m] = (v >= 0.f) ? v : 0.2f * v;
            }
        }
        #pragma unroll
        for (int i = 0; i < 4; i++) {
            int lin = tid + i * 256;
            int n = lin >> 4, k = lin & 15;
            Bs[k][n] = Bw[(n0 + n) * K + k0 + k];
        }
        __syncthreads();
        #pragma unroll
        for (int kk = 0; kk < 16; kk++) {
            float a[4], b[4];
            #pragma unroll
            for (int i = 0; i < 4; i++) a[i] = As[kk][ty * 4 + i];
            #pragma unroll
            for (int j = 0; j < 4; j++) b[j] = Bs[kk][tx * 4 + j];
            #pragma unroll
            for (int i = 0; i < 4; i++)
                #pragma unroll
                for (int j = 0; j < 4; j++) acc[i][j] += a[i] * b[j];
        }
        __syncthreads();
    }
    #pragma unroll
    for (int i = 0; i < 4; i++) {
        int m = m0 + ty * 4 + i;
        #pragma unroll
        for (int j = 0; j < 4; j++) {
            int n = n0 + tx * 4 + j;
            C[m * N + n] = acc[i][j] + bias[n];
        }
    }
}

// ---------------- MMA inner block ------------------------------------------------
__device__ __forceinline__ void mma_block(
    const __nv_bfloat16* __restrict__ As, const __nv_bfloat16* __restrict__ Bs,
    float acc[4][6][4], int wm, int wj, int gID, int tig)
{
    #pragma unroll
    for (int kk = 0; kk < 4; kk++) {
        uint32_t afr[4][4], bfr[6][2];
        const int s0 = kk * 2, s1 = kk * 2 + 1;
        #pragma unroll
        for (int mt = 0; mt < 4; mt++) {
            const int r = wm * 64 + mt * 16 + gID;
            const int x0 = (((s0 ^ (r & 7)) << 3) | (tig * 2));
            const int x1 = (((s1 ^ (r & 7)) << 3) | (tig * 2));
            afr[mt][0] = *(const uint32_t*)(As + r * 64 + x0);
            afr[mt][1] = *(const uint32_t*)(As + (r + 8) * 64 + x0);
            afr[mt][2] = *(const uint32_t*)(As + r * 64 + x1);
            afr[mt][3] = *(const uint32_t*)(As + (r + 8) * 64 + x1);
        }
        #pragma unroll
        for (int g = 0; g < 3; g++)
            #pragma unroll
            for (int jn = 0; jn < 2; jn++) {
                const int r = g * 64 + wj * 16 + jn * 8 + gID;
                const int x0 = (((s0 ^ (r & 7)) << 3) | (tig * 2));
                const int x1 = (((s1 ^ (r & 7)) << 3) | (tig * 2));
                bfr[g * 2 + jn][0] = *(const uint32_t*)(Bs + r * 64 + x0);
                bfr[g * 2 + jn][1] = *(const uint32_t*)(Bs + r * 64 + x1);
            }
        #pragma unroll
        for (int mt = 0; mt < 4; mt++)
            #pragma unroll
            for (int nt = 0; nt < 6; nt++)
                mma16816(acc[mt][nt][0], acc[mt][nt][1],
                         acc[mt][nt][2], acc[mt][nt][3],
                         afr[mt][0], afr[mt][1], afr[mt][2], afr[mt][3],
                         bfr[nt][0], bfr[nt][1]);
    }
}

// ---------------- persistent GRU with 4-block neighborhood sync ------------------
#define SLAB (192 * 64)
#define ATILE (128 * 64)
__global__ void __launch_bounds__(256) gru_persist(
    const float* __restrict__ bhh_f, const float* __restrict__ bhh_b)
{
    extern __shared__ __nv_bfloat16 smem[];
    __nv_bfloat16* Bsh = smem;
    __nv_bfloat16* Bsl = smem + 4 * SLAB;
    __nv_bfloat16* A0  = smem + 8 * SLAB;
    __nv_bfloat16* A1  = A0 + ATILE;

    const int bid = blockIdx.x;
    const int dir = bid >> 6;
    const int sub = bid & 63;
    const int j0 = (sub & 3) * 64;
    const int mtile = sub >> 2;
    const int m0 = mtile * 128;
    int* const flag = &g_sync[(dir * 16 + mtile) * NT];

    const float* bhh = dir ? bhh_b : bhh_f;
    const float* gin = g_gates[dir];
    const __nv_bfloat16* __restrict__ wh = g_whh[dir];
    const __nv_bfloat16* __restrict__ wl = g_whl[dir];

    const int tid = threadIdx.x;
    const int warp = tid >> 5, lane = tid & 31;
    const int wm = warp >> 2, wj = warp & 3;
    const int gID = lane >> 2, tig = lane & 3;

    int lr[4], lc[4];
    #pragma unroll
    for (int i = 0; i < 4; i++) {
        int u = tid + 256 * i;
        lr[i] = u >> 3; lc[i] = (u & 7) * 8;
    }

    // load Whh hi/lo into smem once
    #pragma unroll
    for (int i = 0; i < 24; i++) {
        int u = tid + 256 * i;
        int r = u >> 5;
        int c = (u & 31) * 8;
        int slab = c >> 6, cs = c & 63;
        int g = r >> 6, j = j0 + (r & 63);
        *(uint4*)&Bsh[slab * SLAB + swzidx(r, cs)] =
            *(const uint4*)&wh[(g * NH + j) * NH + c];
        *(uint4*)&Bsl[slab * SLAB + swzidx(r, cs)] =
            *(const uint4*)&wl[(g * NH + j) * NH + c];
    }
    __syncthreads();

    for (int t = 0; t < NT; t++) {
        const int src = t & 1, dst = src ^ 1;
        const float* __restrict__ sfs = g_sf[dir][src];
        const __nv_bfloat16* __restrict__ hh = g_shh[dir][src];
        const __nv_bfloat16* __restrict__ hl = g_shl[dir][src];

        float acc[4][6][4];
        #pragma unroll
        for (int a = 0; a < 4; a++)
            #pragma unroll
            for (int b = 0; b < 6; b++)
                #pragma unroll
                for (int q = 0; q < 4; q++) acc[a][b][q] = 0.f;

        if (t > 0) {
            // wait for the 4 writers of our m-rows to finish step t-1
            if (tid == 0) {
                while (*(volatile int*)&flag[t - 1] < 4) { }
                __threadfence();
            }
            __syncthreads();

            #pragma unroll
            for (int i = 0; i < 4; i++)
                cpasync16(&A0[swzidx(lr[i], lc[i])], &hh[(m0 + lr[i]) * NH + lc[i]]);
            CP_COMMIT();
            for (int ksl = 0; ksl < 4; ksl++) {
                const int ks = ksl * 64;
                CP_WAIT0(); __syncthreads();
                #pragma unroll
                for (int i = 0; i < 4; i++)
                    cpasync16(&A1[swzidx(lr[i], lc[i])],
                              &hl[(m0 + lr[i]) * NH + ks + lc[i]]);
                CP_COMMIT();
                mma_block(A0, Bsl + ksl * SLAB, acc, wm, wj, gID, tig);
                mma_block(A0, Bsh + ksl * SLAB, acc, wm, wj, gID, tig);
                CP_WAIT0(); __syncthreads();
                if (ksl < 3) {
                    #pragma unroll
                    for (int i = 0; i < 4; i++)
                        cpasync16(&A0[swzidx(lr[i], lc[i])],
                                  &hh[(m0 + lr[i]) * NH + ks + 64 + lc[i]]);
                    CP_COMMIT();
                }
                mma_block(A1, Bsh + ksl * SLAB, acc, wm, wj, gID, tig);
            }
        }

        // epilogue (MUFU.TANH-only activations)
        const int tt = dir ? (NT - 1 - t) : t;
        float* sfd = g_sf[dir][dst];
        __nv_bfloat16* dh = g_shh[dir][dst];
        __nv_bfloat16* dl = g_shl[dir][dst];
        #pragma unroll
        for (int mt = 0; mt < 4; mt++)
            #pragma unroll
            for (int part = 0; part < 2; part++) {
                const int m = m0 + wm * 64 + mt * 16 + gID + part * 8;
                #pragma unroll
                for (int jn = 0; jn < 2; jn++) {
                    const int jg = j0 + wj * 16 + jn * 8 + tig * 2;
                    #pragma unroll
                    for (int cc = 0; cc < 2; cc++) {
                        const int j = jg + cc;
                        float ghr = acc[mt][jn][part * 2 + cc]     + bhh[j];
                        float ghz = acc[mt][2 + jn][part * 2 + cc] + bhh[NH + j];
                        float ghn = acc[mt][4 + jn][part * 2 + cc] + bhh[2 * NH + j];
                        const float* gp = gin + m * 3 * NH + j;
                        float r  = fsig_hw(gp[0] + ghr);
                        float zz = fsig_hw(gp[NH] + ghz);
                        float nn = ftanh_hw(gp[2 * NH] + r * ghn);
                        float hold = (t == 0) ? 0.f : sfs[m * NH + j];
                        float hn = (1.f - zz) * nn + zz * hold;
                        sfd[m * NH + j] = hn;
                        __nv_bfloat16 bh, bl;
                        bsplit(hn, bh, bl);
                        dh[m * NH + j] = bh;
                        dl[m * NH + j] = bl;
                        const int go = (m * NT + tt) * (2 * NH) + dir * NH + j;
                        g_gru[go]  = hn;
                        g_gruh[go] = bh;
                        g_grul[go] = bl;
                    }
                }
            }

        if (t < NT - 1) {
            __syncthreads();                    // all state writes done
            if (tid == 0) {
                __threadfence();
                atomicAdd(&flag[t], 1);         // signal our group
            }
        }
    }
}

// ---------------- attention scores via bf16-split MMA ----------------------------
__global__ void __launch_bounds__(256) attn_mma(
    const float* __restrict__ b1, const float* __restrict__ W2)
{
    __shared__ __nv_bfloat16 As[64 * 72];
    __shared__ __nv_bfloat16 Bs[256 * 72];
    __shared__ float red[64];

    const int tid = threadIdx.x;
    const int m0 = blockIdx.x * 64;
    const int warp = tid >> 5, lane = tid & 31;
    const int wm = warp >> 2, wj = warp & 3;
    const int gID = lane >> 2, tig = lane & 3;
    if (tid < 64) red[tid] = 0.f;

    float acc[2][8][4];
    #pragma unroll
    for (int a = 0; a < 2; a++)
        #pragma unroll
        for (int b = 0; b < 8; b++)
            #pragma unroll
            for (int q = 0; q < 4; q++) acc[a][b][q] = 0.f;

    for (int it = 0; it < 24; it++) {
        const int ks = (it / 3) * 64;
        const int ph = it % 3;
        const bool loadA = (ph != 1);
        const bool loadB = (ph != 2);
        const __nv_bfloat16* __restrict__ asrc = (ph == 2) ? g_grul : g_gruh;
        const __nv_bfloat16* __restrict__ bsrc = (ph == 0) ? g_w1l : g_w1h;
        if (it > 0) __syncthreads();
        if (loadA) {
            #pragma unroll
            for (int i = 0; i < 2; i++) {
                int u = tid + 256 * i;
                int r = u >> 3, c = (u & 7) << 3;
                *(uint4*)&As[r * 72 + c] =
                    *(const uint4*)&asrc[(m0 + r) * 512 + ks + c];
            }
        }
        if (loadB) {
            #pragma unroll
            for (int i = 0; i < 8; i++) {
                int u = tid + 256 * i;
                int r = u >> 3, c = (u & 7) << 3;
                *(uint4*)&Bs[r * 72 + c] =
                    *(const uint4*)&bsrc[r * 512 + ks + c];
            }
        }
        __syncthreads();
        #pragma unroll
        for (int kk = 0; kk < 4; kk++) {
            const int kb = kk * 16 + tig * 2;
            uint32_t afr[2][4], bfr[8][2];
            #pragma unroll
            for (int mt = 0; mt < 2; mt++) {
                const __nv_bfloat16* p = As + (wm * 32 + mt * 16 + gID) * 72 + kb;
                afr[mt][0] = *(const uint32_t*)p;
                afr[mt][1] = *(const uint32_t*)(p + 8 * 72);
                afr[mt][2] = *(const uint32_t*)(p + 8);
                afr[mt][3] = *(const uint32_t*)(p + 8 * 72 + 8);
            }
            #pragma unroll
            for (int nt = 0; nt < 8; nt++) {
                const __nv_bfloat16* p = Bs + (wj * 64 + nt * 8 + gID) * 72 + kb;
                bfr[nt][0] = *(const uint32_t*)p;
                bfr[nt][1] = *(const uint32_t*)(p + 8);
            }
            #pragma unroll
            for (int mt = 0; mt < 2; mt++)
                #pragma unroll
                for (int nt = 0; nt < 8; nt++)
                    mma16816(acc[mt][nt][0], acc[mt][nt][1],
                             acc[mt][nt][2], acc[mt][nt][3],
                             afr[mt][0], afr[mt][1], afr[mt][2], afr[mt][3],
                             bfr[nt][0], bfr[nt][1]);
        }
    }

    #pragma unroll
    for (int mt = 0; mt < 2; mt++)
        #pragma unroll
        for (int part = 0; part < 2; part++) {
            float s = 0.f;
            #pragma unroll
            for (int nt = 0; nt < 8; nt++)
                #pragma unroll
                for (int cc = 0; cc < 2; cc++) {
                    int n = wj * 64 + nt * 8 + tig * 2 + cc;
                    s += ftanh_hw(acc[mt][nt][part * 2 + cc] + b1[n]) * W2[n];
                }
            s += __shfl_xor_sync(0xffffffffu, s, 1);
            s += __shfl_xor_sync(0xffffffffu, s, 2);
            if (tig == 0)
                atomicAdd(&red[wm * 32 + mt * 16 + gID + part * 8], s);
        }
    __syncthreads();
    if (tid < 64) g_s[m0 + tid] = red[tid];
}

// ---------------- softmax over time + context vector -----------------------------
__global__ void __launch_bounds__(256) softmax_ctx()
{
    int b = blockIdx.x;
    __shared__ float w[NT];
    int tid = threadIdx.x;
    if (tid == 0) {
        float mx = -1e30f;
        for (int t = 0; t < NT; t++) {
            float v = g_s[b * NT + t];
            if (v > mx) mx = v;
            w[t] = v;
        }
        float s = 0.f;
        for (int t = 0; t < NT; t++) { w[t] = __expf(w[t] - mx); s += w[t]; }
        float inv = __fdividef(1.f, s);
        for (int t = 0; t < NT; t++) w[t] *= inv;
    }
    __syncthreads();
    for (int d = tid; d < 2 * NH; d += 256) {
        float s = 0.f;
        for (int t = 0; t < NT; t++)
            s += w[t] * g_gru[(b * NT + t) * (2 * NH) + d];
        g_c[b * 2 * NH + d] = s;
    }
}

// ---------------- joint head + forward kinematics --------------------------------
__global__ void __launch_bounds__(256) joints_fk(
    const float* __restrict__ jW, const float* __restrict__ jb,
    float* __restrict__ out)
{
    int w = blockIdx.x * 8 + (threadIdx.x >> 5);
    int lane = threadIdx.x & 31;
    if (w >= NB * NT) return;
    int b = w / NT;
    const float* row  = &g_gru[w * 512];
    const float* crow = &g_c[b * 512];
    float p[6] = {};
    #pragma unroll
    for (int k = 0; k < 16; k++) {
        int d = lane + k * 32;
        float x = row[d] + crow[d];
        #pragma unroll
        for (int j = 0; j < 6; j++) p[j] += x * jW[j * 512 + d];
    }
    #pragma unroll
    for (int o = 16; o > 0; o >>= 1)
        #pragma unroll
        for (int j = 0; j < 6; j++) p[j] += __shfl_xor_sync(0xffffffffu, p[j], o);
    if (lane != 0) return;

    const float LO[6] = {-3.1416f, -1.5708f, -3.1416f, -2.6f, -1.5708f, -1.2f};
    const float UP[6] = { 3.1416f,  1.5708f,  3.1416f,  0.1f,  1.5708f,  1.2f};
    float th[6];
    #pragma unroll
    for (int j = 0; j < 6; j++)
        th[j] = (p[j] + jb[j]) * (UP[j] - LO[j]) + LO[j];

    float c0[3] = {1.f, 0.f, 0.f}, c1[3] = {0.f, 1.f, 0.f}, c2[3] = {0.f, 0.f, 1.f};
    float px = 0.f, py = 0.f, pz = 0.10f;
    float sh2x = 0.f, sh2y = 0.f, sh2z = 0.10f;

    float c, s, tmp;
    c = cosf(th[0]); s = sinf(th[0]);
    #pragma unroll
    for (int i = 0; i < 3; i++) { tmp = c*c0[i] + s*c1[i]; c1[i] = c*c1[i] - s*c0[i]; c0[i] = tmp; }
    c = cosf(th[1]); s = sinf(th[1]);
    #pragma unroll
    for (int i = 0; i < 3; i++) { tmp = c*c1[i] + s*c2[i]; c2[i] = c*c2[i] - s*c1[i]; c1[i] = tmp; }
    c = cosf(th[2]); s = sinf(th[2]);
    #pragma unroll
    for (int i = 0; i < 3; i++) { tmp = c*c0[i] - s*c2[i]; c2[i] = c*c2[i] + s*c0[i]; c0[i] = tmp; }
    px -= 0.25f * c1[0]; py -= 0.25f * c1[1]; pz -= 0.25f * c1[2];
    float fax = px, fay = py, faz = pz;
    c = cosf(th[3]); s = sinf(th[3]);
    #pragma unroll
    for (int i = 0; i < 3; i++) { tmp = c*c1[i] + s*c2[i]; c2[i] = c*c2[i] - s*c1[i]; c1[i] = tmp; }
    c = cosf(th[4]); s = sinf(th[4]);
    #pragma unroll
    for (int i = 0; i < 3; i++) { tmp = c*c0[i] - s*c2[i]; c2[i] = c*c2[i] + s*c0[i]; c0[i] = tmp; }
    px -= 0.25f * c1[0]; py -= 0.25f * c1[1]; pz -= 0.25f * c1[2];
    float wx = px, wy = py, wz = pz;
    c = cosf(th[5]); s = sinf(th[5]);
    #pragma unroll
    for (int i = 0; i < 3; i++) { tmp = c*c1[i] + s*c2[i]; c2[i] = c*c2[i] - s*c1[i]; c1[i] = tmp; }

    float f1x = wx - 0.08f*c1[0] + 0.02f*c2[0];
    float f1y = wy - 0.08f*c1[1] + 0.02f*c2[1];
    float f1z = wz - 0.08f*c1[2] + 0.02f*c2[2];
    float f4x = wx - 0.08f*c1[0] - 0.02f*c2[0];
    float f4y = wy - 0.08f*c1[1] - 0.02f*c2[1];
    float f4z = wz - 0.08f*c1[2] - 0.02f*c2[2];

    float d1x = sh2x - fax, d1y = sh2y - fay, d1z = sh2z - faz;
    float d2x = wx - fax,   d2y = wy - fay,   d2z = wz - faz;
    float bodyL = 0.5f * (sqrtf(d1x*d1x + d1y*d1y + d1z*d1z)
                        + sqrtf(d2x*d2x + d2y*d2y + d2z*d2z));
    float inv = 1.f / bodyL;

    float* o = out + (long)w * 9;
    o[0] = (wx  - sh2x) * inv; o[1] = (wy  - sh2y) * inv; o[2] = (wz  - sh2z) * inv;
    o[3] = (f1x - sh2x) * inv; o[4] = (f1y - sh2y) * inv; o[5] = (f1z - sh2z) * inv;
    o[6] = (f4x - sh2x) * inv; o[7] = (f4y - sh2y) * inv; o[8] = (f4z - sh2z) * inv;
}

// ---------------- host launcher ---------------------------------------------------
extern "C" void kernel_launch(void* const* d_in, const int* in_sizes, int n_in,
                              void* d_out, int out_size)
{
    const float* z       = (const float*)d_in[0];
    const float* W_fc    = (const float*)d_in[1];
    const float* b_fc    = (const float*)d_in[2];
    const float* bn_g    = (const float*)d_in[3];
    const float* bn_b    = (const float*)d_in[4];
    const float* Wih_f   = (const float*)d_in[5];
    const float* Whh_f   = (const float*)d_in[6];
    const float* bih_f   = (const float*)d_in[7];
    const float* bhh_f   = (const float*)d_in[8];
    const float* Wih_b   = (const float*)d_in[9];
    const float* Whh_b   = (const float*)d_in[10];
    const float* bih_b   = (const float*)d_in[11];
    const float* bhh_b   = (const float*)d_in[12];
    const float* attn_W1 = (const float*)d_in[13];
    const float* attn_b1 = (const float*)d_in[14];
    const float* attn_W2 = (const float*)d_in[15];
    const float* joint_W = (const float*)d_in[16];
    const float* joint_b = (const float*)d_in[17];
    float* out = (float*)d_out;

    static int smem_set = 0;
    const int gru_smem = (8 * SLAB + 2 * ATILE) * 2;   // 229376 bytes
    if (!smem_set) {
        cudaFuncSetAttribute(gru_persist,
            cudaFuncAttributeMaxDynamicSharedMemorySize, gru_smem);
        smem_set = 1;
    }

    // 1) fc GEMM + weight split + flag reset (fused)
    fc_prep<<<1024, 256>>>(z, W_fc, b_fc, Whh_f, Whh_b, attn_W1);
    // 2) batch stats
    bn_stats<<<ND, 256>>>();
    // 3) gate GEMM with fused BN+LeakyReLU, both dirs
    gemm_gates_bn<<<dim3(3 * NH / 64, NB / 64, 2), 256>>>(
        Wih_f, bih_f, Wih_b, bih_b, bn_g, bn_b);
    // 4) GRU recurrence (persistent, neighborhood sync)  <- ncu capture slot
    gru_persist<<<128, 256, gru_smem>>>(bhh_f, bhh_b);
    // 5) attention scores
    attn_mma<<<NB * NT / 64, 256>>>(attn_b1, attn_W2);
    // 6) softmax + context
    softmax_ctx<<<NB, 256>>>();
    // 7) joint head + FK
    joints_fk<<<NB * NT / 8, 256>>>(joint_W, joint_b, out);
}

// round 8
// speedup vs baseline: 1.3276x; 1.0110x over previous
#include <cuda_runtime.h>
#include <cuda_bf16.h>
#include <math.h>
#include <stdint.h>

#define NB   2048
#define NT   60
#define NDL  100
#define ND   512
#define NH   256

// ---------------- scratch (device globals) ----------------
__device__ float g_h0[NB * ND];
__device__ float g_stats[2 * ND];
__device__ float g_gates[2][NB * 3 * NH];          // x@Wih^T + bih (fp32)
__device__ float g_sf[2][2][NB * NH];              // fp32 GRU state [dir][pingpong]
__device__ __nv_bfloat16 g_shh[2][2][NB * NH];     // bf16 hi copy of state
__device__ __nv_bfloat16 g_shl[2][2][NB * NH];     // bf16 lo copy of state
__device__ __nv_bfloat16 g_whh[2][3 * NH * NH];    // Whh split hi
__device__ __nv_bfloat16 g_whl[2][3 * NH * NH];    // Whh split lo
__device__ __nv_bfloat16 g_w1h[NH * 2 * NH];       // attn_W1 split hi
__device__ __nv_bfloat16 g_w1l[NH * 2 * NH];       // attn_W1 split lo
__device__ float g_gru[NB * NT * 2 * NH];          // concat(gf,gb) fp32 [B,T,512]
__device__ __nv_bfloat16 g_gruh[NB * NT * 2 * NH]; // gru out bf16 hi
__device__ __nv_bfloat16 g_grul[NB * NT * 2 * NH]; // gru out bf16 lo
__device__ float g_s[NB * NT];
__device__ float g_c[NB * 2 * NH];
__device__ int   g_sync[2 * 16 * NT];              // group flags [dir][mtile][t]

__device__ __forceinline__ void bsplit(float v, __nv_bfloat16& h, __nv_bfloat16& l) {
    h = __float2bfloat16(v);
    l = __float2bfloat16(v - __bfloat162float(h));
}

__device__ __forceinline__ void mma16816(float& d0, float& d1, float& d2, float& d3,
    uint32_t a0, uint32_t a1, uint32_t a2, uint32_t a3, uint32_t b0, uint32_t b1)
{
    asm volatile("mma.sync.aligned.m16n8k16.row.col.f32.bf16.bf16.f32 "
                 "{%0,%1,%2,%3},{%4,%5,%6,%7},{%8,%9},{%0,%1,%2,%3};"
                 : "+f"(d0), "+f"(d1), "+f"(d2), "+f"(d3)
                 : "r"(a0), "r"(a1), "r"(a2), "r"(a3), "r"(b0), "r"(b1));
}

#define LDSM4(r0, r1, r2, r3, addr) \
    asm volatile("ldmatrix.sync.aligned.m8n8.x4.shared.b16 {%0,%1,%2,%3}, [%4];" \
                 : "=r"(r0), "=r"(r1), "=r"(r2), "=r"(r3) : "r"(addr))

__device__ __forceinline__ void cpasync16(void* sdst, const void* gsrc) {
    uint32_t s = (uint32_t)__cvta_generic_to_shared(sdst);
    asm volatile("cp.async.cg.shared.global [%0], [%1], 16;" :: "r"(s), "l"(gsrc));
}
#define CP_COMMIT() asm volatile("cp.async.commit_group;")
#define CP_WAIT0()  asm volatile("cp.async.wait_group 0;")

__device__ __forceinline__ float ftanh_hw(float x) {
    float r;
    asm("tanh.approx.f32 %0, %1;" : "=f"(r) : "f"(x));
    return r;
}
__device__ __forceinline__ float fsig_hw(float x) {
    return fmaf(ftanh_hw(0.5f * x), 0.5f, 0.5f);
}

// swizzled smem index (elements): stride 64, XOR 8-col blocks by (row&7).
__device__ __forceinline__ int swzidx(int r, int c) {
    return r * 64 + ((((c >> 3) ^ (r & 7)) << 3) | (c & 7));
}

// ---------------- fused fc GEMM + weight split + flag reset ----------------------
__global__ void __launch_bounds__(256) fc_prep(
    const float* __restrict__ z, const float* __restrict__ W_fc,
    const float* __restrict__ b_fc,
    const float* __restrict__ Whh_f, const float* __restrict__ Whh_b,
    const float* __restrict__ W1)
{
    __shared__ float As[16][65];
    __shared__ float Bs[16][65];
    if (blockIdx.x < 256) {
        const int N = ND, K = NDL;
        int tid = threadIdx.x;
        int tx = tid & 15, ty = tid >> 4;
        int m0 = (blockIdx.x >> 3) * 64, n0 = (blockIdx.x & 7) * 64;
        float acc[4][4] = {};
        for (int k0 = 0; k0 < K; k0 += 16) {
            #pragma unroll
            for (int i = 0; i < 4; i++) {
                int lin = tid + i * 256;
                int m = lin >> 4, k = lin & 15;
                As[k][m] = (k0 + k < K) ? z[(m0 + m) * K + k0 + k] : 0.f;
            }
            #pragma unroll
            for (int i = 0; i < 4; i++) {
                int lin = tid + i * 256;
                int n = lin >> 4, k = lin & 15;
                Bs[k][n] = (k0 + k < K) ? W_fc[(n0 + n) * K + k0 + k] : 0.f;
            }
            __syncthreads();
            #pragma unroll
            for (int kk = 0; kk < 16; kk++) {
                float a[4], b[4];
                #pragma unroll
                for (int i = 0; i < 4; i++) a[i] = As[kk][ty * 4 + i];
                #pragma unroll
                for (int j = 0; j < 4; j++) b[j] = Bs[kk][tx * 4 + j];
                #pragma unroll
                for (int i = 0; i < 4; i++)
                    #pragma unroll
                    for (int j = 0; j < 4; j++) acc[i][j] += a[i] * b[j];
            }
            __syncthreads();
        }
        #pragma unroll
        for (int i = 0; i < 4; i++) {
            int m = m0 + ty * 4 + i;
            #pragma unroll
            for (int j = 0; j < 4; j++) {
                int n = n0 + tx * 4 + j;
                g_h0[m * N + n] = acc[i][j] + b_fc[n];
            }
        }
    } else {
        int i = (blockIdx.x - 256) * 256 + threadIdx.x;
        bsplit(Whh_f[i], g_whh[0][i], g_whl[0][i]);
        bsplit(Whh_b[i], g_whh[1][i], g_whl[1][i]);
        if (i < NH * 2 * NH) bsplit(W1[i], g_w1h[i], g_w1l[i]);
        if (i < 2 * 16 * NT) g_sync[i] = 0;
    }
}

// ---------------- batchnorm stats -------------------------------------------------
__global__ void __launch_bounds__(256) bn_stats()
{
    int c = blockIdx.x;
    float s = 0.f, s2 = 0.f;
    for (int r = threadIdx.x; r < NB; r += 256) {
        float v = g_h0[r * ND + c];
        s += v; s2 += v * v;
    }
    __shared__ float sh[256], sh2[256];
    sh[threadIdx.x] = s; sh2[threadIdx.x] = s2;
    __syncthreads();
    for (int o = 128; o > 0; o >>= 1) {
        if (threadIdx.x < o) {
            sh[threadIdx.x]  += sh[threadIdx.x + o];
            sh2[threadIdx.x] += sh2[threadIdx.x + o];
        }
        __syncthreads();
    }
    if (threadIdx.x == 0) {
        float mu = sh[0] / (float)NB;
        g_stats[c] = mu;
        g_stats[ND + c] = sh2[0] / (float)NB - mu * mu;
    }
}

// ---- gate GEMM with fused BatchNorm+LeakyReLU on the A operand ------------------
__global__ void __launch_bounds__(256) gemm_gates_bn(
    const float* __restrict__ Wf, const float* __restrict__ bf,
    const float* __restrict__ Wb, const float* __restrict__ bb,
    const float* __restrict__ bn_g, const float* __restrict__ bn_b)
{
    const float* Bw   = blockIdx.z ? Wb : Wf;
    const float* bias = blockIdx.z ? bb : bf;
    float* C = g_gates[blockIdx.z];
    const int N = 3 * NH, K = ND;
    __shared__ float As[16][65];
    __shared__ float Bs[16][65];
    int tid = threadIdx.x;
    int tx = tid & 15, ty = tid >> 4;
    int m0 = blockIdx.y * 64, n0 = blockIdx.x * 64;
    float acc[4][4] = {};
    for (int k0 = 0; k0 < K; k0 += 16) {
        {
            const int k = tid & 15;
            const int c = k0 + k;
            const float mu = g_stats[c], var = g_stats[ND + c];
            const float scale = rsqrtf(var + 1e-5f) * bn_g[c];
            const float shift = bn_b[c] - mu * scale;
            #pragma unroll
            for (int i = 0; i < 4; i++) {
                int m = (tid >> 4) + i * 16;
                float v = g_h0[(m0 + m) * K + c] * scale + shift;
                As[k][m] = (v >= 0.f) ? v : 0.2f * v;
            }
        }
        #pragma unroll
        for (int i = 0; i < 4; i++) {
            int lin = tid + i * 256;
            int n = lin >> 4, k = lin & 15;
            Bs[k][n] = Bw[(n0 + n) * K + k0 + k];
        }
        __syncthreads();
        #pragma unroll
        for (int kk = 0; kk < 16; kk++) {
            float a[4], b[4];
            #pragma unroll
            for (int i = 0; i < 4; i++) a[i] = As[kk][ty * 4 + i];
            #pragma unroll
            for (int j = 0; j < 4; j++) b[j] = Bs[kk][tx * 4 + j];
            #pragma unroll
            for (int i = 0; i < 4; i++)
                #pragma unroll
                for (int j = 0; j < 4; j++) acc[i][j] += a[i] * b[j];
        }
        __syncthreads();
    }
    #pragma unroll
    for (int i = 0; i < 4; i++) {
        int m = m0 + ty * 4 + i;
        #pragma unroll
        for (int j = 0; j < 4; j++) {
            int n = n0 + tx * 4 + j;
            C[m * N + n] = acc[i][j] + bias[n];
        }
    }
}

// ---------------- LDSM-based MMA inner blocks ------------------------------------
// A-frag loads via ldmatrix; dual-B version loads A once for two B slabs.
__device__ __forceinline__ void ldsm_afrags(
    uint32_t As_u32, uint32_t afr[4][4], int wm, int lane, int kk)
{
    const int g = lane >> 3, lr = lane & 7;
    const int scol = kk * 2 + (g >> 1);               // s0 for g<2, s1 for g>=2
    #pragma unroll
    for (int mt = 0; mt < 4; mt++) {
        const int row = wm * 64 + mt * 16 + ((g & 1) << 3) + lr;
        const uint32_t addr = As_u32 + row * 128 + ((scol ^ (row & 7)) << 4);
        LDSM4(afr[mt][0], afr[mt][1], afr[mt][2], afr[mt][3], addr);
    }
}

__device__ __forceinline__ void ldsm_bfrags(
    uint32_t Bs_u32, uint32_t bfr[6][2], int wj, int lane, int kk)
{
    const int g = lane >> 3, lr = lane & 7;
    const int scol = kk * 2 + (g & 1);                // s0/s1 alternating
    #pragma unroll
    for (int q = 0; q < 3; q++) {
        const int nt = 2 * q + (g >> 1);
        const int row = (nt >> 1) * 64 + wj * 16 + (nt & 1) * 8 + lr;
        const uint32_t addr = Bs_u32 + row * 128 + ((scol ^ (row & 7)) << 4);
        LDSM4(bfr[2 * q][0], bfr[2 * q][1], bfr[2 * q + 1][0], bfr[2 * q + 1][1], addr);
    }
}

__device__ __forceinline__ void mma_all(
    const uint32_t afr[4][4], const uint32_t bfr[6][2], float acc[4][6][4])
{
    #pragma unroll
    for (int mt = 0; mt < 4; mt++)
        #pragma unroll
        for (int nt = 0; nt < 6; nt++)
            mma16816(acc[mt][nt][0], acc[mt][nt][1], acc[mt][nt][2], acc[mt][nt][3],
                     afr[mt][0], afr[mt][1], afr[mt][2], afr[mt][3],
                     bfr[nt][0], bfr[nt][1]);
}

// A against two B slabs (A frags loaded once per kk)
__device__ __forceinline__ void mma_block2(
    uint32_t As_u32, uint32_t Bs1_u32, uint32_t Bs2_u32,
    float acc[4][6][4], int wm, int wj, int lane)
{
    #pragma unroll
    for (int kk = 0; kk < 4; kk++) {
        uint32_t afr[4][4], bfr[6][2];
        ldsm_afrags(As_u32, afr, wm, lane, kk);
        ldsm_bfrags(Bs1_u32, bfr, wj, lane, kk);
        mma_all(afr, bfr, acc);
        ldsm_bfrags(Bs2_u32, bfr, wj, lane, kk);
        mma_all(afr, bfr, acc);
    }
}

__device__ __forceinline__ void mma_block1(
    uint32_t As_u32, uint32_t Bs_u32,
    float acc[4][6][4], int wm, int wj, int lane)
{
    #pragma unroll
    for (int kk = 0; kk < 4; kk++) {
        uint32_t afr[4][4], bfr[6][2];
        ldsm_afrags(As_u32, afr, wm, lane, kk);
        ldsm_bfrags(Bs_u32, bfr, wj, lane, kk);
        mma_all(afr, bfr, acc);
    }
}

// ---------------- persistent GRU with 4-block neighborhood sync ------------------
#define SLAB (192 * 64)
#define ATILE (128 * 64)
__global__ void __launch_bounds__(256) gru_persist(
    const float* __restrict__ bhh_f, const float* __restrict__ bhh_b)
{
    extern __shared__ __nv_bfloat16 smem[];
    __nv_bfloat16* Bsh = smem;
    __nv_bfloat16* Bsl = smem + 4 * SLAB;
    __nv_bfloat16* A0  = smem + 8 * SLAB;
    __nv_bfloat16* A1  = A0 + ATILE;
    const uint32_t Bsh_u32 = (uint32_t)__cvta_generic_to_shared(Bsh);
    const uint32_t Bsl_u32 = (uint32_t)__cvta_generic_to_shared(Bsl);
    const uint32_t A0_u32  = (uint32_t)__cvta_generic_to_shared(A0);
    const uint32_t A1_u32  = (uint32_t)__cvta_generic_to_shared(A1);
    const uint32_t SLAB_B  = SLAB * 2;   // slab stride in bytes

    const int bid = blockIdx.x;
    const int dir = bid >> 6;
    const int sub = bid & 63;
    const int j0 = (sub & 3) * 64;
    const int mtile = sub >> 2;
    const int m0 = mtile * 128;
    int* const flag = &g_sync[(dir * 16 + mtile) * NT];

    const float* bhh = dir ? bhh_b : bhh_f;
    const float* gin = g_gates[dir];
    const __nv_bfloat16* __restrict__ wh = g_whh[dir];
    const __nv_bfloat16* __restrict__ wl = g_whl[dir];

    const int tid = threadIdx.x;
    const int warp = tid >> 5, lane = tid & 31;
    const int wm = warp >> 2, wj = warp & 3;
    const int gID = lane >> 2, tig = lane & 3;

    int lr[4], lc[4];
    #pragma unroll
    for (int i = 0; i < 4; i++) {
        int u = tid + 256 * i;
        lr[i] = u >> 3; lc[i] = (u & 7) * 8;
    }

    // load Whh hi/lo into smem once
    #pragma unroll
    for (int i = 0; i < 24; i++) {
        int u = tid + 256 * i;
        int r = u >> 5;
        int c = (u & 31) * 8;
        int slab = c >> 6, cs = c & 63;
        int g = r >> 6, j = j0 + (r & 63);
        *(uint4*)&Bsh[slab * SLAB + swzidx(r, cs)] =
            *(const uint4*)&wh[(g * NH + j) * NH + c];
        *(uint4*)&Bsl[slab * SLAB + swzidx(r, cs)] =
            *(const uint4*)&wl[(g * NH + j) * NH + c];
    }
    __syncthreads();

    for (int t = 0; t < NT; t++) {
        const int src = t & 1, dst = src ^ 1;
        const float* __restrict__ sfs = g_sf[dir][src];
        const __nv_bfloat16* __restrict__ hh = g_shh[dir][src];
        const __nv_bfloat16* __restrict__ hl = g_shl[dir][src];

        float acc[4][6][4];
        #pragma unroll
        for (int a = 0; a < 4; a++)
            #pragma unroll
            for (int b = 0; b < 6; b++)
                #pragma unroll
                for (int q = 0; q < 4; q++) acc[a][b][q] = 0.f;

        if (t > 0) {
            if (tid == 0) {
                while (*(volatile int*)&flag[t - 1] < 4) { }
                __threadfence();
            }
            __syncthreads();

            #pragma unroll
            for (int i = 0; i < 4; i++)
                cpasync16(&A0[swzidx(lr[i], lc[i])], &hh[(m0 + lr[i]) * NH + lc[i]]);
            CP_COMMIT();
            for (int ksl = 0; ksl < 4; ksl++) {
                const int ks = ksl * 64;
                CP_WAIT0(); __syncthreads();
                #pragma unroll
                for (int i = 0; i < 4; i++)
                    cpasync16(&A1[swzidx(lr[i], lc[i])],
                              &hl[(m0 + lr[i]) * NH + ks + lc[i]]);
                CP_COMMIT();
                mma_block2(A0_u32, Bsl_u32 + ksl * SLAB_B, Bsh_u32 + ksl * SLAB_B,
                           acc, wm, wj, lane);
                CP_WAIT0(); __syncthreads();
                if (ksl < 3) {
                    #pragma unroll
                    for (int i = 0; i < 4; i++)
                        cpasync16(&A0[swzidx(lr[i], lc[i])],
                                  &hh[(m0 + lr[i]) * NH + ks + 64 + lc[i]]);
                    CP_COMMIT();
                }
                mma_block1(A1_u32, Bsh_u32 + ksl * SLAB_B, acc, wm, wj, lane);
            }
        }

        // epilogue (MUFU.TANH activations)
        const int tt = dir ? (NT - 1 - t) : t;
        float* sfd = g_sf[dir][dst];
        __nv_bfloat16* dh = g_shh[dir][dst];
        __nv_bfloat16* dl = g_shl[dir][dst];
        #pragma unroll
        for (int mt = 0; mt < 4; mt++)
            #pragma unroll
            for (int part = 0; part < 2; part++) {
                const int m = m0 + wm * 64 + mt * 16 + gID + part * 8;
                #pragma unroll
                for (int jn = 0; jn < 2; jn++) {
                    const int jg = j0 + wj * 16 + jn * 8 + tig * 2;
                    #pragma unroll
                    for (int cc = 0; cc < 2; cc++) {
                        const int j = jg + cc;
                        float ghr = acc[mt][jn][part * 2 + cc]     + bhh[j];
                        float ghz = acc[mt][2 + jn][part * 2 + cc] + bhh[NH + j];
                        float ghn = acc[mt][4 + jn][part * 2 + cc] + bhh[2 * NH + j];
                        const float* gp = gin + m * 3 * NH + j;
                        float r  = fsig_hw(gp[0] + ghr);
                        float zz = fsig_hw(gp[NH] + ghz);
                        float nn = ftanh_hw(gp[2 * NH] + r * ghn);
                        float hold = (t == 0) ? 0.f : sfs[m * NH + j];
                        float hn = (1.f - zz) * nn + zz * hold;
                        sfd[m * NH + j] = hn;
                        __nv_bfloat16 bh, bl;
                        bsplit(hn, bh, bl);
                        dh[m * NH + j] = bh;
                        dl[m * NH + j] = bl;
                        const int go = (m * NT + tt) * (2 * NH) + dir * NH + j;
                        g_gru[go]  = hn;
                        g_gruh[go] = bh;
                        g_grul[go] = bl;
                    }
                }
            }

        if (t < NT - 1) {
            __syncthreads();
            if (tid == 0) {
                __threadfence();
                atomicAdd(&flag[t], 1);
            }
        }
    }
}

// ---------------- attention scores via bf16-split MMA ----------------------------
__global__ void __launch_bounds__(256) attn_mma(
    const float* __restrict__ b1, const float* __restrict__ W2)
{
    __shared__ __nv_bfloat16 As[64 * 72];
    __shared__ __nv_bfloat16 Bs[256 * 72];
    __shared__ float red[64];

    const int tid = threadIdx.x;
    const int m0 = blockIdx.x * 64;
    const int warp = tid >> 5, lane = tid & 31;
    const int wm = warp >> 2, wj = warp & 3;
    const int gID = lane >> 2, tig = lane & 3;
    if (tid < 64) red[tid] = 0.f;

    float acc[2][8][4];
    #pragma unroll
    for (int a = 0; a < 2; a++)
        #pragma unroll
        for (int b = 0; b < 8; b++)
            #pragma unroll
            for (int q = 0; q < 4; q++) acc[a][b][q] = 0.f;

    for (int it = 0; it < 24; it++) {
        const int ks = (it / 3) * 64;
        const int ph = it % 3;
        const bool loadA = (ph != 1);
        const bool loadB = (ph != 2);
        const __nv_bfloat16* __restrict__ asrc = (ph == 2) ? g_grul : g_gruh;
        const __nv_bfloat16* __restrict__ bsrc = (ph == 0) ? g_w1l : g_w1h;
        if (it > 0) __syncthreads();
        if (loadA) {
            #pragma unroll
            for (int i = 0; i < 2; i++) {
                int u = tid + 256 * i;
                int r = u >> 3, c = (u & 7) << 3;
                *(uint4*)&As[r * 72 + c] =
                    *(const uint4*)&asrc[(m0 + r) * 512 + ks + c];
            }
        }
        if (loadB) {
            #pragma unroll
            for (int i = 0; i < 8; i++) {
                int u = tid + 256 * i;
                int r = u >> 3, c = (u & 7) << 3;
                *(uint4*)&Bs[r * 72 + c] =
                    *(const uint4*)&bsrc[r * 512 + ks + c];
            }
        }
        __syncthreads();
        #pragma unroll
        for (int kk = 0; kk < 4; kk++) {
            const int kb = kk * 16 + tig * 2;
            uint32_t afr[2][4], bfr[8][2];
            #pragma unroll
            for (int mt = 0; mt < 2; mt++) {
                const __nv_bfloat16* p = As + (wm * 32 + mt * 16 + gID) * 72 + kb;
                afr[mt][0] = *(const uint32_t*)p;
                afr[mt][1] = *(const uint32_t*)(p + 8 * 72);
                afr[mt][2] = *(const uint32_t*)(p + 8);
                afr[mt][3] = *(const uint32_t*)(p + 8 * 72 + 8);
            }
            #pragma unroll
            for (int nt = 0; nt < 8; nt++) {
                const __nv_bfloat16* p = Bs + (wj * 64 + nt * 8 + gID) * 72 + kb;
                bfr[nt][0] = *(const uint32_t*)p;
                bfr[nt][1] = *(const uint32_t*)(p + 8);
            }
            #pragma unroll
            for (int mt = 0; mt < 2; mt++)
                #pragma unroll
                for (int nt = 0; nt < 8; nt++)
                    mma16816(acc[mt][nt][0], acc[mt][nt][1],
                             acc[mt][nt][2], acc[mt][nt][3],
                             afr[mt][0], afr[mt][1], afr[mt][2], afr[mt][3],
                             bfr[nt][0], bfr[nt][1]);
        }
    }

    #pragma unroll
    for (int mt = 0; mt < 2; mt++)
        #pragma unroll
        for (int part = 0; part < 2; part++) {
            float s = 0.f;
            #pragma unroll
            for (int nt = 0; nt < 8; nt++)
                #pragma unroll
                for (int cc = 0; cc < 2; cc++) {
                    int n = wj * 64 + nt * 8 + tig * 2 + cc;
                    s += ftanh_hw(acc[mt][nt][part * 2 + cc] + b1[n]) * W2[n];
                }
            s += __shfl_xor_sync(0xffffffffu, s, 1);
            s += __shfl_xor_sync(0xffffffffu, s, 2);
            if (tig == 0)
                atomicAdd(&red[wm * 32 + mt * 16 + gID + part * 8], s);
        }
    __syncthreads();
    if (tid < 64) g_s[m0 + tid] = red[tid];
}

// ---------------- softmax over time + context vector -----------------------------
__global__ void __launch_bounds__(256) softmax_ctx()
{
    int b = blockIdx.x;
    __shared__ float w[NT];
    int tid = threadIdx.x;
    if (tid == 0) {
        float mx = -1e30f;
        for (int t = 0; t < NT; t++) {
            float v = g_s[b * NT + t];
            if (v > mx) mx = v;
            w[t] = v;
        }
        float s = 0.f;
        for (int t = 0; t < NT; t++) { w[t] = __expf(w[t] - mx); s += w[t]; }
        float inv = __fdividef(1.f, s);
        for (int t = 0; t < NT; t++) w[t] *= inv;
    }
    __syncthreads();
    for (int d = tid; d < 2 * NH; d += 256) {
        float s = 0.f;
        for (int t = 0; t < NT; t++)
            s += w[t] * g_gru[(b * NT + t) * (2 * NH) + d];
        g_c[b * 2 * NH + d] = s;
    }
}

// ---------------- joint head + forward kinematics --------------------------------
__global__ void __launch_bounds__(256) joints_fk(
    const float* __restrict__ jW, const float* __restrict__ jb,
    float* __restrict__ out)
{
    int w = blockIdx.x * 8 + (threadIdx.x >> 5);
    int lane = threadIdx.x & 31;
    if (w >= NB * NT) return;
    int b = w / NT;
    const float* row  = &g_gru[w * 512];
    const float* crow = &g_c[b * 512];
    float p[6] = {};
    #pragma unroll
    for (int k = 0; k < 16; k++) {
        int d = lane + k * 32;
        float x = row[d] + crow[d];
        #pragma unroll
        for (int j = 0; j < 6; j++) p[j] += x * jW[j * 512 + d];
    }
    #pragma unroll
    for (int o = 16; o > 0; o >>= 1)
        #pragma unroll
        for (int j = 0; j < 6; j++) p[j] += __shfl_xor_sync(0xffffffffu, p[j], o);
    if (lane != 0) return;

    const float LO[6] = {-3.1416f, -1.5708f, -3.1416f, -2.6f, -1.5708f, -1.2f};
    const float UP[6] = { 3.1416f,  1.5708f,  3.1416f,  0.1f,  1.5708f,  1.2f};
    float th[6];
    #pragma unroll
    for (int j = 0; j < 6; j++)
        th[j] = (p[j] + jb[j]) * (UP[j] - LO[j]) + LO[j];

    float c0[3] = {1.f, 0.f, 0.f}, c1[3] = {0.f, 1.f, 0.f}, c2[3] = {0.f, 0.f, 1.f};
    float px = 0.f, py = 0.f, pz = 0.10f;
    float sh2x = 0.f, sh2y = 0.f, sh2z = 0.10f;

    float c, s, tmp;
    c = cosf(th[0]); s = sinf(th[0]);
    #pragma unroll
    for (int i = 0; i < 3; i++) { tmp = c*c0[i] + s*c1[i]; c1[i] = c*c1[i] - s*c0[i]; c0[i] = tmp; }
    c = cosf(th[1]); s = sinf(th[1]);
    #pragma unroll
    for (int i = 0; i < 3; i++) { tmp = c*c1[i] + s*c2[i]; c2[i] = c*c2[i] - s*c1[i]; c1[i] = tmp; }
    c = cosf(th[2]); s = sinf(th[2]);
    #pragma unroll
    for (int i = 0; i < 3; i++) { tmp = c*c0[i] - s*c2[i]; c2[i] = c*c2[i] + s*c0[i]; c0[i] = tmp; }
    px -= 0.25f * c1[0]; py -= 0.25f * c1[1]; pz -= 0.25f * c1[2];
    float fax = px, fay = py, faz = pz;
    c = cosf(th[3]); s = sinf(th[3]);
    #pragma unroll
    for (int i = 0; i < 3; i++) { tmp = c*c1[i] + s*c2[i]; c2[i] = c*c2[i] - s*c1[i]; c1[i] = tmp; }
    c = cosf(th[4]); s = sinf(th[4]);
    #pragma unroll
    for (int i = 0; i < 3; i++) { tmp = c*c0[i] - s*c2[i]; c2[i] = c*c2[i] + s*c0[i]; c0[i] = tmp; }
    px -= 0.25f * c1[0]; py -= 0.25f * c1[1]; pz -= 0.25f * c1[2];
    float wx = px, wy = py, wz = pz;
    c = cosf(th[5]); s = sinf(th[5]);
    #pragma unroll
    for (int i = 0; i < 3; i++) { tmp = c*c1[i] + s*c2[i]; c2[i] = c*c2[i] - s*c1[i]; c1[i] = tmp; }

    float f1x = wx - 0.08f*c1[0] + 0.02f*c2[0];
    float f1y = wy - 0.08f*c1[1] + 0.02f*c2[1];
    float f1z = wz - 0.08f*c1[2] + 0.02f*c2[2];
    float f4x = wx - 0.08f*c1[0] - 0.02f*c2[0];
    float f4y = wy - 0.08f*c1[1] - 0.02f*c2[1];
    float f4z = wz - 0.08f*c1[2] - 0.02f*c2[2];

    float d1x = sh2x - fax, d1y = sh2y - fay, d1z = sh2z - faz;
    float d2x = wx - fax,   d2y = wy - fay,   d2z = wz - faz;
    float bodyL = 0.5f * (sqrtf(d1x*d1x + d1y*d1y + d1z*d1z)
                        + sqrtf(d2x*d2x + d2y*d2y + d2z*d2z));
    float inv = 1.f / bodyL;

    float* o = out + (long)w * 9;
    o[0] = (wx  - sh2x) * inv; o[1] = (wy  - sh2y) * inv; o[2] = (wz  - sh2z) * inv;
    o[3] = (f1x - sh2x) * inv; o[4] = (f1y - sh2y) * inv; o[5] = (f1z - sh2z) * inv;
    o[6] = (f4x - sh2x) * inv; o[7] = (f4y - sh2y) * inv; o[8] = (f4z - sh2z) * inv;
}

// ---------------- host launcher ---------------------------------------------------
extern "C" void kernel_launch(void* const* d_in, const int* in_sizes, int n_in,
                              void* d_out, int out_size)
{
    const float* z       = (const float*)d_in[0];
    const float* W_fc    = (const float*)d_in[1];
    const float* b_fc    = (const float*)d_in[2];
    const float* bn_g    = (const float*)d_in[3];
    const float* bn_b    = (const float*)d_in[4];
    const float* Wih_f   = (const float*)d_in[5];
    const float* Whh_f   = (const float*)d_in[6];
    const float* bih_f   = (const float*)d_in[7];
    const float* bhh_f   = (const float*)d_in[8];
    const float* Wih_b   = (const float*)d_in[9];
    const float* Whh_b   = (const float*)d_in[10];
    const float* bih_b   = (const float*)d_in[11];
    const float* bhh_b   = (const float*)d_in[12];
    const float* attn_W1 = (const float*)d_in[13];
    const float* attn_b1 = (const float*)d_in[14];
    const float* attn_W2 = (const float*)d_in[15];
    const float* joint_W = (const float*)d_in[16];
    const float* joint_b = (const float*)d_in[17];
    float* out = (float*)d_out;

    static int smem_set = 0;
    const int gru_smem = (8 * SLAB + 2 * ATILE) * 2;
    if (!smem_set) {
        cudaFuncSetAttribute(gru_persist,
            cudaFuncAttributeMaxDynamicSharedMemorySize, gru_smem);
        smem_set = 1;
    }

    // 1) fc GEMM + weight split + flag reset (fused)
    fc_prep<<<1024, 256>>>(z, W_fc, b_fc, Whh_f, Whh_b, attn_W1);
    // 2) batch stats
    bn_stats<<<ND, 256>>>();
    // 3) gate GEMM with fused BN+LeakyReLU, both dirs
    gemm_gates_bn<<<dim3(3 * NH / 64, NB / 64, 2), 256>>>(
        Wih_f, bih_f, Wih_b, bih_b, bn_g, bn_b);
    // 4) GRU recurrence (persistent, LDSM fragments)  <- ncu capture slot
    gru_persist<<<128, 256, gru_smem>>>(bhh_f, bhh_b);
    // 5) attention scores
    attn_mma<<<NB * NT / 64, 256>>>(attn_b1, attn_W2);
    // 6) softmax + context
    softmax_ctx<<<NB, 256>>>();
    // 7) joint head + FK
    joints_fk<<<NB * NT / 8, 256>>>(joint_W, joint_b, out);
}

// round 9
// speedup vs baseline: 1.7681x; 1.3318x over previous
#include <cuda_runtime.h>
#include <cuda_bf16.h>
#include <math.h>
#include <stdint.h>

#define NB   2048
#define NT   60
#define NDL  100
#define ND   512
#define NH   256

// ---------------- scratch (device globals) ----------------
__device__ float g_h0[NB * ND];
__device__ float g_stats[2 * ND];
__device__ float g_gates[2][NB * 3 * NH];          // x@Wih^T + bih (fp32)
__device__ __nv_bfloat16 g_whh[2][3 * NH * NH];    // Whh split hi
__device__ __nv_bfloat16 g_whl[2][3 * NH * NH];    // Whh split lo
__device__ __nv_bfloat16 g_w1h[NH * 2 * NH];       // attn_W1 split hi
__device__ __nv_bfloat16 g_w1l[NH * 2 * NH];       // attn_W1 split lo
__device__ __nv_bfloat16 g_gruh[NB * NT * 2 * NH]; // gru out bf16 hi (= state!)
__device__ __nv_bfloat16 g_grul[NB * NT * 2 * NH]; // gru out bf16 lo
__device__ float g_s[NB * NT];
__device__ int   g_sync[2 * 16 * NT];              // group flags [dir][mtile][t]

__device__ __forceinline__ void bsplit(float v, __nv_bfloat16& h, __nv_bfloat16& l) {
    h = __float2bfloat16(v);
    l = __float2bfloat16(v - __bfloat162float(h));
}

__device__ __forceinline__ void mma16816(float& d0, float& d1, float& d2, float& d3,
    uint32_t a0, uint32_t a1, uint32_t a2, uint32_t a3, uint32_t b0, uint32_t b1)
{
    asm volatile("mma.sync.aligned.m16n8k16.row.col.f32.bf16.bf16.f32 "
                 "{%0,%1,%2,%3},{%4,%5,%6,%7},{%8,%9},{%0,%1,%2,%3};"
                 : "+f"(d0), "+f"(d1), "+f"(d2), "+f"(d3)
                 : "r"(a0), "r"(a1), "r"(a2), "r"(a3), "r"(b0), "r"(b1));
}

#define LDSM4(r0, r1, r2, r3, addr) \
    asm volatile("ldmatrix.sync.aligned.m8n8.x4.shared.b16 {%0,%1,%2,%3}, [%4];" \
                 : "=r"(r0), "=r"(r1), "=r"(r2), "=r"(r3) : "r"(addr))

__device__ __forceinline__ void cpasync16(void* sdst, const void* gsrc) {
    uint32_t s = (uint32_t)__cvta_generic_to_shared(sdst);
    asm volatile("cp.async.cg.shared.global [%0], [%1], 16;" :: "r"(s), "l"(gsrc));
}
#define CP_COMMIT() asm volatile("cp.async.commit_group;")
#define CP_WAIT0()  asm volatile("cp.async.wait_group 0;")

__device__ __forceinline__ float ftanh_hw(float x) {
    float r;
    asm("tanh.approx.f32 %0, %1;" : "=f"(r) : "f"(x));
    return r;
}
__device__ __forceinline__ float fsig_hw(float x) {
    return fmaf(ftanh_hw(0.5f * x), 0.5f, 0.5f);
}
__device__ __forceinline__ float b2f(__nv_bfloat16 v) { return __bfloat162float(v); }

// swizzled smem index (elements): stride 64, XOR 8-col blocks by (row&7).
__device__ __forceinline__ int swzidx(int r, int c) {
    return r * 64 + ((((c >> 3) ^ (r & 7)) << 3) | (c & 7));
}

// ---------------- fused fc GEMM + weight split + flag reset ----------------------
__global__ void __launch_bounds__(256) fc_prep(
    const float* __restrict__ z, const float* __restrict__ W_fc,
    const float* __restrict__ b_fc,
    const float* __restrict__ Whh_f, const float* __restrict__ Whh_b,
    const float* __restrict__ W1)
{
    __shared__ float As[16][65];
    __shared__ float Bs[16][65];
    if (blockIdx.x < 256) {
        const int N = ND, K = NDL;
        int tid = threadIdx.x;
        int tx = tid & 15, ty = tid >> 4;
        int m0 = (blockIdx.x >> 3) * 64, n0 = (blockIdx.x & 7) * 64;
        float acc[4][4] = {};
        for (int k0 = 0; k0 < K; k0 += 16) {
            #pragma unroll
            for (int i = 0; i < 4; i++) {
                int lin = tid + i * 256;
                int m = lin >> 4, k = lin & 15;
                As[k][m] = (k0 + k < K) ? z[(m0 + m) * K + k0 + k] : 0.f;
            }
            #pragma unroll
            for (int i = 0; i < 4; i++) {
                int lin = tid + i * 256;
                int n = lin >> 4, k = lin & 15;
                Bs[k][n] = (k0 + k < K) ? W_fc[(n0 + n) * K + k0 + k] : 0.f;
            }
            __syncthreads();
            #pragma unroll
            for (int kk = 0; kk < 16; kk++) {
                float a[4], b[4];
                #pragma unroll
                for (int i = 0; i < 4; i++) a[i] = As[kk][ty * 4 + i];
                #pragma unroll
                for (int j = 0; j < 4; j++) b[j] = Bs[kk][tx * 4 + j];
                #pragma unroll
                for (int i = 0; i < 4; i++)
                    #pragma unroll
                    for (int j = 0; j < 4; j++) acc[i][j] += a[i] * b[j];
            }
            __syncthreads();
        }
        #pragma unroll
        for (int i = 0; i < 4; i++) {
            int m = m0 + ty * 4 + i;
            #pragma unroll
            for (int j = 0; j < 4; j++) {
                int n = n0 + tx * 4 + j;
                g_h0[m * N + n] = acc[i][j] + b_fc[n];
            }
        }
    } else {
        int i = (blockIdx.x - 256) * 256 + threadIdx.x;
        bsplit(Whh_f[i], g_whh[0][i], g_whl[0][i]);
        bsplit(Whh_b[i], g_whh[1][i], g_whl[1][i]);
        if (i < NH * 2 * NH) bsplit(W1[i], g_w1h[i], g_w1l[i]);
        if (i < 2 * 16 * NT) g_sync[i] = 0;
    }
}

// ---------------- batchnorm stats -------------------------------------------------
__global__ void __launch_bounds__(256) bn_stats()
{
    int c = blockIdx.x;
    float s = 0.f, s2 = 0.f;
    for (int r = threadIdx.x; r < NB; r += 256) {
        float v = g_h0[r * ND + c];
        s += v; s2 += v * v;
    }
    __shared__ float sh[256], sh2[256];
    sh[threadIdx.x] = s; sh2[threadIdx.x] = s2;
    __syncthreads();
    for (int o = 128; o > 0; o >>= 1) {
        if (threadIdx.x < o) {
            sh[threadIdx.x]  += sh[threadIdx.x + o];
            sh2[threadIdx.x] += sh2[threadIdx.x + o];
        }
        __syncthreads();
    }
    if (threadIdx.x == 0) {
        float mu = sh[0] / (float)NB;
        g_stats[c] = mu;
        g_stats[ND + c] = sh2[0] / (float)NB - mu * mu;
    }
}

// ---- gate GEMM with fused BatchNorm+LeakyReLU on the A operand ------------------
__global__ void __launch_bounds__(256) gemm_gates_bn(
    const float* __restrict__ Wf, const float* __restrict__ bf,
    const float* __restrict__ Wb, const float* __restrict__ bb,
    const float* __restrict__ bn_g, const float* __restrict__ bn_b)
{
    const float* Bw   = blockIdx.z ? Wb : Wf;
    const float* bias = blockIdx.z ? bb : bf;
    float* C = g_gates[blockIdx.z];
    const int N = 3 * NH, K = ND;
    __shared__ float As[16][65];
    __shared__ float Bs[16][65];
    int tid = threadIdx.x;
    int tx = tid & 15, ty = tid >> 4;
    int m0 = blockIdx.y * 64, n0 = blockIdx.x * 64;
    float acc[4][4] = {};
    for (int k0 = 0; k0 < K; k0 += 16) {
        {
            const int k = tid & 15;
            const int c = k0 + k;
            const float mu = g_stats[c], var = g_stats[ND + c];
            const float scale = rsqrtf(var + 1e-5f) * bn_g[c];
            const float shift = bn_b[c] - mu * scale;
            #pragma unroll
            for (int i = 0; i < 4; i++) {
                int m = (tid >> 4) + i * 16;
                float v = g_h0[(m0 + m) * K + c] * scale + shift;
                As[k][m] = (v >= 0.f) ? v : 0.2f * v;
            }
        }
        #pragma unroll
        for (int i = 0; i < 4; i++) {
            int lin = tid + i * 256;
            int n = lin >> 4, k = lin & 15;
            Bs[k][n] = Bw[(n0 + n) * K + k0 + k];
        }
        __syncthreads();
        #pragma unroll
        for (int kk = 0; kk < 16; kk++) {
            float a[4], b[4];
            #pragma unroll
            for (int i = 0; i < 4; i++) a[i] = As[kk][ty * 4 + i];
            #pragma unroll
            for (int j = 0; j < 4; j++) b[j] = Bs[kk][tx * 4 + j];
            #pragma unroll
            for (int i = 0; i < 4; i++)
                #pragma unroll
                for (int j = 0; j < 4; j++) acc[i][j] += a[i] * b[j];
        }
        __syncthreads();
    }
    #pragma unroll
    for (int i = 0; i < 4; i++) {
        int m = m0 + ty * 4 + i;
        #pragma unroll
        for (int j = 0; j < 4; j++) {
            int n = n0 + tx * 4 + j;
            C[m * N + n] = acc[i][j] + bias[n];
        }
    }
}

// ---------------- LDSM-based MMA inner blocks ------------------------------------
__device__ __forceinline__ void ldsm_afrags(
    uint32_t As_u32, uint32_t afr[4][4], int wm, int lane, int kk)
{
    const int g = lane >> 3, lr = lane & 7;
    const int scol = kk * 2 + (g >> 1);
    #pragma unroll
    for (int mt = 0; mt < 4; mt++) {
        const int row = wm * 64 + mt * 16 + ((g & 1) << 3) + lr;
        const uint32_t addr = As_u32 + row * 128 + ((scol ^ (row & 7)) << 4);
        LDSM4(afr[mt][0], afr[mt][1], afr[mt][2], afr[mt][3], addr);
    }
}

__device__ __forceinline__ void ldsm_bfrags(
    uint32_t Bs_u32, uint32_t bfr[6][2], int wj, int lane, int kk)
{
    const int g = lane >> 3, lr = lane & 7;
    const int scol = kk * 2 + (g & 1);
    #pragma unroll
    for (int q = 0; q < 3; q++) {
        const int nt = 2 * q + (g >> 1);
        const int row = (nt >> 1) * 64 + wj * 16 + (nt & 1) * 8 + lr;
        const uint32_t addr = Bs_u32 + row * 128 + ((scol ^ (row & 7)) << 4);
        LDSM4(bfr[2 * q][0], bfr[2 * q][1], bfr[2 * q + 1][0], bfr[2 * q + 1][1], addr);
    }
}

__device__ __forceinline__ void mma_all(
    const uint32_t afr[4][4], const uint32_t bfr[6][2], float acc[4][6][4])
{
    #pragma unroll
    for (int mt = 0; mt < 4; mt++)
        #pragma unroll
        for (int nt = 0; nt < 6; nt++)
            mma16816(acc[mt][nt][0], acc[mt][nt][1], acc[mt][nt][2], acc[mt][nt][3],
                     afr[mt][0], afr[mt][1], afr[mt][2], afr[mt][3],
                     bfr[nt][0], bfr[nt][1]);
}

__device__ __forceinline__ void mma_block2(
    uint32_t As_u32, uint32_t Bs1_u32, uint32_t Bs2_u32,
    float acc[4][6][4], int wm, int wj, int lane)
{
    #pragma unroll
    for (int kk = 0; kk < 4; kk++) {
        uint32_t afr[4][4], bfr[6][2];
        ldsm_afrags(As_u32, afr, wm, lane, kk);
        ldsm_bfrags(Bs1_u32, bfr, wj, lane, kk);
        mma_all(afr, bfr, acc);
        ldsm_bfrags(Bs2_u32, bfr, wj, lane, kk);
        mma_all(afr, bfr, acc);
    }
}

__device__ __forceinline__ void mma_block1(
    uint32_t As_u32, uint32_t Bs_u32,
    float acc[4][6][4], int wm, int wj, int lane)
{
    #pragma unroll
    for (int kk = 0; kk < 4; kk++) {
        uint32_t afr[4][4], bfr[6][2];
        ldsm_afrags(As_u32, afr, wm, lane, kk);
        ldsm_bfrags(Bs_u32, bfr, wj, lane, kk);
        mma_all(afr, bfr, acc);
    }
}

// ---------------- persistent GRU: state lives in g_gruh/g_grul time-slots --------
#define SLAB (192 * 64)
#define ATILE (128 * 64)
__global__ void __launch_bounds__(256) gru_persist(
    const float* __restrict__ bhh_f, const float* __restrict__ bhh_b)
{
    extern __shared__ __nv_bfloat16 smem[];
    __nv_bfloat16* Bsh = smem;
    __nv_bfloat16* Bsl = smem + 4 * SLAB;
    __nv_bfloat16* A0  = smem + 8 * SLAB;
    __nv_bfloat16* A1  = A0 + ATILE;
    const uint32_t Bsh_u32 = (uint32_t)__cvta_generic_to_shared(Bsh);
    const uint32_t Bsl_u32 = (uint32_t)__cvta_generic_to_shared(Bsl);
    const uint32_t A0_u32  = (uint32_t)__cvta_generic_to_shared(A0);
    const uint32_t A1_u32  = (uint32_t)__cvta_generic_to_shared(A1);
    const uint32_t SLAB_B  = SLAB * 2;

    const int bid = blockIdx.x;
    const int dir = bid >> 6;
    const int sub = bid & 63;
    const int j0 = (sub & 3) * 64;
    const int mtile = sub >> 2;
    const int m0 = mtile * 128;
    int* const flag = &g_sync[(dir * 16 + mtile) * NT];

    const float* bhh = dir ? bhh_b : bhh_f;
    const float* gin = g_gates[dir];
    const __nv_bfloat16* __restrict__ wh = g_whh[dir];
    const __nv_bfloat16* __restrict__ wl = g_whl[dir];

    const int tid = threadIdx.x;
    const int warp = tid >> 5, lane = tid & 31;
    const int wm = warp >> 2, wj = warp & 3;
    const int gID = lane >> 2, tig = lane & 3;

    int lr[4], lc[4];
    #pragma unroll
    for (int i = 0; i < 4; i++) {
        int u = tid + 256 * i;
        lr[i] = u >> 3; lc[i] = (u & 7) * 8;
    }

    // load Whh hi/lo into smem once
    #pragma unroll
    for (int i = 0; i < 24; i++) {
        int u = tid + 256 * i;
        int r = u >> 5;
        int c = (u & 31) * 8;
        int slab = c >> 6, cs = c & 63;
        int g = r >> 6, j = j0 + (r & 63);
        *(uint4*)&Bsh[slab * SLAB + swzidx(r, cs)] =
            *(const uint4*)&wh[(g * NH + j) * NH + c];
        *(uint4*)&Bsl[slab * SLAB + swzidx(r, cs)] =
            *(const uint4*)&wl[(g * NH + j) * NH + c];
    }
    __syncthreads();

    for (int t = 0; t < NT; t++) {
        const int tt  = dir ? (NT - 1 - t) : t;        // this step's slot
        const int ttp = dir ? (NT - t) : (t - 1);      // previous step's slot

        float acc[4][6][4];
        #pragma unroll
        for (int a = 0; a < 4; a++)
            #pragma unroll
            for (int b = 0; b < 6; b++)
                #pragma unroll
                for (int q = 0; q < 4; q++) acc[a][b][q] = 0.f;

        if (t > 0) {
            if (tid == 0) {
                while (*(volatile int*)&flag[t - 1] < 4) { }
                __threadfence();
            }
            __syncthreads();

            // A source: previous time-slot rows of g_gruh/g_grul, this dir's half
            #pragma unroll
            for (int i = 0; i < 4; i++)
                cpasync16(&A0[swzidx(lr[i], lc[i])],
                          &g_gruh[((size_t)(m0 + lr[i]) * NT + ttp) * 512 + dir * NH + lc[i]]);
            CP_COMMIT();
            for (int ksl = 0; ksl < 4; ksl++) {
                const int ks = ksl * 64;
                CP_WAIT0(); __syncthreads();
                #pragma unroll
                for (int i = 0; i < 4; i++)
                    cpasync16(&A1[swzidx(lr[i], lc[i])],
                              &g_grul[((size_t)(m0 + lr[i]) * NT + ttp) * 512 + dir * NH + ks + lc[i]]);
                CP_COMMIT();
                mma_block2(A0_u32, Bsl_u32 + ksl * SLAB_B, Bsh_u32 + ksl * SLAB_B,
                           acc, wm, wj, lane);
                CP_WAIT0(); __syncthreads();
                if (ksl < 3) {
                    #pragma unroll
                    for (int i = 0; i < 4; i++)
                        cpasync16(&A0[swzidx(lr[i], lc[i])],
                                  &g_gruh[((size_t)(m0 + lr[i]) * NT + ttp) * 512 + dir * NH + ks + 64 + lc[i]]);
                    CP_COMMIT();
                }
                mma_block1(A1_u32, Bsh_u32 + ksl * SLAB_B, acc, wm, wj, lane);
            }
        }

        // epilogue: writes ONLY the two bf16 arrays (4 B/element)
        #pragma unroll
        for (int mt = 0; mt < 4; mt++)
            #pragma unroll
            for (int part = 0; part < 2; part++) {
                const int m = m0 + wm * 64 + mt * 16 + gID + part * 8;
                #pragma unroll
                for (int jn = 0; jn < 2; jn++) {
                    const int jg = j0 + wj * 16 + jn * 8 + tig * 2;
                    float hn2[2];
                    #pragma unroll
                    for (int cc = 0; cc < 2; cc++) {
                        const int j = jg + cc;
                        float ghr = acc[mt][jn][part * 2 + cc]     + bhh[j];
                        float ghz = acc[mt][2 + jn][part * 2 + cc] + bhh[NH + j];
                        float ghn = acc[mt][4 + jn][part * 2 + cc] + bhh[2 * NH + j];
                        const float* gp = gin + m * 3 * NH + j;
                        float r  = fsig_hw(gp[0] + ghr);
                        float zz = fsig_hw(gp[NH] + ghz);
                        float nn = ftanh_hw(gp[2 * NH] + r * ghn);
                        float hold = 0.f;
                        if (t > 0) {
                            size_t hp = ((size_t)m * NT + ttp) * 512 + dir * NH + j;
                            hold = b2f(g_gruh[hp]) + b2f(g_grul[hp]);
                        }
                        hn2[cc] = (1.f - zz) * nn + zz * hold;
                    }
                    __nv_bfloat16 h0, l0, h1, l1;
                    bsplit(hn2[0], h0, l0);
                    bsplit(hn2[1], h1, l1);
                    __nv_bfloat162 vh, vl;
                    vh.x = h0; vh.y = h1; vl.x = l0; vl.y = l1;
                    size_t go = ((size_t)m * NT + tt) * 512 + dir * NH + jg;
                    *(__nv_bfloat162*)(g_gruh + go) = vh;
                    *(__nv_bfloat162*)(g_grul + go) = vl;
                }
            }

        if (t < NT - 1) {
            __syncthreads();
            if (tid == 0) {
                __threadfence();
                atomicAdd(&flag[t], 1);
            }
        }
    }
}

// ---------------- attention scores via bf16-split MMA ----------------------------
__global__ void __launch_bounds__(256) attn_mma(
    const float* __restrict__ b1, const float* __restrict__ W2)
{
    __shared__ __nv_bfloat16 As[64 * 72];
    __shared__ __nv_bfloat16 Bs[256 * 72];
    __shared__ float red[64];

    const int tid = threadIdx.x;
    const int m0 = blockIdx.x * 64;
    const int warp = tid >> 5, lane = tid & 31;
    const int wm = warp >> 2, wj = warp & 3;
    const int gID = lane >> 2, tig = lane & 3;
    if (tid < 64) red[tid] = 0.f;

    float acc[2][8][4];
    #pragma unroll
    for (int a = 0; a < 2; a++)
        #pragma unroll
        for (int b = 0; b < 8; b++)
            #pragma unroll
            for (int q = 0; q < 4; q++) acc[a][b][q] = 0.f;

    for (int it = 0; it < 24; it++) {
        const int ks = (it / 3) * 64;
        const int ph = it % 3;
        const bool loadA = (ph != 1);
        const bool loadB = (ph != 2);
        const __nv_bfloat16* __restrict__ asrc = (ph == 2) ? g_grul : g_gruh;
        const __nv_bfloat16* __restrict__ bsrc = (ph == 0) ? g_w1l : g_w1h;
        if (it > 0) __syncthreads();
        if (loadA) {
            #pragma unroll
            for (int i = 0; i < 2; i++) {
                int u = tid + 256 * i;
                int r = u >> 3, c = (u & 7) << 3;
                *(uint4*)&As[r * 72 + c] =
                    *(const uint4*)&asrc[(size_t)(m0 + r) * 512 + ks + c];
            }
        }
        if (loadB) {
            #pragma unroll
            for (int i = 0; i < 8; i++) {
                int u = tid + 256 * i;
                int r = u >> 3, c = (u & 7) << 3;
                *(uint4*)&Bs[r * 72 + c] =
                    *(const uint4*)&bsrc[r * 512 + ks + c];
            }
        }
        __syncthreads();
        #pragma unroll
        for (int kk = 0; kk < 4; kk++) {
            const int kb = kk * 16 + tig * 2;
            uint32_t afr[2][4], bfr[8][2];
            #pragma unroll
            for (int mt = 0; mt < 2; mt++) {
                const __nv_bfloat16* p = As + (wm * 32 + mt * 16 + gID) * 72 + kb;
                afr[mt][0] = *(const uint32_t*)p;
                afr[mt][1] = *(const uint32_t*)(p + 8 * 72);
                afr[mt][2] = *(const uint32_t*)(p + 8);
                afr[mt][3] = *(const uint32_t*)(p + 8 * 72 + 8);
            }
            #pragma unroll
            for (int nt = 0; nt < 8; nt++) {
                const __nv_bfloat16* p = Bs + (wj * 64 + nt * 8 + gID) * 72 + kb;
                bfr[nt][0] = *(const uint32_t*)p;
                bfr[nt][1] = *(const uint32_t*)(p + 8);
            }
            #pragma unroll
            for (int mt = 0; mt < 2; mt++)
                #pragma unroll
                for (int nt = 0; nt < 8; nt++)
                    mma16816(acc[mt][nt][0], acc[mt][nt][1],
                             acc[mt][nt][2], acc[mt][nt][3],
                             afr[mt][0], afr[mt][1], afr[mt][2], afr[mt][3],
                             bfr[nt][0], bfr[nt][1]);
        }
    }

    #pragma unroll
    for (int mt = 0; mt < 2; mt++)
        #pragma unroll
        for (int part = 0; part < 2; part++) {
            float s = 0.f;
            #pragma unroll
            for (int nt = 0; nt < 8; nt++)
                #pragma unroll
                for (int cc = 0; cc < 2; cc++) {
                    int n = wj * 64 + nt * 8 + tig * 2 + cc;
                    s += ftanh_hw(acc[mt][nt][part * 2 + cc] + b1[n]) * W2[n];
                }
            s += __shfl_xor_sync(0xffffffffu, s, 1);
            s += __shfl_xor_sync(0xffffffffu, s, 2);
            if (tig == 0)
                atomicAdd(&red[wm * 32 + mt * 16 + gID + part * 8], s);
        }
    __syncthreads();
    if (tid < 64) g_s[m0 + tid] = red[tid];
}

// ---------------- fused softmax + context + joint head + FK ----------------------
// One block per batch element. joints[t] = row[t].jW + c.jW + jb (c = sum w[t] row[t]).
__global__ void __launch_bounds__(256) ctx_fk(
    const float* __restrict__ jW, const float* __restrict__ jb,
    float* __restrict__ out)
{
    const int b = blockIdx.x;
    const int tid = threadIdx.x;
    const int warp = tid >> 5, lane = tid & 31;

    __shared__ float jWs[6][512];
    __shared__ float w[NT];
    __shared__ float csh[512];
    __shared__ float p1sh[NT][8];
    __shared__ float cJ[8];

    for (int i = tid; i < 6 * 512; i += 256) jWs[i >> 9][i & 511] = jW[i];
    for (int i = tid; i < 512; i += 256) csh[i] = 0.f;
    if (tid == 0) {            // softmax over time (60 values, serial is fine)
        float mx = -1e30f;
        float tmpv[NT];
        for (int t = 0; t < NT; t++) {
            tmpv[t] = g_s[b * NT + t];
            if (tmpv[t] > mx) mx = tmpv[t];
        }
        float s = 0.f;
        for (int t = 0; t < NT; t++) { tmpv[t] = __expf(tmpv[t] - mx); s += tmpv[t]; }
        float inv = __fdividef(1.f, s);
        for (int t = 0; t < NT; t++) w[t] = tmpv[t] * inv;
    }
    __syncthreads();

    // stream rows once: accumulate context partials + per-t joint dots
    float creg[16];
    #pragma unroll
    for (int k = 0; k < 16; k++) creg[k] = 0.f;

    for (int t = warp; t < NT; t += 8) {
        const __nv_bfloat16* rh = g_gruh + ((size_t)b * NT + t) * 512;
        const __nv_bfloat16* rl = g_grul + ((size_t)b * NT + t) * 512;
        const float wt = w[t];
        float pj[6];
        #pragma unroll
        for (int j = 0; j < 6; j++) pj[j] = 0.f;
        #pragma unroll
        for (int k = 0; k < 16; k++) {
            const int d = lane + 32 * k;
            float x = b2f(rh[d]) + b2f(rl[d]);
            creg[k] += wt * x;
            #pragma unroll
            for (int j = 0; j < 6; j++) pj[j] += x * jWs[j][d];
        }
        #pragma unroll
        for (int o = 16; o > 0; o >>= 1)
            #pragma unroll
            for (int j = 0; j < 6; j++)
                pj[j] += __shfl_xor_sync(0xffffffffu, pj[j], o);
        if (lane == 0) {
            #pragma unroll
            for (int j = 0; j < 6; j++) p1sh[t][j] = pj[j];
        }
    }
    #pragma unroll
    for (int k = 0; k < 16; k++)
        atomicAdd(&csh[lane + 32 * k], creg[k]);
    __syncthreads();

    if (warp == 0) {           // cJ = c . jW
        float pj[6];
        #pragma unroll
        for (int j = 0; j < 6; j++) pj[j] = 0.f;
        #pragma unroll
        for (int k = 0; k < 16; k++) {
            const int d = lane + 32 * k;
            float cv = csh[d];
            #pragma unroll
            for (int j = 0; j < 6; j++) pj[j] += cv * jWs[j][d];
        }
        #pragma unroll
        for (int o = 16; o > 0; o >>= 1)
            #pragma unroll
            for (int j = 0; j < 6; j++)
                pj[j] += __shfl_xor_sync(0xffffffffu, pj[j], o);
        if (lane == 0) {
            #pragma unroll
            for (int j = 0; j < 6; j++) cJ[j] = pj[j];
        }
    }
    __syncthreads();

    if (tid < NT) {            // one thread per timestep: FK
        const int t = tid;
        const float LO[6] = {-3.1416f, -1.5708f, -3.1416f, -2.6f, -1.5708f, -1.2f};
        const float UP[6] = { 3.1416f,  1.5708f,  3.1416f,  0.1f,  1.5708f,  1.2f};
        float th[6];
        #pragma unroll
        for (int j = 0; j < 6; j++)
            th[j] = (p1sh[t][j] + cJ[j] + jb[j]) * (UP[j] - LO[j]) + LO[j];

        float c0[3] = {1.f, 0.f, 0.f}, c1[3] = {0.f, 1.f, 0.f}, c2[3] = {0.f, 0.f, 1.f};
        float px = 0.f, py = 0.f, pz = 0.10f;
        const float sh2x = 0.f, sh2y = 0.f, sh2z = 0.10f;

        float c, s, tmp;
        c = cosf(th[0]); s = sinf(th[0]);
        #pragma unroll
        for (int i = 0; i < 3; i++) { tmp = c*c0[i] + s*c1[i]; c1[i] = c*c1[i] - s*c0[i]; c0[i] = tmp; }
        c = cosf(th[1]); s = sinf(th[1]);
        #pragma unroll
        for (int i = 0; i < 3; i++) { tmp = c*c1[i] + s*c2[i]; c2[i] = c*c2[i] - s*c1[i]; c1[i] = tmp; }
        c = cosf(th[2]); s = sinf(th[2]);
        #pragma unroll
        for (int i = 0; i < 3; i++) { tmp = c*c0[i] - s*c2[i]; c2[i] = c*c2[i] + s*c0[i]; c0[i] = tmp; }
        px -= 0.25f * c1[0]; py -= 0.25f * c1[1]; pz -= 0.25f * c1[2];
        float fax = px, fay = py, faz = pz;
        c = cosf(th[3]); s = sinf(th[3]);
        #pragma unroll
        for (int i = 0; i < 3; i++) { tmp = c*c1[i] + s*c2[i]; c2[i] = c*c2[i] - s*c1[i]; c1[i] = tmp; }
        c = cosf(th[4]); s = sinf(th[4]);
        #pragma unroll
        for (int i = 0; i < 3; i++) { tmp = c*c0[i] - s*c2[i]; c2[i] = c*c2[i] + s*c0[i]; c0[i] = tmp; }
        px -= 0.25f * c1[0]; py -= 0.25f * c1[1]; pz -= 0.25f * c1[2];
        float wx = px, wy = py, wz = pz;
        c = cosf(th[5]); s = sinf(th[5]);
        #pragma unroll
        for (int i = 0; i < 3; i++) { tmp = c*c1[i] + s*c2[i]; c2[i] = c*c2[i] - s*c1[i]; c1[i] = tmp; }

        float f1x = wx - 0.08f*c1[0] + 0.02f*c2[0];
        float f1y = wy - 0.08f*c1[1] + 0.02f*c2[1];
        float f1z = wz - 0.08f*c1[2] + 0.02f*c2[2];
        float f4x = wx - 0.08f*c1[0] - 0.02f*c2[0];
        float f4y = wy - 0.08f*c1[1] - 0.02f*c2[1];
        float f4z = wz - 0.08f*c1[2] - 0.02f*c2[2];

        float d1x = sh2x - fax, d1y = sh2y - fay, d1z = sh2z - faz;
        float d2x = wx - fax,   d2y = wy - fay,   d2z = wz - faz;
        float bodyL = 0.5f * (sqrtf(d1x*d1x + d1y*d1y + d1z*d1z)
                            + sqrtf(d2x*d2x + d2y*d2y + d2z*d2z));
        float inv = 1.f / bodyL;

        float* o = out + ((size_t)b * NT + t) * 9;
        o[0] = (wx  - sh2x) * inv; o[1] = (wy  - sh2y) * inv; o[2] = (wz  - sh2z) * inv;
        o[3] = (f1x - sh2x) * inv; o[4] = (f1y - sh2y) * inv; o[5] = (f1z - sh2z) * inv;
        o[6] = (f4x - sh2x) * inv; o[7] = (f4y - sh2y) * inv; o[8] = (f4z - sh2z) * inv;
    }
}

// ---------------- host launcher ---------------------------------------------------
extern "C" void kernel_launch(void* const* d_in, const int* in_sizes, int n_in,
                              void* d_out, int out_size)
{
    const float* z       = (const float*)d_in[0];
    const float* W_fc    = (const float*)d_in[1];
    const float* b_fc    = (const float*)d_in[2];
    const float* bn_g    = (const float*)d_in[3];
    const float* bn_b    = (const float*)d_in[4];
    const float* Wih_f   = (const float*)d_in[5];
    const float* Whh_f   = (const float*)d_in[6];
    const float* bih_f   = (const float*)d_in[7];
    const float* bhh_f   = (const float*)d_in[8];
    const float* Wih_b   = (const float*)d_in[9];
    const float* Whh_b   = (const float*)d_in[10];
    const float* bih_b   = (const float*)d_in[11];
    const float* bhh_b   = (const float*)d_in[12];
    const float* attn_W1 = (const float*)d_in[13];
    const float* attn_b1 = (const float*)d_in[14];
    const float* attn_W2 = (const float*)d_in[15];
    const float* joint_W = (const float*)d_in[16];
    const float* joint_b = (const float*)d_in[17];
    float* out = (float*)d_out;

    static int smem_set = 0;
    const int gru_smem = (8 * SLAB + 2 * ATILE) * 2;
    if (!smem_set) {
        cudaFuncSetAttribute(gru_persist,
            cudaFuncAttributeMaxDynamicSharedMemorySize, gru_smem);
        smem_set = 1;
    }

    // 1) fc GEMM + weight split + flag reset (fused)
    fc_prep<<<1024, 256>>>(z, W_fc, b_fc, Whh_f, Whh_b, attn_W1);
    // 2) batch stats
    bn_stats<<<ND, 256>>>();
    // 3) gate GEMM with fused BN+LeakyReLU, both dirs
    gemm_gates_bn<<<dim3(3 * NH / 64, NB / 64, 2), 256>>>(
        Wih_f, bih_f, Wih_b, bih_b, bn_g, bn_b);
    // 4) GRU recurrence (persistent; state = output time-slots)
    gru_persist<<<128, 256, gru_smem>>>(bhh_f, bhh_b);
    // 5) attention scores
    attn_mma<<<NB * NT / 64, 256>>>(attn_b1, attn_W2);
    // 6) fused softmax + context + joints + FK
    ctx_fk<<<NB, 256>>>(joint_W, joint_b, out);
}

// round 10
// speedup vs baseline: 1.8918x; 1.0699x over previous
#include <cuda_runtime.h>
#include <cuda_bf16.h>
#include <math.h>
#include <stdint.h>

#define NB   2048
#define NT   60
#define NDL  100
#define ND   512
#define NH   256

// ---------------- scratch (device globals) ----------------
__device__ float g_h0[NB * ND];
__device__ float g_stats[2 * ND];
__device__ float g_gates[2][NB * 3 * NH];          // x@Wih^T + bih (fp32)
__device__ __nv_bfloat16 g_xh[NB * ND];            // BN+lrelu x split hi
__device__ __nv_bfloat16 g_xl[NB * ND];            // BN+lrelu x split lo
__device__ __nv_bfloat16 g_whh[2][3 * NH * NH];    // Whh split hi
__device__ __nv_bfloat16 g_whl[2][3 * NH * NH];    // Whh split lo
__device__ __nv_bfloat16 g_wihh[2][3 * NH * ND];   // Wih split hi
__device__ __nv_bfloat16 g_wihl[2][3 * NH * ND];   // Wih split lo
__device__ __nv_bfloat16 g_w1h[NH * 2 * NH];       // attn_W1 split hi
__device__ __nv_bfloat16 g_w1l[NH * 2 * NH];       // attn_W1 split lo
__device__ __nv_bfloat16 g_gruh[NB * NT * 2 * NH]; // gru out bf16 hi (= state)
__device__ __nv_bfloat16 g_grul[NB * NT * 2 * NH]; // gru out bf16 lo
__device__ float g_s[NB * NT];
__device__ int   g_sync[2 * 16 * NT];              // group flags [dir][mtile][t]

__device__ __forceinline__ void bsplit(float v, __nv_bfloat16& h, __nv_bfloat16& l) {
    h = __float2bfloat16(v);
    l = __float2bfloat16(v - __bfloat162float(h));
}

__device__ __forceinline__ void mma16816(float& d0, float& d1, float& d2, float& d3,
    uint32_t a0, uint32_t a1, uint32_t a2, uint32_t a3, uint32_t b0, uint32_t b1)
{
    asm volatile("mma.sync.aligned.m16n8k16.row.col.f32.bf16.bf16.f32 "
                 "{%0,%1,%2,%3},{%4,%5,%6,%7},{%8,%9},{%0,%1,%2,%3};"
                 : "+f"(d0), "+f"(d1), "+f"(d2), "+f"(d3)
                 : "r"(a0), "r"(a1), "r"(a2), "r"(a3), "r"(b0), "r"(b1));
}

#define LDSM4(r0, r1, r2, r3, addr) \
    asm volatile("ldmatrix.sync.aligned.m8n8.x4.shared.b16 {%0,%1,%2,%3}, [%4];" \
                 : "=r"(r0), "=r"(r1), "=r"(r2), "=r"(r3) : "r"(addr))

__device__ __forceinline__ void cpasync16(void* sdst, const void* gsrc) {
    uint32_t s = (uint32_t)__cvta_generic_to_shared(sdst);
    asm volatile("cp.async.cg.shared.global [%0], [%1], 16;" :: "r"(s), "l"(gsrc));
}
#define CP_COMMIT() asm volatile("cp.async.commit_group;")
#define CP_WAIT0()  asm volatile("cp.async.wait_group 0;")

__device__ __forceinline__ float ftanh_hw(float x) {
    float r;
    asm("tanh.approx.f32 %0, %1;" : "=f"(r) : "f"(x));
    return r;
}
__device__ __forceinline__ float fsig_hw(float x) {
    return fmaf(ftanh_hw(0.5f * x), 0.5f, 0.5f);
}
__device__ __forceinline__ float b2f(__nv_bfloat16 v) { return __bfloat162float(v); }

// swizzled smem index (elements): stride 64, XOR 8-col blocks by (row&7).
__device__ __forceinline__ int swzidx(int r, int c) {
    return r * 64 + ((((c >> 3) ^ (r & 7)) << 3) | (c & 7));
}

// ---------------- fused fc GEMM + weight splits + flag reset ---------------------
// blocks [0,256): fc GEMM tiles. blocks [256,1792): splits (Wih range = 393216).
__global__ void __launch_bounds__(256) fc_prep(
    const float* __restrict__ z, const float* __restrict__ W_fc,
    const float* __restrict__ b_fc,
    const float* __restrict__ Whh_f, const float* __restrict__ Whh_b,
    const float* __restrict__ Wih_f, const float* __restrict__ Wih_b,
    const float* __restrict__ W1)
{
    __shared__ float As[16][65];
    __shared__ float Bs[16][65];
    if (blockIdx.x < 256) {
        const int N = ND, K = NDL;
        int tid = threadIdx.x;
        int tx = tid & 15, ty = tid >> 4;
        int m0 = (blockIdx.x >> 3) * 64, n0 = (blockIdx.x & 7) * 64;
        float acc[4][4] = {};
        for (int k0 = 0; k0 < K; k0 += 16) {
            #pragma unroll
            for (int i = 0; i < 4; i++) {
                int lin = tid + i * 256;
                int m = lin >> 4, k = lin & 15;
                As[k][m] = (k0 + k < K) ? z[(m0 + m) * K + k0 + k] : 0.f;
            }
            #pragma unroll
            for (int i = 0; i < 4; i++) {
                int lin = tid + i * 256;
                int n = lin >> 4, k = lin & 15;
                Bs[k][n] = (k0 + k < K) ? W_fc[(n0 + n) * K + k0 + k] : 0.f;
            }
            __syncthreads();
            #pragma unroll
            for (int kk = 0; kk < 16; kk++) {
                float a[4], b[4];
                #pragma unroll
                for (int i = 0; i < 4; i++) a[i] = As[kk][ty * 4 + i];
                #pragma unroll
                for (int j = 0; j < 4; j++) b[j] = Bs[kk][tx * 4 + j];
                #pragma unroll
                for (int i = 0; i < 4; i++)
                    #pragma unroll
                    for (int j = 0; j < 4; j++) acc[i][j] += a[i] * b[j];
            }
            __syncthreads();
        }
        #pragma unroll
        for (int i = 0; i < 4; i++) {
            int m = m0 + ty * 4 + i;
            #pragma unroll
            for (int j = 0; j < 4; j++) {
                int n = n0 + tx * 4 + j;
                g_h0[m * N + n] = acc[i][j] + b_fc[n];
            }
        }
    } else {
        int i = (blockIdx.x - 256) * 256 + threadIdx.x;   // 0 .. 393215
        bsplit(Wih_f[i], g_wihh[0][i], g_wihl[0][i]);
        bsplit(Wih_b[i], g_wihh[1][i], g_wihl[1][i]);
        if (i < 3 * NH * NH) {
            bsplit(Whh_f[i], g_whh[0][i], g_whl[0][i]);
            bsplit(Whh_b[i], g_whh[1][i], g_whl[1][i]);
        }
        if (i < NH * 2 * NH) bsplit(W1[i], g_w1h[i], g_w1l[i]);
        if (i < 2 * 16 * NT) g_sync[i] = 0;
    }
}

// ---------------- batchnorm stats -------------------------------------------------
__global__ void __launch_bounds__(256) bn_stats()
{
    int c = blockIdx.x;
    float s = 0.f, s2 = 0.f;
    for (int r = threadIdx.x; r < NB; r += 256) {
        float v = g_h0[r * ND + c];
        s += v; s2 += v * v;
    }
    __shared__ float sh[256], sh2[256];
    sh[threadIdx.x] = s; sh2[threadIdx.x] = s2;
    __syncthreads();
    for (int o = 128; o > 0; o >>= 1) {
        if (threadIdx.x < o) {
            sh[threadIdx.x]  += sh[threadIdx.x + o];
            sh2[threadIdx.x] += sh2[threadIdx.x + o];
        }
        __syncthreads();
    }
    if (threadIdx.x == 0) {
        float mu = sh[0] / (float)NB;
        g_stats[c] = mu;
        g_stats[ND + c] = sh2[0] / (float)NB - mu * mu;
    }
}

// ---------------- BN + LeakyReLU + bf16 hi/lo split -------------------------------
__global__ void __launch_bounds__(256) bn_apply_split(
    const float* __restrict__ bn_g, const float* __restrict__ bn_b)
{
    int i = blockIdx.x * 256 + threadIdx.x;
    int c = i & (ND - 1);
    float mu = g_stats[c], var = g_stats[ND + c];
    float v = (g_h0[i] - mu) * rsqrtf(var + 1e-5f) * bn_g[c] + bn_b[c];
    v = (v >= 0.f) ? v : 0.2f * v;
    bsplit(v, g_xh[i], g_xl[i]);
}

// ---------------- gate GEMM on tensor cores (clone of attn_mma template) ---------
// g_gates[dir][m][n] = x[m] . Wih[n] + bih[n]. M=2048, N=768, K'=3x512.
// grid (3 ct, 32 mtile, 2 dir). Block tile: 64 m x 256 n.
__global__ void __launch_bounds__(256) gemm_gates_mma(
    const float* __restrict__ bf, const float* __restrict__ bb)
{
    __shared__ __nv_bfloat16 As[64 * 72];
    __shared__ __nv_bfloat16 Bs[256 * 72];

    const int tid = threadIdx.x;
    const int ct = blockIdx.x;              // 256-col tile of N=768
    const int m0 = blockIdx.y * 64;
    const int dir = blockIdx.z;
    const float* bias = dir ? bb : bf;
    float* C = g_gates[dir];
    const __nv_bfloat16* __restrict__ wh = g_wihh[dir];
    const __nv_bfloat16* __restrict__ wl = g_wihl[dir];

    const int warp = tid >> 5, lane = tid & 31;
    const int wm = warp >> 2, wj = warp & 3;
    const int gID = lane >> 2, tig = lane & 3;

    float acc[2][8][4];
    #pragma unroll
    for (int a = 0; a < 2; a++)
        #pragma unroll
        for (int b = 0; b < 8; b++)
            #pragma unroll
            for (int q = 0; q < 4; q++) acc[a][b][q] = 0.f;

    for (int it = 0; it < 24; it++) {
        const int ks = (it / 3) * 64;
        const int ph = it % 3;
        const bool loadA = (ph != 1);
        const bool loadB = (ph != 2);
        const __nv_bfloat16* __restrict__ asrc = (ph == 2) ? g_xl : g_xh;
        const __nv_bfloat16* __restrict__ bsrc = (ph == 0) ? wl : wh;
        if (it > 0) __syncthreads();
        if (loadA) {
            #pragma unroll
            for (int i = 0; i < 2; i++) {
                int u = tid + 256 * i;
                int r = u >> 3, c = (u & 7) << 3;
                *(uint4*)&As[r * 72 + c] =
                    *(const uint4*)&asrc[(size_t)(m0 + r) * 512 + ks + c];
            }
        }
        if (loadB) {
            #pragma unroll
            for (int i = 0; i < 8; i++) {
                int u = tid + 256 * i;
                int r = u >> 3, c = (u & 7) << 3;
                *(uint4*)&Bs[r * 72 + c] =
                    *(const uint4*)&bsrc[(size_t)(ct * 256 + r) * 512 + ks + c];
            }
        }
        __syncthreads();
        #pragma unroll
        for (int kk = 0; kk < 4; kk++) {
            const int kb = kk * 16 + tig * 2;
            uint32_t afr[2][4], bfr[8][2];
            #pragma unroll
            for (int mt = 0; mt < 2; mt++) {
                const __nv_bfloat16* p = As + (wm * 32 + mt * 16 + gID) * 72 + kb;
                afr[mt][0] = *(const uint32_t*)p;
                afr[mt][1] = *(const uint32_t*)(p + 8 * 72);
                afr[mt][2] = *(const uint32_t*)(p + 8);
                afr[mt][3] = *(const uint32_t*)(p + 8 * 72 + 8);
            }
            #pragma unroll
            for (int nt = 0; nt < 8; nt++) {
                const __nv_bfloat16* p = Bs + (wj * 64 + nt * 8 + gID) * 72 + kb;
                bfr[nt][0] = *(const uint32_t*)p;
                bfr[nt][1] = *(const uint32_t*)(p + 8);
            }
            #pragma unroll
            for (int mt = 0; mt < 2; mt++)
                #pragma unroll
                for (int nt = 0; nt < 8; nt++)
                    mma16816(acc[mt][nt][0], acc[mt][nt][1],
                             acc[mt][nt][2], acc[mt][nt][3],
                             afr[mt][0], afr[mt][1], afr[mt][2], afr[mt][3],
                             bfr[nt][0], bfr[nt][1]);
        }
    }

    // epilogue: + bias, write fp32 gates
    #pragma unroll
    for (int mt = 0; mt < 2; mt++)
        #pragma unroll
        for (int part = 0; part < 2; part++) {
            const int m = m0 + wm * 32 + mt * 16 + gID + part * 8;
            #pragma unroll
            for (int nt = 0; nt < 8; nt++)
                #pragma unroll
                for (int cc = 0; cc < 2; cc++) {
                    const int n = ct * 256 + wj * 64 + nt * 8 + tig * 2 + cc;
                    C[(size_t)m * 768 + n] = acc[mt][nt][part * 2 + cc] + bias[n];
                }
        }
}

// ---------------- LDSM-based MMA inner blocks ------------------------------------
__device__ __forceinline__ void ldsm_afrags(
    uint32_t As_u32, uint32_t afr[4][4], int wm, int lane, int kk)
{
    const int g = lane >> 3, lr = lane & 7;
    const int scol = kk * 2 + (g >> 1);
    #pragma unroll
    for (int mt = 0; mt < 4; mt++) {
        const int row = wm * 64 + mt * 16 + ((g & 1) << 3) + lr;
        const uint32_t addr = As_u32 + row * 128 + ((scol ^ (row & 7)) << 4);
        LDSM4(afr[mt][0], afr[mt][1], afr[mt][2], afr[mt][3], addr);
    }
}

__device__ __forceinline__ void ldsm_bfrags(
    uint32_t Bs_u32, uint32_t bfr[6][2], int wj, int lane, int kk)
{
    const int g = lane >> 3, lr = lane & 7;
    const int scol = kk * 2 + (g & 1);
    #pragma unroll
    for (int q = 0; q < 3; q++) {
        const int nt = 2 * q + (g >> 1);
        const int row = (nt >> 1) * 64 + wj * 16 + (nt & 1) * 8 + lr;
        const uint32_t addr = Bs_u32 + row * 128 + ((scol ^ (row & 7)) << 4);
        LDSM4(bfr[2 * q][0], bfr[2 * q][1], bfr[2 * q + 1][0], bfr[2 * q + 1][1], addr);
    }
}

__device__ __forceinline__ void mma_all(
    const uint32_t afr[4][4], const uint32_t bfr[6][2], float acc[4][6][4])
{
    #pragma unroll
    for (int mt = 0; mt < 4; mt++)
        #pragma unroll
        for (int nt = 0; nt < 6; nt++)
            mma16816(acc[mt][nt][0], acc[mt][nt][1], acc[mt][nt][2], acc[mt][nt][3],
                     afr[mt][0], afr[mt][1], afr[mt][2], afr[mt][3],
                     bfr[nt][0], bfr[nt][1]);
}

__device__ __forceinline__ void mma_block2(
    uint32_t As_u32, uint32_t Bs1_u32, uint32_t Bs2_u32,
    float acc[4][6][4], int wm, int wj, int lane)
{
    #pragma unroll
    for (int kk = 0; kk < 4; kk++) {
        uint32_t afr[4][4], bfr[6][2];
        ldsm_afrags(As_u32, afr, wm, lane, kk);
        ldsm_bfrags(Bs1_u32, bfr, wj, lane, kk);
        mma_all(afr, bfr, acc);
        ldsm_bfrags(Bs2_u32, bfr, wj, lane, kk);
        mma_all(afr, bfr, acc);
    }
}

__device__ __forceinline__ void mma_block1(
    uint32_t As_u32, uint32_t Bs_u32,
    float acc[4][6][4], int wm, int wj, int lane)
{
    #pragma unroll
    for (int kk = 0; kk < 4; kk++) {
        uint32_t afr[4][4], bfr[6][2];
        ldsm_afrags(As_u32, afr, wm, lane, kk);
        ldsm_bfrags(Bs_u32, bfr, wj, lane, kk);
        mma_all(afr, bfr, acc);
    }
}

// ---------------- persistent GRU: state lives in g_gruh/g_grul time-slots --------
#define SLAB (192 * 64)
#define ATILE (128 * 64)
__global__ void __launch_bounds__(256) gru_persist(
    const float* __restrict__ bhh_f, const float* __restrict__ bhh_b)
{
    extern __shared__ __nv_bfloat16 smem[];
    __nv_bfloat16* Bsh = smem;
    __nv_bfloat16* Bsl = smem + 4 * SLAB;
    __nv_bfloat16* A0  = smem + 8 * SLAB;
    __nv_bfloat16* A1  = A0 + ATILE;
    const uint32_t Bsh_u32 = (uint32_t)__cvta_generic_to_shared(Bsh);
    const uint32_t Bsl_u32 = (uint32_t)__cvta_generic_to_shared(Bsl);
    const uint32_t A0_u32  = (uint32_t)__cvta_generic_to_shared(A0);
    const uint32_t A1_u32  = (uint32_t)__cvta_generic_to_shared(A1);
    const uint32_t SLAB_B  = SLAB * 2;

    const int bid = blockIdx.x;
    const int dir = bid >> 6;
    const int sub = bid & 63;
    const int j0 = (sub & 3) * 64;
    const int mtile = sub >> 2;
    const int m0 = mtile * 128;
    int* const flag = &g_sync[(dir * 16 + mtile) * NT];

    const float* bhh = dir ? bhh_b : bhh_f;
    const float* gin = g_gates[dir];
    const __nv_bfloat16* __restrict__ wh = g_whh[dir];
    const __nv_bfloat16* __restrict__ wl = g_whl[dir];

    const int tid = threadIdx.x;
    const int warp = tid >> 5, lane = tid & 31;
    const int wm = warp >> 2, wj = warp & 3;
    const int gID = lane >> 2, tig = lane & 3;

    int lr[4], lc[4];
    #pragma unroll
    for (int i = 0; i < 4; i++) {
        int u = tid + 256 * i;
        lr[i] = u >> 3; lc[i] = (u & 7) * 8;
    }

    #pragma unroll
    for (int i = 0; i < 24; i++) {
        int u = tid + 256 * i;
        int r = u >> 5;
        int c = (u & 31) * 8;
        int slab = c >> 6, cs = c & 63;
        int g = r >> 6, j = j0 + (r & 63);
        *(uint4*)&Bsh[slab * SLAB + swzidx(r, cs)] =
            *(const uint4*)&wh[(g * NH + j) * NH + c];
        *(uint4*)&Bsl[slab * SLAB + swzidx(r, cs)] =
            *(const uint4*)&wl[(g * NH + j) * NH + c];
    }
    __syncthreads();

    for (int t = 0; t < NT; t++) {
        const int tt  = dir ? (NT - 1 - t) : t;
        const int ttp = dir ? (NT - t) : (t - 1);

        float acc[4][6][4];
        #pragma unroll
        for (int a = 0; a < 4; a++)
            #pragma unroll
            for (int b = 0; b < 6; b++)
                #pragma unroll
                for (int q = 0; q < 4; q++) acc[a][b][q] = 0.f;

        if (t > 0) {
            if (tid == 0) {
                while (*(volatile int*)&flag[t - 1] < 4) { }
                __threadfence();
            }
            __syncthreads();

            #pragma unroll
            for (int i = 0; i < 4; i++)
                cpasync16(&A0[swzidx(lr[i], lc[i])],
                          &g_gruh[((size_t)(m0 + lr[i]) * NT + ttp) * 512 + dir * NH + lc[i]]);
            CP_COMMIT();
            for (int ksl = 0; ksl < 4; ksl++) {
                const int ks = ksl * 64;
                CP_WAIT0(); __syncthreads();
                #pragma unroll
                for (int i = 0; i < 4; i++)
                    cpasync16(&A1[swzidx(lr[i], lc[i])],
                              &g_grul[((size_t)(m0 + lr[i]) * NT + ttp) * 512 + dir * NH + ks + lc[i]]);
                CP_COMMIT();
                mma_block2(A0_u32, Bsl_u32 + ksl * SLAB_B, Bsh_u32 + ksl * SLAB_B,
                           acc, wm, wj, lane);
                CP_WAIT0(); __syncthreads();
                if (ksl < 3) {
                    #pragma unroll
                    for (int i = 0; i < 4; i++)
                        cpasync16(&A0[swzidx(lr[i], lc[i])],
                                  &g_gruh[((size_t)(m0 + lr[i]) * NT + ttp) * 512 + dir * NH + ks + 64 + lc[i]]);
                    CP_COMMIT();
                }
                mma_block1(A1_u32, Bsh_u32 + ksl * SLAB_B, acc, wm, wj, lane);
            }
        }

        #pragma unroll
        for (int mt = 0; mt < 4; mt++)
            #pragma unroll
            for (int part = 0; part < 2; part++) {
                const int m = m0 + wm * 64 + mt * 16 + gID + part * 8;
                #pragma unroll
                for (int jn = 0; jn < 2; jn++) {
                    const int jg = j0 + wj * 16 + jn * 8 + tig * 2;
                    float hn2[2];
                    #pragma unroll
                    for (int cc = 0; cc < 2; cc++) {
                        const int j = jg + cc;
                        float ghr = acc[mt][jn][part * 2 + cc]     + bhh[j];
                        float ghz = acc[mt][2 + jn][part * 2 + cc] + bhh[NH + j];
                        float ghn = acc[mt][4 + jn][part * 2 + cc] + bhh[2 * NH + j];
                        const float* gp = gin + m * 3 * NH + j;
                        float r  = fsig_hw(gp[0] + ghr);
                        float zz = fsig_hw(gp[NH] + ghz);
                        float nn = ftanh_hw(gp[2 * NH] + r * ghn);
                        float hold = 0.f;
                        if (t > 0) {
                            size_t hp = ((size_t)m * NT + ttp) * 512 + dir * NH + j;
                            hold = b2f(g_gruh[hp]) + b2f(g_grul[hp]);
                        }
                        hn2[cc] = (1.f - zz) * nn + zz * hold;
                    }
                    __nv_bfloat16 h0, l0, h1, l1;
                    bsplit(hn2[0], h0, l0);
                    bsplit(hn2[1], h1, l1);
                    __nv_bfloat162 vh, vl;
                    vh.x = h0; vh.y = h1; vl.x = l0; vl.y = l1;
                    size_t go = ((size_t)m * NT + tt) * 512 + dir * NH + jg;
                    *(__nv_bfloat162*)(g_gruh + go) = vh;
                    *(__nv_bfloat162*)(g_grul + go) = vl;
                }
            }

        if (t < NT - 1) {
            __syncthreads();
            if (tid == 0) {
                __threadfence();
                atomicAdd(&flag[t], 1);
            }
        }
    }
}

// ---------------- attention scores via bf16-split MMA ----------------------------
__global__ void __launch_bounds__(256) attn_mma(
    const float* __restrict__ b1, const float* __restrict__ W2)
{
    __shared__ __nv_bfloat16 As[64 * 72];
    __shared__ __nv_bfloat16 Bs[256 * 72];
    __shared__ float red[64];

    const int tid = threadIdx.x;
    const int m0 = blockIdx.x * 64;
    const int warp = tid >> 5, lane = tid & 31;
    const int wm = warp >> 2, wj = warp & 3;
    const int gID = lane >> 2, tig = lane & 3;
    if (tid < 64) red[tid] = 0.f;

    float acc[2][8][4];
    #pragma unroll
    for (int a = 0; a < 2; a++)
        #pragma unroll
        for (int b = 0; b < 8; b++)
            #pragma unroll
            for (int q = 0; q < 4; q++) acc[a][b][q] = 0.f;

    for (int it = 0; it < 24; it++) {
        const int ks = (it / 3) * 64;
        const int ph = it % 3;
        const bool loadA = (ph != 1);
        const bool loadB = (ph != 2);
        const __nv_bfloat16* __restrict__ asrc = (ph == 2) ? g_grul : g_gruh;
        const __nv_bfloat16* __restrict__ bsrc = (ph == 0) ? g_w1l : g_w1h;
        if (it > 0) __syncthreads();
        if (loadA) {
            #pragma unroll
            for (int i = 0; i < 2; i++) {
                int u = tid + 256 * i;
                int r = u >> 3, c = (u & 7) << 3;
                *(uint4*)&As[r * 72 + c] =
                    *(const uint4*)&asrc[(size_t)(m0 + r) * 512 + ks + c];
            }
        }
        if (loadB) {
            #pragma unroll
            for (int i = 0; i < 8; i++) {
                int u = tid + 256 * i;
                int r = u >> 3, c = (u & 7) << 3;
                *(uint4*)&Bs[r * 72 + c] =
                    *(const uint4*)&bsrc[r * 512 + ks + c];
            }
        }
        __syncthreads();
        #pragma unroll
        for (int kk = 0; kk < 4; kk++) {
            const int kb = kk * 16 + tig * 2;
            uint32_t afr[2][4], bfr[8][2];
            #pragma unroll
            for (int mt = 0; mt < 2; mt++) {
                const __nv_bfloat16* p = As + (wm * 32 + mt * 16 + gID) * 72 + kb;
                afr[mt][0] = *(const uint32_t*)p;
                afr[mt][1] = *(const uint32_t*)(p + 8 * 72);
                afr[mt][2] = *(const uint32_t*)(p + 8);
                afr[mt][3] = *(const uint32_t*)(p + 8 * 72 + 8);
            }
            #pragma unroll
            for (int nt = 0; nt < 8; nt++) {
                const __nv_bfloat16* p = Bs + (wj * 64 + nt * 8 + gID) * 72 + kb;
                bfr[nt][0] = *(const uint32_t*)p;
                bfr[nt][1] = *(const uint32_t*)(p + 8);
            }
            #pragma unroll
            for (int mt = 0; mt < 2; mt++)
                #pragma unroll
                for (int nt = 0; nt < 8; nt++)
                    mma16816(acc[mt][nt][0], acc[mt][nt][1],
                             acc[mt][nt][2], acc[mt][nt][3],
                             afr[mt][0], afr[mt][1], afr[mt][2], afr[mt][3],
                             bfr[nt][0], bfr[nt][1]);
        }
    }

    #pragma unroll
    for (int mt = 0; mt < 2; mt++)
        #pragma unroll
        for (int part = 0; part < 2; part++) {
            float s = 0.f;
            #pragma unroll
            for (int nt = 0; nt < 8; nt++)
                #pragma unroll
                for (int cc = 0; cc < 2; cc++) {
                    int n = wj * 64 + nt * 8 + tig * 2 + cc;
                    s += ftanh_hw(acc[mt][nt][part * 2 + cc] + b1[n]) * W2[n];
                }
            s += __shfl_xor_sync(0xffffffffu, s, 1);
            s += __shfl_xor_sync(0xffffffffu, s, 2);
            if (tig == 0)
                atomicAdd(&red[wm * 32 + mt * 16 + gID + part * 8], s);
        }
    __syncthreads();
    if (tid < 64) g_s[m0 + tid] = red[tid];
}

// ---------------- fused softmax + context + joint head + FK ----------------------
__global__ void __launch_bounds__(256) ctx_fk(
    const float* __restrict__ jW, const float* __restrict__ jb,
    float* __restrict__ out)
{
    const int b = blockIdx.x;
    const int tid = threadIdx.x;
    const int warp = tid >> 5, lane = tid & 31;

    __shared__ float jWs[6][512];
    __shared__ float w[NT];
    __shared__ float csh[512];
    __shared__ float p1sh[NT][8];
    __shared__ float cJ[8];

    for (int i = tid; i < 6 * 512; i += 256) jWs[i >> 9][i & 511] = jW[i];
    for (int i = tid; i < 512; i += 256) csh[i] = 0.f;
    if (tid == 0) {
        float mx = -1e30f;
        float tmpv[NT];
        for (int t = 0; t < NT; t++) {
            tmpv[t] = g_s[b * NT + t];
            if (tmpv[t] > mx) mx = tmpv[t];
        }
        float s = 0.f;
        for (int t = 0; t < NT; t++) { tmpv[t] = __expf(tmpv[t] - mx); s += tmpv[t]; }
        float inv = __fdividef(1.f, s);
        for (int t = 0; t < NT; t++) w[t] = tmpv[t] * inv;
    }
    __syncthreads();

    float creg[16];
    #pragma unroll
    for (int k = 0; k < 16; k++) creg[k] = 0.f;

    for (int t = warp; t < NT; t += 8) {
        const __nv_bfloat16* rh = g_gruh + ((size_t)b * NT + t) * 512;
        const __nv_bfloat16* rl = g_grul + ((size_t)b * NT + t) * 512;
        const float wt = w[t];
        float pj[6];
        #pragma unroll
        for (int j = 0; j < 6; j++) pj[j] = 0.f;
        #pragma unroll
        for (int k = 0; k < 16; k++) {
            const int d = lane + 32 * k;
            float x = b2f(rh[d]) + b2f(rl[d]);
            creg[k] += wt * x;
            #pragma unroll
            for (int j = 0; j < 6; j++) pj[j] += x * jWs[j][d];
        }
        #pragma unroll
        for (int o = 16; o > 0; o >>= 1)
            #pragma unroll
            for (int j = 0; j < 6; j++)
                pj[j] += __shfl_xor_sync(0xffffffffu, pj[j], o);
        if (lane == 0) {
            #pragma unroll
            for (int j = 0; j < 6; j++) p1sh[t][j] = pj[j];
        }
    }
    #pragma unroll
    for (int k = 0; k < 16; k++)
        atomicAdd(&csh[lane + 32 * k], creg[k]);
    __syncthreads();

    if (warp == 0) {
        float pj[6];
        #pragma unroll
        for (int j = 0; j < 6; j++) pj[j] = 0.f;
        #pragma unroll
        for (int k = 0; k < 16; k++) {
            const int d = lane + 32 * k;
            float cv = csh[d];
            #pragma unroll
            for (int j = 0; j < 6; j++) pj[j] += cv * jWs[j][d];
        }
        #pragma unroll
        for (int o = 16; o > 0; o >>= 1)
            #pragma unroll
            for (int j = 0; j < 6; j++)
                pj[j] += __shfl_xor_sync(0xffffffffu, pj[j], o);
        if (lane == 0) {
            #pragma unroll
            for (int j = 0; j < 6; j++) cJ[j] = pj[j];
        }
    }
    __syncthreads();

    if (tid < NT) {
        const int t = tid;
        const float LO[6] = {-3.1416f, -1.5708f, -3.1416f, -2.6f, -1.5708f, -1.2f};
        const float UP[6] = { 3.1416f,  1.5708f,  3.1416f,  0.1f,  1.5708f,  1.2f};
        float th[6];
        #pragma unroll
        for (int j = 0; j < 6; j++)
            th[j] = (p1sh[t][j] + cJ[j] + jb[j]) * (UP[j] - LO[j]) + LO[j];

        float c0[3] = {1.f, 0.f, 0.f}, c1[3] = {0.f, 1.f, 0.f}, c2[3] = {0.f, 0.f, 1.f};
        float px = 0.f, py = 0.f, pz = 0.10f;
        const float sh2x = 0.f, sh2y = 0.f, sh2z = 0.10f;

        float c, s, tmp;
        c = cosf(th[0]); s = sinf(th[0]);
        #pragma unroll
        for (int i = 0; i < 3; i++) { tmp = c*c0[i] + s*c1[i]; c1[i] = c*c1[i] - s*c0[i]; c0[i] = tmp; }
        c = cosf(th[1]); s = sinf(th[1]);
        #pragma unroll
        for (int i = 0; i < 3; i++) { tmp = c*c1[i] + s*c2[i]; c2[i] = c*c2[i] - s*c1[i]; c1[i] = tmp; }
        c = cosf(th[2]); s = sinf(th[2]);
        #pragma unroll
        for (int i = 0; i < 3; i++) { tmp = c*c0[i] - s*c2[i]; c2[i] = c*c2[i] + s*c0[i]; c0[i] = tmp; }
        px -= 0.25f * c1[0]; py -= 0.25f * c1[1]; pz -= 0.25f * c1[2];
        float fax = px, fay = py, faz = pz;
        c = cosf(th[3]); s = sinf(th[3]);
        #pragma unroll
        for (int i = 0; i < 3; i++) { tmp = c*c1[i] + s*c2[i]; c2[i] = c*c2[i] - s*c1[i]; c1[i] = tmp; }
        c = cosf(th[4]); s = sinf(th[4]);
        #pragma unroll
        for (int i = 0; i < 3; i++) { tmp = c*c0[i] - s*c2[i]; c2[i] = c*c2[i] + s*c0[i]; c0[i] = tmp; }
        px -= 0.25f * c1[0]; py -= 0.25f * c1[1]; pz -= 0.25f * c1[2];
        float wx = px, wy = py, wz = pz;
        c = cosf(th[5]); s = sinf(th[5]);
        #pragma unroll
        for (int i = 0; i < 3; i++) { tmp = c*c1[i] + s*c2[i]; c2[i] = c*c2[i] - s*c1[i]; c1[i] = tmp; }

        float f1x = wx - 0.08f*c1[0] + 0.02f*c2[0];
        float f1y = wy - 0.08f*c1[1] + 0.02f*c2[1];
        float f1z = wz - 0.08f*c1[2] + 0.02f*c2[2];
        float f4x = wx - 0.08f*c1[0] - 0.02f*c2[0];
        float f4y = wy - 0.08f*c1[1] - 0.02f*c2[1];
        float f4z = wz - 0.08f*c1[2] - 0.02f*c2[2];

        float d1x = sh2x - fax, d1y = sh2y - fay, d1z = sh2z - faz;
        float d2x = wx - fax,   d2y = wy - fay,   d2z = wz - faz;
        float bodyL = 0.5f * (sqrtf(d1x*d1x + d1y*d1y + d1z*d1z)
                            + sqrtf(d2x*d2x + d2y*d2y + d2z*d2z));
        float inv = 1.f / bodyL;

        float* o = out + ((size_t)b * NT + t) * 9;
        o[0] = (wx  - sh2x) * inv; o[1] = (wy  - sh2y) * inv; o[2] = (wz  - sh2z) * inv;
        o[3] = (f1x - sh2x) * inv; o[4] = (f1y - sh2y) * inv; o[5] = (f1z - sh2z) * inv;
        o[6] = (f4x - sh2x) * inv; o[7] = (f4y - sh2y) * inv; o[8] = (f4z - sh2z) * inv;
    }
}

// ---------------- host launcher ---------------------------------------------------
extern "C" void kernel_launch(void* const* d_in, const int* in_sizes, int n_in,
                              void* d_out, int out_size)
{
    const float* z       = (const float*)d_in[0];
    const float* W_fc    = (const float*)d_in[1];
    const float* b_fc    = (const float*)d_in[2];
    const float* bn_g    = (const float*)d_in[3];
    const float* bn_b    = (const float*)d_in[4];
    const float* Wih_f   = (const float*)d_in[5];
    const float* Whh_f   = (const float*)d_in[6];
    const float* bih_f   = (const float*)d_in[7];
    const float* bhh_f   = (const float*)d_in[8];
    const float* Wih_b   = (const float*)d_in[9];
    const float* Whh_b   = (const float*)d_in[10];
    const float* bih_b   = (const float*)d_in[11];
    const float* bhh_b   = (const float*)d_in[12];
    const float* attn_W1 = (const float*)d_in[13];
    const float* attn_b1 = (const float*)d_in[14];
    const float* attn_W2 = (const float*)d_in[15];
    const float* joint_W = (const float*)d_in[16];
    const float* joint_b = (const float*)d_in[17];
    float* out = (float*)d_out;

    static int smem_set = 0;
    const int gru_smem = (8 * SLAB + 2 * ATILE) * 2;
    if (!smem_set) {
        cudaFuncSetAttribute(gru_persist,
            cudaFuncAttributeMaxDynamicSharedMemorySize, gru_smem);
        smem_set = 1;
    }

    // 1) fc GEMM + weight splits + flag reset
    fc_prep<<<1792, 256>>>(z, W_fc, b_fc, Whh_f, Whh_b, Wih_f, Wih_b, attn_W1);
    // 2) batch stats
    bn_stats<<<ND, 256>>>();
    // 3) BN + lrelu + bf16 split of x
    bn_apply_split<<<NB * ND / 256, 256>>>(bn_g, bn_b);
    // 4) gate GEMM on tensor cores (both dirs)
    gemm_gates_mma<<<dim3(3, NB / 64, 2), 256>>>(bih_f, bih_b);
    // 5) GRU recurrence (persistent)
    gru_persist<<<128, 256, gru_smem>>>(bhh_f, bhh_b);
    // 6) attention scores
    attn_mma<<<NB * NT / 64, 256>>>(attn_b1, attn_W2);
    // 7) fused softmax + context + joints + FK
    ctx_fk<<<NB, 256>>>(joint_W, joint_b, out);
}

// round 11
// speedup vs baseline: 1.9520x; 1.0318x over previous
#include <cuda_runtime.h>
#include <cuda_bf16.h>
#include <math.h>
#include <stdint.h>

#define NB   2048
#define NT   60
#define NDL  100
#define ND   512
#define NH   256

// ---------------- scratch (device globals) ----------------
__device__ float g_h0[NB * ND];
__device__ float g_stats[2 * ND];
__device__ float g_gates[2][NB * 3 * NH];          // x@Wih^T + bih (fp32)
__device__ __nv_bfloat16 g_xh[NB * ND];            // BN+lrelu x split hi
__device__ __nv_bfloat16 g_xl[NB * ND];            // BN+lrelu x split lo
__device__ __nv_bfloat16 g_whh[2][3 * NH * NH];    // Whh split hi
__device__ __nv_bfloat16 g_whl[2][3 * NH * NH];    // Whh split lo
__device__ __nv_bfloat16 g_wihh[2][3 * NH * ND];   // Wih split hi
__device__ __nv_bfloat16 g_wihl[2][3 * NH * ND];   // Wih split lo
__device__ __nv_bfloat16 g_w1h[NH * 2 * NH];       // attn_W1 split hi
__device__ __nv_bfloat16 g_w1l[NH * 2 * NH];       // attn_W1 split lo
__device__ __nv_bfloat16 g_gruh[NB * NT * 2 * NH]; // gru out bf16 hi (= state)
__device__ __nv_bfloat16 g_grul[NB * NT * 2 * NH]; // gru out bf16 lo
__device__ float g_s[NB * NT];
__device__ int   g_sync[2 * 16 * NT];              // group flags [dir][mtile][t]

__device__ __forceinline__ void bsplit(float v, __nv_bfloat16& h, __nv_bfloat16& l) {
    h = __float2bfloat16(v);
    l = __float2bfloat16(v - __bfloat162float(h));
}

__device__ __forceinline__ void mma16816(float& d0, float& d1, float& d2, float& d3,
    uint32_t a0, uint32_t a1, uint32_t a2, uint32_t a3, uint32_t b0, uint32_t b1)
{
    asm volatile("mma.sync.aligned.m16n8k16.row.col.f32.bf16.bf16.f32 "
                 "{%0,%1,%2,%3},{%4,%5,%6,%7},{%8,%9},{%0,%1,%2,%3};"
                 : "+f"(d0), "+f"(d1), "+f"(d2), "+f"(d3)
                 : "r"(a0), "r"(a1), "r"(a2), "r"(a3), "r"(b0), "r"(b1));
}

#define LDSM4(r0, r1, r2, r3, addr) \
    asm volatile("ldmatrix.sync.aligned.m8n8.x4.shared.b16 {%0,%1,%2,%3}, [%4];" \
                 : "=r"(r0), "=r"(r1), "=r"(r2), "=r"(r3) : "r"(addr))

__device__ __forceinline__ void cpasync16(void* sdst, const void* gsrc) {
    uint32_t s = (uint32_t)__cvta_generic_to_shared(sdst);
    asm volatile("cp.async.cg.shared.global [%0], [%1], 16;" :: "r"(s), "l"(gsrc));
}
#define CP_COMMIT() asm volatile("cp.async.commit_group;")
#define CP_WAIT0()  asm volatile("cp.async.wait_group 0;")

__device__ __forceinline__ float ftanh_hw(float x) {
    float r;
    asm("tanh.approx.f32 %0, %1;" : "=f"(r) : "f"(x));
    return r;
}
__device__ __forceinline__ float fsig_hw(float x) {
    return fmaf(ftanh_hw(0.5f * x), 0.5f, 0.5f);
}
__device__ __forceinline__ float b2f(__nv_bfloat16 v) { return __bfloat162float(v); }

// swizzled smem index (elements): stride 64, XOR 8-col blocks by (row&7).
__device__ __forceinline__ int swzidx(int r, int c) {
    return r * 64 + ((((c >> 3) ^ (r & 7)) << 3) | (c & 7));
}

// ---------------- fused fc GEMM + weight splits + flag reset ---------------------
__global__ void __launch_bounds__(256) fc_prep(
    const float* __restrict__ z, const float* __restrict__ W_fc,
    const float* __restrict__ b_fc,
    const float* __restrict__ Whh_f, const float* __restrict__ Whh_b,
    const float* __restrict__ Wih_f, const float* __restrict__ Wih_b,
    const float* __restrict__ W1)
{
    __shared__ float As[16][65];
    __shared__ float Bs[16][65];
    if (blockIdx.x < 256) {
        const int N = ND, K = NDL;
        int tid = threadIdx.x;
        int tx = tid & 15, ty = tid >> 4;
        int m0 = (blockIdx.x >> 3) * 64, n0 = (blockIdx.x & 7) * 64;
        float acc[4][4] = {};
        for (int k0 = 0; k0 < K; k0 += 16) {
            #pragma unroll
            for (int i = 0; i < 4; i++) {
                int lin = tid + i * 256;
                int m = lin >> 4, k = lin & 15;
                As[k][m] = (k0 + k < K) ? z[(m0 + m) * K + k0 + k] : 0.f;
            }
            #pragma unroll
            for (int i = 0; i < 4; i++) {
                int lin = tid + i * 256;
                int n = lin >> 4, k = lin & 15;
                Bs[k][n] = (k0 + k < K) ? W_fc[(n0 + n) * K + k0 + k] : 0.f;
            }
            __syncthreads();
            #pragma unroll
            for (int kk = 0; kk < 16; kk++) {
                float a[4], b[4];
                #pragma unroll
                for (int i = 0; i < 4; i++) a[i] = As[kk][ty * 4 + i];
                #pragma unroll
                for (int j = 0; j < 4; j++) b[j] = Bs[kk][tx * 4 + j];
                #pragma unroll
                for (int i = 0; i < 4; i++)
                    #pragma unroll
                    for (int j = 0; j < 4; j++) acc[i][j] += a[i] * b[j];
            }
            __syncthreads();
        }
        #pragma unroll
        for (int i = 0; i < 4; i++) {
            int m = m0 + ty * 4 + i;
            #pragma unroll
            for (int j = 0; j < 4; j++) {
                int n = n0 + tx * 4 + j;
                g_h0[m * N + n] = acc[i][j] + b_fc[n];
            }
        }
    } else {
        int i = (blockIdx.x - 256) * 256 + threadIdx.x;
        bsplit(Wih_f[i], g_wihh[0][i], g_wihl[0][i]);
        bsplit(Wih_b[i], g_wihh[1][i], g_wihl[1][i]);
        if (i < 3 * NH * NH) {
            bsplit(Whh_f[i], g_whh[0][i], g_whl[0][i]);
            bsplit(Whh_b[i], g_whh[1][i], g_whl[1][i]);
        }
        if (i < NH * 2 * NH) bsplit(W1[i], g_w1h[i], g_w1l[i]);
        if (i < 2 * 16 * NT) g_sync[i] = 0;
    }
}

// ---------------- batchnorm stats -------------------------------------------------
__global__ void __launch_bounds__(256) bn_stats()
{
    int c = blockIdx.x;
    float s = 0.f, s2 = 0.f;
    for (int r = threadIdx.x; r < NB; r += 256) {
        float v = g_h0[r * ND + c];
        s += v; s2 += v * v;
    }
    __shared__ float sh[256], sh2[256];
    sh[threadIdx.x] = s; sh2[threadIdx.x] = s2;
    __syncthreads();
    for (int o = 128; o > 0; o >>= 1) {
        if (threadIdx.x < o) {
            sh[threadIdx.x]  += sh[threadIdx.x + o];
            sh2[threadIdx.x] += sh2[threadIdx.x + o];
        }
        __syncthreads();
    }
    if (threadIdx.x == 0) {
        float mu = sh[0] / (float)NB;
        g_stats[c] = mu;
        g_stats[ND + c] = sh2[0] / (float)NB - mu * mu;
    }
}

// ---------------- BN + LeakyReLU + bf16 hi/lo split -------------------------------
__global__ void __launch_bounds__(256) bn_apply_split(
    const float* __restrict__ bn_g, const float* __restrict__ bn_b)
{
    int i = blockIdx.x * 256 + threadIdx.x;
    int c = i & (ND - 1);
    float mu = g_stats[c], var = g_stats[ND + c];
    float v = (g_h0[i] - mu) * rsqrtf(var + 1e-5f) * bn_g[c] + bn_b[c];
    v = (v >= 0.f) ? v : 0.2f * v;
    bsplit(v, g_xh[i], g_xl[i]);
}

// ---------------- shared 64x256 x K=512 split-MMA core ---------------------------
// smem layout (elements, swizzled stride 64): As0[4096] As1[4096] Bs0[16384] Bs1[16384]
#define AT_AS0 0
#define AT_AS1 4096
#define AT_BS0 8192
#define AT_BS1 24576
#define AT_SMEM_ELEMS 40960

__device__ __forceinline__ void ldsmA2(
    uint32_t base, uint32_t afr[2][4], int wm, int lane, int kk)
{
    const int g = lane >> 3, lr = lane & 7;
    const int scol = kk * 2 + (g >> 1);
    #pragma unroll
    for (int mt = 0; mt < 2; mt++) {
        const int row = wm * 32 + mt * 16 + ((g & 1) << 3) + lr;
        const uint32_t addr = base + row * 128 + ((scol ^ (row & 7)) << 4);
        LDSM4(afr[mt][0], afr[mt][1], afr[mt][2], afr[mt][3], addr);
    }
}

__device__ __forceinline__ void ldsmB8(
    uint32_t base, uint32_t bfr[8][2], int wj, int lane, int kk)
{
    const int g = lane >> 3, lr = lane & 7;
    const int scol = kk * 2 + (g & 1);
    #pragma unroll
    for (int q = 0; q < 4; q++) {
        const int nt = 2 * q + (g >> 1);
        const int row = wj * 64 + nt * 8 + lr;
        const uint32_t addr = base + row * 128 + ((scol ^ (row & 7)) << 4);
        LDSM4(bfr[2 * q][0], bfr[2 * q][1], bfr[2 * q + 1][0], bfr[2 * q + 1][1], addr);
    }
}

__device__ __forceinline__ void mma28(
    const uint32_t afr[2][4], const uint32_t bfr[8][2], float acc[2][8][4])
{
    #pragma unroll
    for (int mt = 0; mt < 2; mt++)
        #pragma unroll
        for (int nt = 0; nt < 8; nt++)
            mma16816(acc[mt][nt][0], acc[mt][nt][1], acc[mt][nt][2], acc[mt][nt][3],
                     afr[mt][0], afr[mt][1], afr[mt][2], afr[mt][3],
                     bfr[nt][0], bfr[nt][1]);
}

// Accumulate acc += Ah@(Bh+Bl)^T + Al@Bh^T over K=512 (3-term bf16 split).
// A rows: ah/al + (row)*512; B rows: bh/bl + (row)*512 (256 rows).
__device__ __forceinline__ void split_mma_64x256(
    const __nv_bfloat16* __restrict__ ah, const __nv_bfloat16* __restrict__ al,
    const __nv_bfloat16* __restrict__ bh, const __nv_bfloat16* __restrict__ bl,
    __nv_bfloat16* smem, float acc[2][8][4], int tid)
{
    const uint32_t s_u32 = (uint32_t)__cvta_generic_to_shared(smem);
    const uint32_t As0 = s_u32 + AT_AS0 * 2;
    const uint32_t As1 = s_u32 + AT_AS1 * 2;
    const uint32_t Bs0 = s_u32 + AT_BS0 * 2;
    const uint32_t Bs1 = s_u32 + AT_BS1 * 2;
    const int warp = tid >> 5, lane = tid & 31;
    const int wm = warp >> 2, wj = warp & 3;

    for (int ksi = 0; ksi < 8; ksi++) {
        const int ks = ksi * 64;
        if (ksi > 0) __syncthreads();          // previous slab reads done
        #pragma unroll
        for (int i = 0; i < 2; i++) {          // A slabs: 64x64 each
            int u = tid + 256 * i;
            int r = u >> 3, c = (u & 7) << 3;
            cpasync16(&smem[AT_AS0 + swzidx(r, c)], &ah[(size_t)r * 512 + ks + c]);
            cpasync16(&smem[AT_AS1 + swzidx(r, c)], &al[(size_t)r * 512 + ks + c]);
        }
        #pragma unroll
        for (int i = 0; i < 8; i++) {          // B slabs: 256x64 each
            int u = tid + 256 * i;
            int r = u >> 3, c = (u & 7) << 3;
            cpasync16(&smem[AT_BS0 + swzidx(r, c)], &bh[(size_t)r * 512 + ks + c]);
            cpasync16(&smem[AT_BS1 + swzidx(r, c)], &bl[(size_t)r * 512 + ks + c]);
        }
        CP_COMMIT();
        CP_WAIT0();
        __syncthreads();
        #pragma unroll
        for (int kk = 0; kk < 4; kk++) {
            uint32_t afr[2][4], bfr[8][2];
            ldsmA2(As0, afr, wm, lane, kk);    // A hi frags, reused for 2 products
            ldsmB8(Bs1, bfr, wj, lane, kk);    // hi * lo
            mma28(afr, bfr, acc);
            ldsmB8(Bs0, bfr, wj, lane, kk);    // hi * hi
            mma28(afr, bfr, acc);
            ldsmA2(As1, afr, wm, lane, kk);    // lo * hi
            mma28(afr, bfr, acc);
        }
    }
}

// ---------------- gate GEMM on tensor cores --------------------------------------
__global__ void __launch_bounds__(256) gemm_gates_mma(
    const float* __restrict__ bf, const float* __restrict__ bb)
{
    extern __shared__ __nv_bfloat16 dynsm[];
    const int tid = threadIdx.x;
    const int ct = blockIdx.x;              // 256-col tile of N=768
    const int m0 = blockIdx.y * 64;
    const int dir = blockIdx.z;
    const float* bias = dir ? bb : bf;
    float* C = g_gates[dir];

    float acc[2][8][4];
    #pragma unroll
    for (int a = 0; a < 2; a++)
        #pragma unroll
        for (int b = 0; b < 8; b++)
            #pragma unroll
            for (int q = 0; q < 4; q++) acc[a][b][q] = 0.f;

    split_mma_64x256(g_xh + (size_t)m0 * 512, g_xl + (size_t)m0 * 512,
                     g_wihh[dir] + (size_t)ct * 256 * 512,
                     g_wihl[dir] + (size_t)ct * 256 * 512,
                     dynsm, acc, tid);

    const int warp = tid >> 5, lane = tid & 31;
    const int wm = warp >> 2, wj = warp & 3;
    const int gID = lane >> 2, tig = lane & 3;
    #pragma unroll
    for (int mt = 0; mt < 2; mt++)
        #pragma unroll
        for (int part = 0; part < 2; part++) {
            const int m = m0 + wm * 32 + mt * 16 + gID + part * 8;
            #pragma unroll
            for (int nt = 0; nt < 8; nt++)
                #pragma unroll
                for (int cc = 0; cc < 2; cc++) {
                    const int n = ct * 256 + wj * 64 + nt * 8 + tig * 2 + cc;
                    C[(size_t)m * 768 + n] = acc[mt][nt][part * 2 + cc] + bias[n];
                }
        }
}

// ---------------- attention scores ------------------------------------------------
__global__ void __launch_bounds__(256) attn_mma(
    const float* __restrict__ b1, const float* __restrict__ W2)
{
    extern __shared__ __nv_bfloat16 dynsm[];
    __shared__ float red[64];
    const int tid = threadIdx.x;
    const int m0 = blockIdx.x * 64;
    if (tid < 64) red[tid] = 0.f;

    float acc[2][8][4];
    #pragma unroll
    for (int a = 0; a < 2; a++)
        #pragma unroll
        for (int b = 0; b < 8; b++)
            #pragma unroll
            for (int q = 0; q < 4; q++) acc[a][b][q] = 0.f;

    split_mma_64x256(g_gruh + (size_t)m0 * 512, g_grul + (size_t)m0 * 512,
                     g_w1h, g_w1l, dynsm, acc, tid);

    const int warp = tid >> 5, lane = tid & 31;
    const int wm = warp >> 2, wj = warp & 3;
    const int gID = lane >> 2, tig = lane & 3;
    __syncthreads();
    #pragma unroll
    for (int mt = 0; mt < 2; mt++)
        #pragma unroll
        for (int part = 0; part < 2; part++) {
            float s = 0.f;
            #pragma unroll
            for (int nt = 0; nt < 8; nt++)
                #pragma unroll
                for (int cc = 0; cc < 2; cc++) {
                    int n = wj * 64 + nt * 8 + tig * 2 + cc;
                    s += ftanh_hw(acc[mt][nt][part * 2 + cc] + b1[n]) * W2[n];
                }
            s += __shfl_xor_sync(0xffffffffu, s, 1);
            s += __shfl_xor_sync(0xffffffffu, s, 2);
            if (tig == 0)
                atomicAdd(&red[wm * 32 + mt * 16 + gID + part * 8], s);
        }
    __syncthreads();
    if (tid < 64) g_s[m0 + tid] = red[tid];
}

// ---------------- GRU LDSM inner blocks (unchanged, verified) --------------------
__device__ __forceinline__ void ldsm_afrags(
    uint32_t As_u32, uint32_t afr[4][4], int wm, int lane, int kk)
{
    const int g = lane >> 3, lr = lane & 7;
    const int scol = kk * 2 + (g >> 1);
    #pragma unroll
    for (int mt = 0; mt < 4; mt++) {
        const int row = wm * 64 + mt * 16 + ((g & 1) << 3) + lr;
        const uint32_t addr = As_u32 + row * 128 + ((scol ^ (row & 7)) << 4);
        LDSM4(afr[mt][0], afr[mt][1], afr[mt][2], afr[mt][3], addr);
    }
}

__device__ __forceinline__ void ldsm_bfrags(
    uint32_t Bs_u32, uint32_t bfr[6][2], int wj, int lane, int kk)
{
    const int g = lane >> 3, lr = lane & 7;
    const int scol = kk * 2 + (g & 1);
    #pragma unroll
    for (int q = 0; q < 3; q++) {
        const int nt = 2 * q + (g >> 1);
        const int row = (nt >> 1) * 64 + wj * 16 + (nt & 1) * 8 + lr;
        const uint32_t addr = Bs_u32 + row * 128 + ((scol ^ (row & 7)) << 4);
        LDSM4(bfr[2 * q][0], bfr[2 * q][1], bfr[2 * q + 1][0], bfr[2 * q + 1][1], addr);
    }
}

__device__ __forceinline__ void mma_all(
    const uint32_t afr[4][4], const uint32_t bfr[6][2], float acc[4][6][4])
{
    #pragma unroll
    for (int mt = 0; mt < 4; mt++)
        #pragma unroll
        for (int nt = 0; nt < 6; nt++)
            mma16816(acc[mt][nt][0], acc[mt][nt][1], acc[mt][nt][2], acc[mt][nt][3],
                     afr[mt][0], afr[mt][1], afr[mt][2], afr[mt][3],
                     bfr[nt][0], bfr[nt][1]);
}

__device__ __forceinline__ void mma_block2(
    uint32_t As_u32, uint32_t Bs1_u32, uint32_t Bs2_u32,
    float acc[4][6][4], int wm, int wj, int lane)
{
    #pragma unroll
    for (int kk = 0; kk < 4; kk++) {
        uint32_t afr[4][4], bfr[6][2];
        ldsm_afrags(As_u32, afr, wm, lane, kk);
        ldsm_bfrags(Bs1_u32, bfr, wj, lane, kk);
        mma_all(afr, bfr, acc);
        ldsm_bfrags(Bs2_u32, bfr, wj, lane, kk);
        mma_all(afr, bfr, acc);
    }
}

__device__ __forceinline__ void mma_block1(
    uint32_t As_u32, uint32_t Bs_u32,
    float acc[4][6][4], int wm, int wj, int lane)
{
    #pragma unroll
    for (int kk = 0; kk < 4; kk++) {
        uint32_t afr[4][4], bfr[6][2];
        ldsm_afrags(As_u32, afr, wm, lane, kk);
        ldsm_bfrags(Bs_u32, bfr, wj, lane, kk);
        mma_all(afr, bfr, acc);
    }
}

// ---------------- persistent GRU (unchanged from R10) ----------------------------
#define SLAB (192 * 64)
#define ATILE (128 * 64)
__global__ void __launch_bounds__(256) gru_persist(
    const float* __restrict__ bhh_f, const float* __restrict__ bhh_b)
{
    extern __shared__ __nv_bfloat16 smem[];
    __nv_bfloat16* Bsh = smem;
    __nv_bfloat16* Bsl = smem + 4 * SLAB;
    __nv_bfloat16* A0  = smem + 8 * SLAB;
    __nv_bfloat16* A1  = A0 + ATILE;
    const uint32_t Bsh_u32 = (uint32_t)__cvta_generic_to_shared(Bsh);
    const uint32_t Bsl_u32 = (uint32_t)__cvta_generic_to_shared(Bsl);
    const uint32_t A0_u32  = (uint32_t)__cvta_generic_to_shared(A0);
    const uint32_t A1_u32  = (uint32_t)__cvta_generic_to_shared(A1);
    const uint32_t SLAB_B  = SLAB * 2;

    const int bid = blockIdx.x;
    const int dir = bid >> 6;
    const int sub = bid & 63;
    const int j0 = (sub & 3) * 64;
    const int mtile = sub >> 2;
    const int m0 = mtile * 128;
    int* const flag = &g_sync[(dir * 16 + mtile) * NT];

    const float* bhh = dir ? bhh_b : bhh_f;
    const float* gin = g_gates[dir];
    const __nv_bfloat16* __restrict__ wh = g_whh[dir];
    const __nv_bfloat16* __restrict__ wl = g_whl[dir];

    const int tid = threadIdx.x;
    const int warp = tid >> 5, lane = tid & 31;
    const int wm = warp >> 2, wj = warp & 3;
    const int gID = lane >> 2, tig = lane & 3;

    int lr[4], lc[4];
    #pragma unroll
    for (int i = 0; i < 4; i++) {
        int u = tid + 256 * i;
        lr[i] = u >> 3; lc[i] = (u & 7) * 8;
    }

    #pragma unroll
    for (int i = 0; i < 24; i++) {
        int u = tid + 256 * i;
        int r = u >> 5;
        int c = (u & 31) * 8;
        int slab = c >> 6, cs = c & 63;
        int g = r >> 6, j = j0 + (r & 63);
        *(uint4*)&Bsh[slab * SLAB + swzidx(r, cs)] =
            *(const uint4*)&wh[(g * NH + j) * NH + c];
        *(uint4*)&Bsl[slab * SLAB + swzidx(r, cs)] =
            *(const uint4*)&wl[(g * NH + j) * NH + c];
    }
    __syncthreads();

    for (int t = 0; t < NT; t++) {
        const int tt  = dir ? (NT - 1 - t) : t;
        const int ttp = dir ? (NT - t) : (t - 1);

        float acc[4][6][4];
        #pragma unroll
        for (int a = 0; a < 4; a++)
            #pragma unroll
            for (int b = 0; b < 6; b++)
                #pragma unroll
                for (int q = 0; q < 4; q++) acc[a][b][q] = 0.f;

        if (t > 0) {
            if (tid == 0) {
                while (*(volatile int*)&flag[t - 1] < 4) { }
                __threadfence();
            }
            __syncthreads();

            #pragma unroll
            for (int i = 0; i < 4; i++)
                cpasync16(&A0[swzidx(lr[i], lc[i])],
                          &g_gruh[((size_t)(m0 + lr[i]) * NT + ttp) * 512 + dir * NH + lc[i]]);
            CP_COMMIT();
            for (int ksl = 0; ksl < 4; ksl++) {
                const int ks = ksl * 64;
                CP_WAIT0(); __syncthreads();
                #pragma unroll
                for (int i = 0; i < 4; i++)
                    cpasync16(&A1[swzidx(lr[i], lc[i])],
                              &g_grul[((size_t)(m0 + lr[i]) * NT + ttp) * 512 + dir * NH + ks + lc[i]]);
                CP_COMMIT();
                mma_block2(A0_u32, Bsl_u32 + ksl * SLAB_B, Bsh_u32 + ksl * SLAB_B,
                           acc, wm, wj, lane);
                CP_WAIT0(); __syncthreads();
                if (ksl < 3) {
                    #pragma unroll
                    for (int i = 0; i < 4; i++)
                        cpasync16(&A0[swzidx(lr[i], lc[i])],
                                  &g_gruh[((size_t)(m0 + lr[i]) * NT + ttp) * 512 + dir * NH + ks + 64 + lc[i]]);
                    CP_COMMIT();
                }
                mma_block1(A1_u32, Bsh_u32 + ksl * SLAB_B, acc, wm, wj, lane);
            }
        }

        #pragma unroll
        for (int mt = 0; mt < 4; mt++)
            #pragma unroll
            for (int part = 0; part < 2; part++) {
                const int m = m0 + wm * 64 + mt * 16 + gID + part * 8;
                #pragma unroll
                for (int jn = 0; jn < 2; jn++) {
                    const int jg = j0 + wj * 16 + jn * 8 + tig * 2;
                    float hn2[2];
                    #pragma unroll
                    for (int cc = 0; cc < 2; cc++) {
                        const int j = jg + cc;
                        float ghr = acc[mt][jn][part * 2 + cc]     + bhh[j];
                        float ghz = acc[mt][2 + jn][part * 2 + cc] + bhh[NH + j];
                        float ghn = acc[mt][4 + jn][part * 2 + cc] + bhh[2 * NH + j];
                        const float* gp = gin + m * 3 * NH + j;
                        float r  = fsig_hw(gp[0] + ghr);
                        float zz = fsig_hw(gp[NH] + ghz);
                        float nn = ftanh_hw(gp[2 * NH] + r * ghn);
                        float hold = 0.f;
                        if (t > 0) {
                            size_t hp = ((size_t)m * NT + ttp) * 512 + dir * NH + j;
                            hold = b2f(g_gruh[hp]) + b2f(g_grul[hp]);
                        }
                        hn2[cc] = (1.f - zz) * nn + zz * hold;
                    }
                    __nv_bfloat16 h0, l0, h1, l1;
                    bsplit(hn2[0], h0, l0);
                    bsplit(hn2[1], h1, l1);
                    __nv_bfloat162 vh, vl;
                    vh.x = h0; vh.y = h1; vl.x = l0; vl.y = l1;
                    size_t go = ((size_t)m * NT + tt) * 512 + dir * NH + jg;
                    *(__nv_bfloat162*)(g_gruh + go) = vh;
                    *(__nv_bfloat162*)(g_grul + go) = vl;
                }
            }

        if (t < NT - 1) {
            __syncthreads();
            if (tid == 0) {
                __threadfence();
                atomicAdd(&flag[t], 1);
            }
        }
    }
}

// ---------------- fused softmax + context + joint head + FK ----------------------
__global__ void __launch_bounds__(256) ctx_fk(
    const float* __restrict__ jW, const float* __restrict__ jb,
    float* __restrict__ out)
{
    const int b = blockIdx.x;
    const int tid = threadIdx.x;
    const int warp = tid >> 5, lane = tid & 31;

    __shared__ float jWs[6][512];
    __shared__ float w[NT];
    __shared__ float csh[512];
    __shared__ float p1sh[NT][8];
    __shared__ float cJ[8];

    for (int i = tid; i < 6 * 512; i += 256) jWs[i >> 9][i & 511] = jW[i];
    for (int i = tid; i < 512; i += 256) csh[i] = 0.f;
    if (tid == 0) {
        float mx = -1e30f;
        float tmpv[NT];
        for (int t = 0; t < NT; t++) {
            tmpv[t] = g_s[b * NT + t];
            if (tmpv[t] > mx) mx = tmpv[t];
        }
        float s = 0.f;
        for (int t = 0; t < NT; t++) { tmpv[t] = __expf(tmpv[t] - mx); s += tmpv[t]; }
        float inv = __fdividef(1.f, s);
        for (int t = 0; t < NT; t++) w[t] = tmpv[t] * inv;
    }
    __syncthreads();

    float creg[16];
    #pragma unroll
    for (int k = 0; k < 16; k++) creg[k] = 0.f;

    for (int t = warp; t < NT; t += 8) {
        const __nv_bfloat16* rh = g_gruh + ((size_t)b * NT + t) * 512;
        const __nv_bfloat16* rl = g_grul + ((size_t)b * NT + t) * 512;
        const float wt = w[t];
        float pj[6];
        #pragma unroll
        for (int j = 0; j < 6; j++) pj[j] = 0.f;
        #pragma unroll
        for (int k = 0; k < 16; k++) {
            const int d = lane + 32 * k;
            float x = b2f(rh[d]) + b2f(rl[d]);
            creg[k] += wt * x;
            #pragma unroll
            for (int j = 0; j < 6; j++) pj[j] += x * jWs[j][d];
        }
        #pragma unroll
        for (int o = 16; o > 0; o >>= 1)
            #pragma unroll
            for (int j = 0; j < 6; j++)
                pj[j] += __shfl_xor_sync(0xffffffffu, pj[j], o);
        if (lane == 0) {
            #pragma unroll
            for (int j = 0; j < 6; j++) p1sh[t][j] = pj[j];
        }
    }
    #pragma unroll
    for (int k = 0; k < 16; k++)
        atomicAdd(&csh[lane + 32 * k], creg[k]);
    __syncthreads();

    if (warp == 0) {
        float pj[6];
        #pragma unroll
        for (int j = 0; j < 6; j++) pj[j] = 0.f;
        #pragma unroll
        for (int k = 0; k < 16; k++) {
            const int d = lane + 32 * k;
            float cv = csh[d];
            #pragma unroll
            for (int j = 0; j < 6; j++) pj[j] += cv * jWs[j][d];
        }
        #pragma unroll
        for (int o = 16; o > 0; o >>= 1)
            #pragma unroll
            for (int j = 0; j < 6; j++)
                pj[j] += __shfl_xor_sync(0xffffffffu, pj[j], o);
        if (lane == 0) {
            #pragma unroll
            for (int j = 0; j < 6; j++) cJ[j] = pj[j];
        }
    }
    __syncthreads();

    if (tid < NT) {
        const int t = tid;
        const float LO[6] = {-3.1416f, -1.5708f, -3.1416f, -2.6f, -1.5708f, -1.2f};
        const float UP[6] = { 3.1416f,  1.5708f,  3.1416f,  0.1f,  1.5708f,  1.2f};
        float th[6];
        #pragma unroll
        for (int j = 0; j < 6; j++)
            th[j] = (p1sh[t][j] + cJ[j] + jb[j]) * (UP[j] - LO[j]) + LO[j];

        float c0[3] = {1.f, 0.f, 0.f}, c1[3] = {0.f, 1.f, 0.f}, c2[3] = {0.f, 0.f, 1.f};
        float px = 0.f, py = 0.f, pz = 0.10f;
        const float sh2x = 0.f, sh2y = 0.f, sh2z = 0.10f;

        float c, s, tmp;
        c = cosf(th[0]); s = sinf(th[0]);
        #pragma unroll
        for (int i = 0; i < 3; i++) { tmp = c*c0[i] + s*c1[i]; c1[i] = c*c1[i] - s*c0[i]; c0[i] = tmp; }
        c = cosf(th[1]); s = sinf(th[1]);
        #pragma unroll
        for (int i = 0; i < 3; i++) { tmp = c*c1[i] + s*c2[i]; c2[i] = c*c2[i] - s*c1[i]; c1[i] = tmp; }
        c = cosf(th[2]); s = sinf(th[2]);
        #pragma unroll
        for (int i = 0; i < 3; i++) { tmp = c*c0[i] - s*c2[i]; c2[i] = c*c2[i] + s*c0[i]; c0[i] = tmp; }
        px -= 0.25f * c1[0]; py -= 0.25f * c1[1]; pz -= 0.25f * c1[2];
        float fax = px, fay = py, faz = pz;
        c = cosf(th[3]); s = sinf(th[3]);
        #pragma unroll
        for (int i = 0; i < 3; i++) { tmp = c*c1[i] + s*c2[i]; c2[i] = c*c2[i] - s*c1[i]; c1[i] = tmp; }
        c = cosf(th[4]); s = sinf(th[4]);
        #pragma unroll
        for (int i = 0; i < 3; i++) { tmp = c*c0[i] - s*c2[i]; c2[i] = c*c2[i] + s*c0[i]; c0[i] = tmp; }
        px -= 0.25f * c1[0]; py -= 0.25f * c1[1]; pz -= 0.25f * c1[2];
        float wx = px, wy = py, wz = pz;
        c = cosf(th[5]); s = sinf(th[5]);
        #pragma unroll
        for (int i = 0; i < 3; i++) { tmp = c*c1[i] + s*c2[i]; c2[i] = c*c2[i] - s*c1[i]; c1[i] = tmp; }

        float f1x = wx - 0.08f*c1[0] + 0.02f*c2[0];
        float f1y = wy - 0.08f*c1[1] + 0.02f*c2[1];
        float f1z = wz - 0.08f*c1[2] + 0.02f*c2[2];
        float f4x = wx - 0.08f*c1[0] - 0.02f*c2[0];
        float f4y = wy - 0.08f*c1[1] - 0.02f*c2[1];
        float f4z = wz - 0.08f*c1[2] - 0.02f*c2[2];

        float d1x = sh2x - fax, d1y = sh2y - fay, d1z = sh2z - faz;
        float d2x = wx - fax,   d2y = wy - fay,   d2z = wz - faz;
        float bodyL = 0.5f * (sqrtf(d1x*d1x + d1y*d1y + d1z*d1z)
                            + sqrtf(d2x*d2x + d2y*d2y + d2z*d2z));
        float inv = 1.f / bodyL;

        float* o = out + ((size_t)b * NT + t) * 9;
        o[0] = (wx  - sh2x) * inv; o[1] = (wy  - sh2y) * inv; o[2] = (wz  - sh2z) * inv;
        o[3] = (f1x - sh2x) * inv; o[4] = (f1y - sh2y) * inv; o[5] = (f1z - sh2z) * inv;
        o[6] = (f4x - sh2x) * inv; o[7] = (f4y - sh2y) * inv; o[8] = (f4z - sh2z) * inv;
    }
}

// ---------------- host launcher ---------------------------------------------------
extern "C" void kernel_launch(void* const* d_in, const int* in_sizes, int n_in,
                              void* d_out, int out_size)
{
    const float* z       = (const float*)d_in[0];
    const float* W_fc    = (const float*)d_in[1];
    const float* b_fc    = (const float*)d_in[2];
    const float* bn_g    = (const float*)d_in[3];
    const float* bn_b    = (const float*)d_in[4];
    const float* Wih_f   = (const float*)d_in[5];
    const float* Whh_f   = (const float*)d_in[6];
    const float* bih_f   = (const float*)d_in[7];
    const float* bhh_f   = (const float*)d_in[8];
    const float* Wih_b   = (const float*)d_in[9];
    const float* Whh_b   = (const float*)d_in[10];
    const float* bih_b   = (const float*)d_in[11];
    const float* bhh_b   = (const float*)d_in[12];
    const float* attn_W1 = (const float*)d_in[13];
    const float* attn_b1 = (const float*)d_in[14];
    const float* attn_W2 = (const float*)d_in[15];
    const float* joint_W = (const float*)d_in[16];
    const float* joint_b = (const float*)d_in[17];
    float* out = (float*)d_out;

    static int smem_set = 0;
    const int gru_smem = (8 * SLAB + 2 * ATILE) * 2;
    const int at_smem = AT_SMEM_ELEMS * 2;             // 81920 bytes
    if (!smem_set) {
        cudaFuncSetAttribute(gru_persist,
            cudaFuncAttributeMaxDynamicSharedMemorySize, gru_smem);
        cudaFuncSetAttribute(attn_mma,
            cudaFuncAttributeMaxDynamicSharedMemorySize, at_smem);
        cudaFuncSetAttribute(gemm_gates_mma,
            cudaFuncAttributeMaxDynamicSharedMemorySize, at_smem);
        smem_set = 1;
    }

    // 1) fc GEMM + weight splits + flag reset
    fc_prep<<<1792, 256>>>(z, W_fc, b_fc, Whh_f, Whh_b, Wih_f, Wih_b, attn_W1);
    // 2) batch stats
    bn_stats<<<ND, 256>>>();
    // 3) BN + lrelu + bf16 split of x
    bn_apply_split<<<NB * ND / 256, 256>>>(bn_g, bn_b);
    // 4) gate GEMM on tensor cores (both dirs)
    gemm_gates_mma<<<dim3(3, NB / 64, 2), 256, at_smem>>>(bih_f, bih_b);
    // 5) GRU recurrence (persistent)
    gru_persist<<<128, 256, gru_smem>>>(bhh_f, bhh_b);
    // 6) attention scores
    attn_mma<<<NB * NT / 64, 256, at_smem>>>(attn_b1, attn_W2);
    // 7) fused softmax + context + joints + FK
    ctx_fk<<<NB, 256>>>(joint_W, joint_b, out);
}

// round 12
// speedup vs baseline: 2.1051x; 1.0785x over previous
#include <cuda_runtime.h>
#include <cuda_bf16.h>
#include <math.h>
#include <stdint.h>

#define NB   2048
#define NT   60
#define NDL  100
#define ND   512
#define NH   256

// ---------------- scratch (device globals) ----------------
__device__ float g_h0[NB * ND];
__device__ float g_stats[2 * ND];
__device__ float g_gates[2][NB * 3 * NH];          // x@Wih^T + bih (fp32)
__device__ __nv_bfloat16 g_xh[NB * ND];            // BN+lrelu x split hi
__device__ __nv_bfloat16 g_xl[NB * ND];            // BN+lrelu x split lo
__device__ __nv_bfloat16 g_whh[2][3 * NH * NH];    // Whh split hi
__device__ __nv_bfloat16 g_whl[2][3 * NH * NH];    // Whh split lo
__device__ __nv_bfloat16 g_wihh[2][3 * NH * ND];   // Wih split hi
__device__ __nv_bfloat16 g_wihl[2][3 * NH * ND];   // Wih split lo
__device__ __nv_bfloat16 g_w1h[NH * 2 * NH];       // attn_W1 split hi
__device__ __nv_bfloat16 g_w1l[NH * 2 * NH];       // attn_W1 split lo
__device__ __nv_bfloat16 g_gruh[NB * NT * 2 * NH]; // gru out bf16 hi (= state)
__device__ __nv_bfloat16 g_grul[NB * NT * 2 * NH]; // gru out bf16 lo
__device__ float g_s[NB * NT];
__device__ int   g_sync[2 * 16 * NT];              // group flags [dir][mtile][t]

__device__ __forceinline__ void bsplit(float v, __nv_bfloat16& h, __nv_bfloat16& l) {
    h = __float2bfloat16(v);
    l = __float2bfloat16(v - __bfloat162float(h));
}

__device__ __forceinline__ void mma16816(float& d0, float& d1, float& d2, float& d3,
    uint32_t a0, uint32_t a1, uint32_t a2, uint32_t a3, uint32_t b0, uint32_t b1)
{
    asm volatile("mma.sync.aligned.m16n8k16.row.col.f32.bf16.bf16.f32 "
                 "{%0,%1,%2,%3},{%4,%5,%6,%7},{%8,%9},{%0,%1,%2,%3};"
                 : "+f"(d0), "+f"(d1), "+f"(d2), "+f"(d3)
                 : "r"(a0), "r"(a1), "r"(a2), "r"(a3), "r"(b0), "r"(b1));
}

#define LDSM4(r0, r1, r2, r3, addr) \
    asm volatile("ldmatrix.sync.aligned.m8n8.x4.shared.b16 {%0,%1,%2,%3}, [%4];" \
                 : "=r"(r0), "=r"(r1), "=r"(r2), "=r"(r3) : "r"(addr))

__device__ __forceinline__ void cpasync16(void* sdst, const void* gsrc) {
    uint32_t s = (uint32_t)__cvta_generic_to_shared(sdst);
    asm volatile("cp.async.cg.shared.global [%0], [%1], 16;" :: "r"(s), "l"(gsrc));
}
#define CP_COMMIT() asm volatile("cp.async.commit_group;")
#define CP_WAIT0()  asm volatile("cp.async.wait_group 0;")

__device__ __forceinline__ float ftanh_hw(float x) {
    float r;
    asm("tanh.approx.f32 %0, %1;" : "=f"(r) : "f"(x));
    return r;
}
__device__ __forceinline__ float fsig_hw(float x) {
    return fmaf(ftanh_hw(0.5f * x), 0.5f, 0.5f);
}
__device__ __forceinline__ float b2f(__nv_bfloat16 v) { return __bfloat162float(v); }

// swizzled smem index (elements): stride 64, XOR 8-col blocks by (row&7).
__device__ __forceinline__ int swzidx(int r, int c) {
    return r * 64 + ((((c >> 3) ^ (r & 7)) << 3) | (c & 7));
}

// ---------------- fused fc GEMM + weight splits + flag reset ---------------------
__global__ void __launch_bounds__(256) fc_prep(
    const float* __restrict__ z, const float* __restrict__ W_fc,
    const float* __restrict__ b_fc,
    const float* __restrict__ Whh_f, const float* __restrict__ Whh_b,
    const float* __restrict__ Wih_f, const float* __restrict__ Wih_b,
    const float* __restrict__ W1)
{
    __shared__ float As[16][65];
    __shared__ float Bs[16][65];
    if (blockIdx.x < 256) {
        const int N = ND, K = NDL;
        int tid = threadIdx.x;
        int tx = tid & 15, ty = tid >> 4;
        int m0 = (blockIdx.x >> 3) * 64, n0 = (blockIdx.x & 7) * 64;
        float acc[4][4] = {};
        for (int k0 = 0; k0 < K; k0 += 16) {
            #pragma unroll
            for (int i = 0; i < 4; i++) {
                int lin = tid + i * 256;
                int m = lin >> 4, k = lin & 15;
                As[k][m] = (k0 + k < K) ? z[(m0 + m) * K + k0 + k] : 0.f;
            }
            #pragma unroll
            for (int i = 0; i < 4; i++) {
                int lin = tid + i * 256;
                int n = lin >> 4, k = lin & 15;
                Bs[k][n] = (k0 + k < K) ? W_fc[(n0 + n) * K + k0 + k] : 0.f;
            }
            __syncthreads();
            #pragma unroll
            for (int kk = 0; kk < 16; kk++) {
                float a[4], b[4];
                #pragma unroll
                for (int i = 0; i < 4; i++) a[i] = As[kk][ty * 4 + i];
                #pragma unroll
                for (int j = 0; j < 4; j++) b[j] = Bs[kk][tx * 4 + j];
                #pragma unroll
                for (int i = 0; i < 4; i++)
                    #pragma unroll
                    for (int j = 0; j < 4; j++) acc[i][j] += a[i] * b[j];
            }
            __syncthreads();
        }
        #pragma unroll
        for (int i = 0; i < 4; i++) {
            int m = m0 + ty * 4 + i;
            #pragma unroll
            for (int j = 0; j < 4; j++) {
                int n = n0 + tx * 4 + j;
                g_h0[m * N + n] = acc[i][j] + b_fc[n];
            }
        }
    } else {
        int i = (blockIdx.x - 256) * 256 + threadIdx.x;
        bsplit(Wih_f[i], g_wihh[0][i], g_wihl[0][i]);
        bsplit(Wih_b[i], g_wihh[1][i], g_wihl[1][i]);
        if (i < 3 * NH * NH) {
            bsplit(Whh_f[i], g_whh[0][i], g_whl[0][i]);
            bsplit(Whh_b[i], g_whh[1][i], g_whl[1][i]);
        }
        if (i < NH * 2 * NH) bsplit(W1[i], g_w1h[i], g_w1l[i]);
        if (i < 2 * 16 * NT) g_sync[i] = 0;
    }
}

// ---------------- batchnorm stats -------------------------------------------------
__global__ void __launch_bounds__(256) bn_stats()
{
    int c = blockIdx.x;
    float s = 0.f, s2 = 0.f;
    for (int r = threadIdx.x; r < NB; r += 256) {
        float v = g_h0[r * ND + c];
        s += v; s2 += v * v;
    }
    __shared__ float sh[256], sh2[256];
    sh[threadIdx.x] = s; sh2[threadIdx.x] = s2;
    __syncthreads();
    for (int o = 128; o > 0; o >>= 1) {
        if (threadIdx.x < o) {
            sh[threadIdx.x]  += sh[threadIdx.x + o];
            sh2[threadIdx.x] += sh2[threadIdx.x + o];
        }
        __syncthreads();
    }
    if (threadIdx.x == 0) {
        float mu = sh[0] / (float)NB;
        g_stats[c] = mu;
        g_stats[ND + c] = sh2[0] / (float)NB - mu * mu;
    }
}

// ---------------- BN + LeakyReLU + bf16 hi/lo split -------------------------------
__global__ void __launch_bounds__(256) bn_apply_split(
    const float* __restrict__ bn_g, const float* __restrict__ bn_b)
{
    int i = blockIdx.x * 256 + threadIdx.x;
    int c = i & (ND - 1);
    float mu = g_stats[c], var = g_stats[ND + c];
    float v = (g_h0[i] - mu) * rsqrtf(var + 1e-5f) * bn_g[c] + bn_b[c];
    v = (v >= 0.f) ? v : 0.2f * v;
    bsplit(v, g_xh[i], g_xl[i]);
}

// ---------------- LDSM fragment loaders (verified in GRU) ------------------------
__device__ __forceinline__ void ldsm_afrags(
    uint32_t As_u32, uint32_t afr[4][4], int wm, int lane, int kk)
{
    const int g = lane >> 3, lr = lane & 7;
    const int scol = kk * 2 + (g >> 1);
    #pragma unroll
    for (int mt = 0; mt < 4; mt++) {
        const int row = wm * 64 + mt * 16 + ((g & 1) << 3) + lr;
        const uint32_t addr = As_u32 + row * 128 + ((scol ^ (row & 7)) << 4);
        LDSM4(afr[mt][0], afr[mt][1], afr[mt][2], afr[mt][3], addr);
    }
}

__device__ __forceinline__ void ldsmB8(
    uint32_t base, uint32_t bfr[8][2], int wj, int lane, int kk)
{
    const int g = lane >> 3, lr = lane & 7;
    const int scol = kk * 2 + (g & 1);
    #pragma unroll
    for (int q = 0; q < 4; q++) {
        const int nt = 2 * q + (g >> 1);
        const int row = wj * 64 + nt * 8 + lr;
        const uint32_t addr = base + row * 128 + ((scol ^ (row & 7)) << 4);
        LDSM4(bfr[2 * q][0], bfr[2 * q][1], bfr[2 * q + 1][0], bfr[2 * q + 1][1], addr);
    }
}

__device__ __forceinline__ void mma48(
    const uint32_t afr[4][4], const uint32_t bfr[8][2], float acc[4][8][4])
{
    #pragma unroll
    for (int mt = 0; mt < 4; mt++)
        #pragma unroll
        for (int nt = 0; nt < 8; nt++)
            mma16816(acc[mt][nt][0], acc[mt][nt][1], acc[mt][nt][2], acc[mt][nt][3],
                     afr[mt][0], afr[mt][1], afr[mt][2], afr[mt][3],
                     bfr[nt][0], bfr[nt][1]);
}

// ---------------- shared 128x256 x K=512 split-MMA core --------------------------
#define AT_AS0 0
#define AT_AS1 8192
#define AT_BS0 16384
#define AT_BS1 32768
#define AT_SMEM_ELEMS 49152

__device__ __forceinline__ void split_mma_128x256(
    const __nv_bfloat16* __restrict__ ah, const __nv_bfloat16* __restrict__ al,
    const __nv_bfloat16* __restrict__ bh, const __nv_bfloat16* __restrict__ bl,
    __nv_bfloat16* smem, float acc[4][8][4], int tid)
{
    const uint32_t s_u32 = (uint32_t)__cvta_generic_to_shared(smem);
    const uint32_t As0 = s_u32 + AT_AS0 * 2;
    const uint32_t As1 = s_u32 + AT_AS1 * 2;
    const uint32_t Bs0 = s_u32 + AT_BS0 * 2;
    const uint32_t Bs1 = s_u32 + AT_BS1 * 2;
    const int warp = tid >> 5, lane = tid & 31;
    const int wm = warp >> 2, wj = warp & 3;

    for (int ksi = 0; ksi < 8; ksi++) {
        const int ks = ksi * 64;
        if (ksi > 0) __syncthreads();
        #pragma unroll
        for (int i = 0; i < 4; i++) {          // A slabs: 128x64 each
            int u = tid + 256 * i;
            int r = u >> 3, c = (u & 7) << 3;
            cpasync16(&smem[AT_AS0 + swzidx(r, c)], &ah[(size_t)r * 512 + ks + c]);
            cpasync16(&smem[AT_AS1 + swzidx(r, c)], &al[(size_t)r * 512 + ks + c]);
        }
        #pragma unroll
        for (int i = 0; i < 8; i++) {          // B slabs: 256x64 each
            int u = tid + 256 * i;
            int r = u >> 3, c = (u & 7) << 3;
            cpasync16(&smem[AT_BS0 + swzidx(r, c)], &bh[(size_t)r * 512 + ks + c]);
            cpasync16(&smem[AT_BS1 + swzidx(r, c)], &bl[(size_t)r * 512 + ks + c]);
        }
        CP_COMMIT();
        CP_WAIT0();
        __syncthreads();
        #pragma unroll
        for (int kk = 0; kk < 4; kk++) {
            uint32_t afr[4][4], bfr[8][2];
            ldsm_afrags(As0, afr, wm, lane, kk);   // A hi, reused for two products
            ldsmB8(Bs1, bfr, wj, lane, kk);        // hi * lo
            mma48(afr, bfr, acc);
            ldsmB8(Bs0, bfr, wj, lane, kk);        // hi * hi
            mma48(afr, bfr, acc);
            ldsm_afrags(As1, afr, wm, lane, kk);   // lo * hi
            mma48(afr, bfr, acc);
        }
    }
}

// ---------------- gate GEMM on tensor cores (128x256 tiles) ----------------------
__global__ void __launch_bounds__(256) gemm_gates_mma(
    const float* __restrict__ bf, const float* __restrict__ bb)
{
    extern __shared__ __nv_bfloat16 dynsm[];
    const int tid = threadIdx.x;
    const int ct = blockIdx.x;              // 256-col tile of N=768
    const int m0 = blockIdx.y * 128;
    const int dir = blockIdx.z;
    const float* bias = dir ? bb : bf;
    float* C = g_gates[dir];

    float acc[4][8][4];
    #pragma unroll
    for (int a = 0; a < 4; a++)
        #pragma unroll
        for (int b = 0; b < 8; b++)
            #pragma unroll
            for (int q = 0; q < 4; q++) acc[a][b][q] = 0.f;

    split_mma_128x256(g_xh + (size_t)m0 * 512, g_xl + (size_t)m0 * 512,
                      g_wihh[dir] + (size_t)ct * 256 * 512,
                      g_wihl[dir] + (size_t)ct * 256 * 512,
                      dynsm, acc, tid);

    const int warp = tid >> 5, lane = tid & 31;
    const int wm = warp >> 2, wj = warp & 3;
    const int gID = lane >> 2, tig = lane & 3;
    #pragma unroll
    for (int mt = 0; mt < 4; mt++)
        #pragma unroll
        for (int part = 0; part < 2; part++) {
            const int m = m0 + wm * 64 + mt * 16 + gID + part * 8;
            #pragma unroll
            for (int nt = 0; nt < 8; nt++)
                #pragma unroll
                for (int cc = 0; cc < 2; cc++) {
                    const int n = ct * 256 + wj * 64 + nt * 8 + tig * 2 + cc;
                    C[(size_t)m * 768 + n] = acc[mt][nt][part * 2 + cc] + bias[n];
                }
        }
}

// ---------------- attention scores (128x256 tiles) -------------------------------
__global__ void __launch_bounds__(256) attn_mma(
    const float* __restrict__ b1, const float* __restrict__ W2)
{
    extern __shared__ __nv_bfloat16 dynsm[];
    __shared__ float red[128];
    const int tid = threadIdx.x;
    const int m0 = blockIdx.x * 128;
    if (tid < 128) red[tid] = 0.f;

    float acc[4][8][4];
    #pragma unroll
    for (int a = 0; a < 4; a++)
        #pragma unroll
        for (int b = 0; b < 8; b++)
            #pragma unroll
            for (int q = 0; q < 4; q++) acc[a][b][q] = 0.f;

    split_mma_128x256(g_gruh + (size_t)m0 * 512, g_grul + (size_t)m0 * 512,
                      g_w1h, g_w1l, dynsm, acc, tid);

    const int warp = tid >> 5, lane = tid & 31;
    const int wm = warp >> 2, wj = warp & 3;
    const int gID = lane >> 2, tig = lane & 3;
    __syncthreads();
    #pragma unroll
    for (int mt = 0; mt < 4; mt++)
        #pragma unroll
        for (int part = 0; part < 2; part++) {
            float s = 0.f;
            #pragma unroll
            for (int nt = 0; nt < 8; nt++)
                #pragma unroll
                for (int cc = 0; cc < 2; cc++) {
                    int n = wj * 64 + nt * 8 + tig * 2 + cc;
                    s += ftanh_hw(acc[mt][nt][part * 2 + cc] + b1[n]) * W2[n];
                }
            s += __shfl_xor_sync(0xffffffffu, s, 1);
            s += __shfl_xor_sync(0xffffffffu, s, 2);
            if (tig == 0)
                atomicAdd(&red[wm * 64 + mt * 16 + gID + part * 8], s);
        }
    __syncthreads();
    if (tid < 128) g_s[m0 + tid] = red[tid];
}

// ---------------- GRU LDSM inner blocks ------------------------------------------
__device__ __forceinline__ void ldsm_bfrags(
    uint32_t Bs_u32, uint32_t bfr[6][2], int wj, int lane, int kk)
{
    const int g = lane >> 3, lr = lane & 7;
    const int scol = kk * 2 + (g & 1);
    #pragma unroll
    for (int q = 0; q < 3; q++) {
        const int nt = 2 * q + (g >> 1);
        const int row = (nt >> 1) * 64 + wj * 16 + (nt & 1) * 8 + lr;
        const uint32_t addr = Bs_u32 + row * 128 + ((scol ^ (row & 7)) << 4);
        LDSM4(bfr[2 * q][0], bfr[2 * q][1], bfr[2 * q + 1][0], bfr[2 * q + 1][1], addr);
    }
}

__device__ __forceinline__ void mma_all(
    const uint32_t afr[4][4], const uint32_t bfr[6][2], float acc[4][6][4])
{
    #pragma unroll
    for (int mt = 0; mt < 4; mt++)
        #pragma unroll
        for (int nt = 0; nt < 6; nt++)
            mma16816(acc[mt][nt][0], acc[mt][nt][1], acc[mt][nt][2], acc[mt][nt][3],
                     afr[mt][0], afr[mt][1], afr[mt][2], afr[mt][3],
                     bfr[nt][0], bfr[nt][1]);
}

__device__ __forceinline__ void mma_block2(
    uint32_t As_u32, uint32_t Bs1_u32, uint32_t Bs2_u32,
    float acc[4][6][4], int wm, int wj, int lane)
{
    #pragma unroll
    for (int kk = 0; kk < 4; kk++) {
        uint32_t afr[4][4], bfr[6][2];
        ldsm_afrags(As_u32, afr, wm, lane, kk);
        ldsm_bfrags(Bs1_u32, bfr, wj, lane, kk);
        mma_all(afr, bfr, acc);
        ldsm_bfrags(Bs2_u32, bfr, wj, lane, kk);
        mma_all(afr, bfr, acc);
    }
}

__device__ __forceinline__ void mma_block1(
    uint32_t As_u32, uint32_t Bs_u32,
    float acc[4][6][4], int wm, int wj, int lane)
{
    #pragma unroll
    for (int kk = 0; kk < 4; kk++) {
        uint32_t afr[4][4], bfr[6][2];
        ldsm_afrags(As_u32, afr, wm, lane, kk);
        ldsm_bfrags(Bs_u32, bfr, wj, lane, kk);
        mma_all(afr, bfr, acc);
    }
}

// ---------------- persistent GRU (ksl permuted so hold ends in smem) -------------
#define SLAB (192 * 64)
#define ATILE (128 * 64)
__global__ void __launch_bounds__(256) gru_persist(
    const float* __restrict__ bhh_f, const float* __restrict__ bhh_b)
{
    extern __shared__ __nv_bfloat16 smem[];
    __nv_bfloat16* Bsh = smem;
    __nv_bfloat16* Bsl = smem + 4 * SLAB;
    __nv_bfloat16* A0  = smem + 8 * SLAB;
    __nv_bfloat16* A1  = A0 + ATILE;
    const uint32_t Bsh_u32 = (uint32_t)__cvta_generic_to_shared(Bsh);
    const uint32_t Bsl_u32 = (uint32_t)__cvta_generic_to_shared(Bsl);
    const uint32_t A0_u32  = (uint32_t)__cvta_generic_to_shared(A0);
    const uint32_t A1_u32  = (uint32_t)__cvta_generic_to_shared(A1);
    const uint32_t SLAB_B  = SLAB * 2;

    const int bid = blockIdx.x;
    const int dir = bid >> 6;
    const int sub = bid & 63;
    const int j0 = (sub & 3) * 64;
    const int jslab = j0 >> 6;
    const int mtile = sub >> 2;
    const int m0 = mtile * 128;
    int* const flag = &g_sync[(dir * 16 + mtile) * NT];

    const float* bhh = dir ? bhh_b : bhh_f;
    const float* gin = g_gates[dir];
    const __nv_bfloat16* __restrict__ wh = g_whh[dir];
    const __nv_bfloat16* __restrict__ wl = g_whl[dir];

    const int tid = threadIdx.x;
    const int warp = tid >> 5, lane = tid & 31;
    const int wm = warp >> 2, wj = warp & 3;
    const int gID = lane >> 2, tig = lane & 3;

    int lr[4], lc[4];
    #pragma unroll
    for (int i = 0; i < 4; i++) {
        int u = tid + 256 * i;
        lr[i] = u >> 3; lc[i] = (u & 7) * 8;
    }

    #pragma unroll
    for (int i = 0; i < 24; i++) {
        int u = tid + 256 * i;
        int r = u >> 5;
        int c = (u & 31) * 8;
        int slab = c >> 6, cs = c & 63;
        int g = r >> 6, j = j0 + (r & 63);
        *(uint4*)&Bsh[slab * SLAB + swzidx(r, cs)] =
            *(const uint4*)&wh[(g * NH + j) * NH + c];
        *(uint4*)&Bsl[slab * SLAB + swzidx(r, cs)] =
            *(const uint4*)&wl[(g * NH + j) * NH + c];
    }
    __syncthreads();

    for (int t = 0; t < NT; t++) {
        const int tt  = dir ? (NT - 1 - t) : t;
        const int ttp = dir ? (NT - t) : (t - 1);

        float acc[4][6][4];
        #pragma unroll
        for (int a = 0; a < 4; a++)
            #pragma unroll
            for (int b = 0; b < 6; b++)
                #pragma unroll
                for (int q = 0; q < 4; q++) acc[a][b][q] = 0.f;

        if (t > 0) {
            if (tid == 0) {
                while (*(volatile int*)&flag[t - 1] < 4) { }
                __threadfence();
            }
            __syncthreads();

            // ksl order: jslab+1, jslab+2, jslab+3, jslab (ends on hold slab)
            const int ks0 = (((jslab + 1) & 3)) * 64;
            #pragma unroll
            for (int i = 0; i < 4; i++)
                cpasync16(&A0[swzidx(lr[i], lc[i])],
                          &g_gruh[((size_t)(m0 + lr[i]) * NT + ttp) * 512 + dir * NH + ks0 + lc[i]]);
            CP_COMMIT();
            for (int it = 0; it < 4; it++) {
                const int ksl = (jslab + 1 + it) & 3;
                const int ks = ksl * 64;
                CP_WAIT0(); __syncthreads();
                #pragma unroll
                for (int i = 0; i < 4; i++)
                    cpasync16(&A1[swzidx(lr[i], lc[i])],
                              &g_grul[((size_t)(m0 + lr[i]) * NT + ttp) * 512 + dir * NH + ks + lc[i]]);
                CP_COMMIT();
                mma_block2(A0_u32, Bsl_u32 + ksl * SLAB_B, Bsh_u32 + ksl * SLAB_B,
                           acc, wm, wj, lane);
                CP_WAIT0(); __syncthreads();
                if (it < 3) {
                    const int ksn = ((jslab + 2 + it) & 3) * 64;
                    #pragma unroll
                    for (int i = 0; i < 4; i++)
                        cpasync16(&A0[swzidx(lr[i], lc[i])],
                                  &g_gruh[((size_t)(m0 + lr[i]) * NT + ttp) * 512 + dir * NH + ksn + lc[i]]);
                    CP_COMMIT();
                }
                mma_block1(A1_u32, Bsh_u32 + ksl * SLAB_B, acc, wm, wj, lane);
            }
        }

        // epilogue: hold read from A0/A1 smem (slab jslab is resident)
        #pragma unroll
        for (int mt = 0; mt < 4; mt++)
            #pragma unroll
            for (int part = 0; part < 2; part++) {
                const int m = m0 + wm * 64 + mt * 16 + gID + part * 8;
                const int mrow = m - m0;
                #pragma unroll
                for (int jn = 0; jn < 2; jn++) {
                    const int jg = j0 + wj * 16 + jn * 8 + tig * 2;
                    float hn2[2];
                    #pragma unroll
                    for (int cc = 0; cc < 2; cc++) {
                        const int j = jg + cc;
                        float ghr = acc[mt][jn][part * 2 + cc]     + bhh[j];
                        float ghz = acc[mt][2 + jn][part * 2 + cc] + bhh[NH + j];
                        float ghn = acc[mt][4 + jn][part * 2 + cc] + bhh[2 * NH + j];
                        const float* gp = gin + m * 3 * NH + j;
                        float r  = fsig_hw(gp[0] + ghr);
                        float zz = fsig_hw(gp[NH] + ghz);
                        float nn = ftanh_hw(gp[2 * NH] + r * ghn);
                        float hold = 0.f;
                        if (t > 0) {
                            const int sw = swzidx(mrow, j & 63);
                            hold = b2f(A0[sw]) + b2f(A1[sw]);
                        }
                        hn2[cc] = (1.f - zz) * nn + zz * hold;
                    }
                    __nv_bfloat16 h0, l0, h1, l1;
                    bsplit(hn2[0], h0, l0);
                    bsplit(hn2[1], h1, l1);
                    __nv_bfloat162 vh, vl;
                    vh.x = h0; vh.y = h1; vl.x = l0; vl.y = l1;
                    size_t go = ((size_t)m * NT + tt) * 512 + dir * NH + jg;
                    *(__nv_bfloat162*)(g_gruh + go) = vh;
                    *(__nv_bfloat162*)(g_grul + go) = vl;
                }
            }

        if (t < NT - 1) {
            __syncthreads();
            if (tid == 0) {
                __threadfence();
                atomicAdd(&flag[t], 1);
            }
        }
    }
}

// ---------------- fused softmax + context + joint head + FK ----------------------
__global__ void __launch_bounds__(256) ctx_fk(
    const float* __restrict__ jW, const float* __restrict__ jb,
    float* __restrict__ out)
{
    const int b = blockIdx.x;
    const int tid = threadIdx.x;
    const int warp = tid >> 5, lane = tid & 31;

    __shared__ float jWs[6][512];
    __shared__ float w[NT];
    __shared__ float csh[512];
    __shared__ float p1sh[NT][8];
    __shared__ float cJ[8];

    for (int i = tid; i < 6 * 512; i += 256) jWs[i >> 9][i & 511] = jW[i];
    for (int i = tid; i < 512; i += 256) csh[i] = 0.f;
    if (tid == 0) {
        float mx = -1e30f;
        float tmpv[NT];
        for (int t = 0; t < NT; t++) {
            tmpv[t] = g_s[b * NT + t];
            if (tmpv[t] > mx) mx = tmpv[t];
        }
        float s = 0.f;
        for (int t = 0; t < NT; t++) { tmpv[t] = __expf(tmpv[t] - mx); s += tmpv[t]; }
        float inv = __fdividef(1.f, s);
        for (int t = 0; t < NT; t++) w[t] = tmpv[t] * inv;
    }
    __syncthreads();

    float creg[16];
    #pragma unroll
    for (int k = 0; k < 16; k++) creg[k] = 0.f;

    for (int t = warp; t < NT; t += 8) {
        const __nv_bfloat16* rh = g_gruh + ((size_t)b * NT + t) * 512;
        const __nv_bfloat16* rl = g_grul + ((size_t)b * NT + t) * 512;
        const float wt = w[t];
        float pj[6];
        #pragma unroll
        for (int j = 0; j < 6; j++) pj[j] = 0.f;
        #pragma unroll
        for (int k = 0; k < 16; k++) {
            const int d = lane + 32 * k;
            float x = b2f(rh[d]) + b2f(rl[d]);
            creg[k] += wt * x;
            #pragma unroll
            for (int j = 0; j < 6; j++) pj[j] += x * jWs[j][d];
        }
        #pragma unroll
        for (int o = 16; o > 0; o >>= 1)
            #pragma unroll
            for (int j = 0; j < 6; j++)
                pj[j] += __shfl_xor_sync(0xffffffffu, pj[j], o);
        if (lane == 0) {
            #pragma unroll
            for (int j = 0; j < 6; j++) p1sh[t][j] = pj[j];
        }
    }
    #pragma unroll
    for (int k = 0; k < 16; k++)
        atomicAdd(&csh[lane + 32 * k], creg[k]);
    __syncthreads();

    if (warp == 0) {
        float pj[6];
        #pragma unroll
        for (int j = 0; j < 6; j++) pj[j] = 0.f;
        #pragma unroll
        for (int k = 0; k < 16; k++) {
            const int d = lane + 32 * k;
            float cv = csh[d];
            #pragma unroll
            for (int j = 0; j < 6; j++) pj[j] += cv * jWs[j][d];
        }
        #pragma unroll
        for (int o = 16; o > 0; o >>= 1)
            #pragma unroll
            for (int j = 0; j < 6; j++)
                pj[j] += __shfl_xor_sync(0xffffffffu, pj[j], o);
        if (lane == 0) {
            #pragma unroll
            for (int j = 0; j < 6; j++) cJ[j] = pj[j];
        }
    }
    __syncthreads();

    if (tid < NT) {
        const int t = tid;
        const float LO[6] = {-3.1416f, -1.5708f, -3.1416f, -2.6f, -1.5708f, -1.2f};
        const float UP[6] = { 3.1416f,  1.5708f,  3.1416f,  0.1f,  1.5708f,  1.2f};
        float th[6];
        #pragma unroll
        for (int j = 0; j < 6; j++)
            th[j] = (p1sh[t][j] + cJ[j] + jb[j]) * (UP[j] - LO[j]) + LO[j];

        float c0[3] = {1.f, 0.f, 0.f}, c1[3] = {0.f, 1.f, 0.f}, c2[3] = {0.f, 0.f, 1.f};
        float px = 0.f, py = 0.f, pz = 0.10f;
        const float sh2x = 0.f, sh2y = 0.f, sh2z = 0.10f;

        float c, s, tmp;
        c = cosf(th[0]); s = sinf(th[0]);
        #pragma unroll
        for (int i = 0; i < 3; i++) { tmp = c*c0[i] + s*c1[i]; c1[i] = c*c1[i] - s*c0[i]; c0[i] = tmp; }
        c = cosf(th[1]); s = sinf(th[1]);
        #pragma unroll
        for (int i = 0; i < 3; i++) { tmp = c*c1[i] + s*c2[i]; c2[i] = c*c2[i] - s*c1[i]; c1[i] = tmp; }
        c = cosf(th[2]); s = sinf(th[2]);
        #pragma unroll
        for (int i = 0; i < 3; i++) { tmp = c*c0[i] - s*c2[i]; c2[i] = c*c2[i] + s*c0[i]; c0[i] = tmp; }
        px -= 0.25f * c1[0]; py -= 0.25f * c1[1]; pz -= 0.25f * c1[2];
        float fax = px, fay = py, faz = pz;
        c = cosf(th[3]); s = sinf(th[3]);
        #pragma unroll
        for (int i = 0; i < 3; i++) { tmp = c*c1[i] + s*c2[i]; c2[i] = c*c2[i] - s*c1[i]; c1[i] = tmp; }
        c = cosf(th[4]); s = sinf(th[4]);
        #pragma unroll
        for (int i = 0; i < 3; i++) { tmp = c*c0[i] - s*c2[i]; c2[i] = c*c2[i] + s*c0[i]; c0[i] = tmp; }
        px -= 0.25f * c1[0]; py -= 0.25f * c1[1]; pz -= 0.25f * c1[2];
        float wx = px, wy = py, wz = pz;
        c = cosf(th[5]); s = sinf(th[5]);
        #pragma unroll
        for (int i = 0; i < 3; i++) { tmp = c*c1[i] + s*c2[i]; c2[i] = c*c2[i] - s*c1[i]; c1[i] = tmp; }

        float f1x = wx - 0.08f*c1[0] + 0.02f*c2[0];
        float f1y = wy - 0.08f*c1[1] + 0.02f*c2[1];
        float f1z = wz - 0.08f*c1[2] + 0.02f*c2[2];
        float f4x = wx - 0.08f*c1[0] - 0.02f*c2[0];
        float f4y = wy - 0.08f*c1[1] - 0.02f*c2[1];
        float f4z = wz - 0.08f*c1[2] - 0.02f*c2[2];

        float d1x = sh2x - fax, d1y = sh2y - fay, d1z = sh2z - faz;
        float d2x = wx - fax,   d2y = wy - fay,   d2z = wz - faz;
        float bodyL = 0.5f * (sqrtf(d1x*d1x + d1y*d1y + d1z*d1z)
                            + sqrtf(d2x*d2x + d2y*d2y + d2z*d2z));
        float inv = 1.f / bodyL;

        float* o = out + ((size_t)b * NT + t) * 9;
        o[0] = (wx  - sh2x) * inv; o[1] = (wy  - sh2y) * inv; o[2] = (wz  - sh2z) * inv;
        o[3] = (f1x - sh2x) * inv; o[4] = (f1y - sh2y) * inv; o[5] = (f1z - sh2z) * inv;
        o[6] = (f4x - sh2x) * inv; o[7] = (f4y - sh2y) * inv; o[8] = (f4z - sh2z) * inv;
    }
}

// ---------------- host launcher ---------------------------------------------------
extern "C" void kernel_launch(void* const* d_in, const int* in_sizes, int n_in,
                              void* d_out, int out_size)
{
    const float* z       = (const float*)d_in[0];
    const float* W_fc    = (const float*)d_in[1];
    const float* b_fc    = (const float*)d_in[2];
    const float* bn_g    = (const float*)d_in[3];
    const float* bn_b    = (const float*)d_in[4];
    const float* Wih_f   = (const float*)d_in[5];
    const float* Whh_f   = (const float*)d_in[6];
    const float* bih_f   = (const float*)d_in[7];
    const float* bhh_f   = (const float*)d_in[8];
    const float* Wih_b   = (const float*)d_in[9];
    const float* Whh_b   = (const float*)d_in[10];
    const float* bih_b   = (const float*)d_in[11];
    const float* bhh_b   = (const float*)d_in[12];
    const float* attn_W1 = (const float*)d_in[13];
    const float* attn_b1 = (const float*)d_in[14];
    const float* attn_W2 = (const float*)d_in[15];
    const float* joint_W = (const float*)d_in[16];
    const float* joint_b = (const float*)d_in[17];
    float* out = (float*)d_out;

    static int smem_set = 0;
    const int gru_smem = (8 * SLAB + 2 * ATILE) * 2;
    const int at_smem = AT_SMEM_ELEMS * 2;             // 98304 bytes
    if (!smem_set) {
        cudaFuncSetAttribute(gru_persist,
            cudaFuncAttributeMaxDynamicSharedMemorySize, gru_smem);
        cudaFuncSetAttribute(attn_mma,
            cudaFuncAttributeMaxDynamicSharedMemorySize, at_smem);
        cudaFuncSetAttribute(gemm_gates_mma,
            cudaFuncAttributeMaxDynamicSharedMemorySize, at_smem);
        smem_set = 1;
    }

    // 1) fc GEMM + weight splits + flag reset
    fc_prep<<<1792, 256>>>(z, W_fc, b_fc, Whh_f, Whh_b, Wih_f, Wih_b, attn_W1);
    // 2) batch stats
    bn_stats<<<ND, 256>>>();
    // 3) BN + lrelu + bf16 split of x
    bn_apply_split<<<NB * ND / 256, 256>>>(bn_g, bn_b);
    // 4) gate GEMM on tensor cores (both dirs)
    gemm_gates_mma<<<dim3(3, NB / 128, 2), 256, at_smem>>>(bih_f, bih_b);
    // 5) GRU recurrence (persistent)
    gru_persist<<<128, 256, gru_smem>>>(bhh_f, bhh_b);
    // 6) attention scores
    attn_mma<<<NB * NT / 128, 256, at_smem>>>(attn_b1, attn_W2);
    // 7) fused softmax + context + joints + FK
    ctx_fk<<<NB, 256>>>(joint_W, joint_b, out);
}

// round 13
// speedup vs baseline: 2.2243x; 1.0566x over previous
#include <cuda_runtime.h>
#include <cuda_bf16.h>
#include <math.h>
#include <stdint.h>

#define NB   2048
#define NT   60
#define NDL  100
#define ND   512
#define NH   256

// ---------------- scratch (device globals) ----------------
__device__ float g_h0[NB * ND];
__device__ float g_stats[2 * ND];
__device__ float g_gates[2][NB * 3 * NH];          // x@Wih^T + bih (fp32)
__device__ __nv_bfloat16 g_xh[NB * ND];            // BN+lrelu x split hi
__device__ __nv_bfloat16 g_xl[NB * ND];            // BN+lrelu x split lo
__device__ __nv_bfloat16 g_whh[2][3 * NH * NH];    // Whh split hi
__device__ __nv_bfloat16 g_whl[2][3 * NH * NH];    // Whh split lo
__device__ __nv_bfloat16 g_wihh[2][3 * NH * ND];   // Wih split hi
__device__ __nv_bfloat16 g_wihl[2][3 * NH * ND];   // Wih split lo
__device__ __nv_bfloat16 g_w1h[NH * 2 * NH];       // attn_W1 split hi
__device__ __nv_bfloat16 g_w1l[NH * 2 * NH];       // attn_W1 split lo
__device__ __nv_bfloat16 g_gruh[NB * NT * 2 * NH]; // gru out bf16 hi (= state)
__device__ __nv_bfloat16 g_grul[NB * NT * 2 * NH]; // gru out bf16 lo
__device__ float g_s[NB * NT];
__device__ int   g_sync[2 * 16 * NT];              // group flags [dir][mtile][t]

__device__ __forceinline__ void bsplit(float v, __nv_bfloat16& h, __nv_bfloat16& l) {
    h = __float2bfloat16(v);
    l = __float2bfloat16(v - __bfloat162float(h));
}

__device__ __forceinline__ void mma16816(float& d0, float& d1, float& d2, float& d3,
    uint32_t a0, uint32_t a1, uint32_t a2, uint32_t a3, uint32_t b0, uint32_t b1)
{
    asm volatile("mma.sync.aligned.m16n8k16.row.col.f32.bf16.bf16.f32 "
                 "{%0,%1,%2,%3},{%4,%5,%6,%7},{%8,%9},{%0,%1,%2,%3};"
                 : "+f"(d0), "+f"(d1), "+f"(d2), "+f"(d3)
                 : "r"(a0), "r"(a1), "r"(a2), "r"(a3), "r"(b0), "r"(b1));
}

#define LDSM4(r0, r1, r2, r3, addr) \
    asm volatile("ldmatrix.sync.aligned.m8n8.x4.shared.b16 {%0,%1,%2,%3}, [%4];" \
                 : "=r"(r0), "=r"(r1), "=r"(r2), "=r"(r3) : "r"(addr))

__device__ __forceinline__ void cpasync16(void* sdst, const void* gsrc) {
    uint32_t s = (uint32_t)__cvta_generic_to_shared(sdst);
    asm volatile("cp.async.cg.shared.global [%0], [%1], 16;" :: "r"(s), "l"(gsrc));
}
#define CP_COMMIT() asm volatile("cp.async.commit_group;")
#define CP_WAIT0()  asm volatile("cp.async.wait_group 0;")

__device__ __forceinline__ float ftanh_hw(float x) {
    float r;
    asm("tanh.approx.f32 %0, %1;" : "=f"(r) : "f"(x));
    return r;
}
__device__ __forceinline__ float fsig_hw(float x) {
    return fmaf(ftanh_hw(0.5f * x), 0.5f, 0.5f);
}
__device__ __forceinline__ float b2f(__nv_bfloat16 v) { return __bfloat162float(v); }

// swizzled smem index (elements): stride 64, XOR 8-col blocks by (row&7).
__device__ __forceinline__ int swzidx(int r, int c) {
    return r * 64 + ((((c >> 3) ^ (r & 7)) << 3) | (c & 7));
}

// ---------------- fused fc GEMM + weight splits + flag reset ---------------------
__global__ void __launch_bounds__(256) fc_prep(
    const float* __restrict__ z, const float* __restrict__ W_fc,
    const float* __restrict__ b_fc,
    const float* __restrict__ Whh_f, const float* __restrict__ Whh_b,
    const float* __restrict__ Wih_f, const float* __restrict__ Wih_b,
    const float* __restrict__ W1)
{
    __shared__ float As[16][65];
    __shared__ float Bs[16][65];
    if (blockIdx.x < 256) {
        const int N = ND, K = NDL;
        int tid = threadIdx.x;
        int tx = tid & 15, ty = tid >> 4;
        int m0 = (blockIdx.x >> 3) * 64, n0 = (blockIdx.x & 7) * 64;
        float acc[4][4] = {};
        for (int k0 = 0; k0 < K; k0 += 16) {
            #pragma unroll
            for (int i = 0; i < 4; i++) {
                int lin = tid + i * 256;
                int m = lin >> 4, k = lin & 15;
                As[k][m] = (k0 + k < K) ? z[(m0 + m) * K + k0 + k] : 0.f;
            }
            #pragma unroll
            for (int i = 0; i < 4; i++) {
                int lin = tid + i * 256;
                int n = lin >> 4, k = lin & 15;
                Bs[k][n] = (k0 + k < K) ? W_fc[(n0 + n) * K + k0 + k] : 0.f;
            }
            __syncthreads();
            #pragma unroll
            for (int kk = 0; kk < 16; kk++) {
                float a[4], b[4];
                #pragma unroll
                for (int i = 0; i < 4; i++) a[i] = As[kk][ty * 4 + i];
                #pragma unroll
                for (int j = 0; j < 4; j++) b[j] = Bs[kk][tx * 4 + j];
                #pragma unroll
                for (int i = 0; i < 4; i++)
                    #pragma unroll
                    for (int j = 0; j < 4; j++) acc[i][j] += a[i] * b[j];
            }
            __syncthreads();
        }
        #pragma unroll
        for (int i = 0; i < 4; i++) {
            int m = m0 + ty * 4 + i;
            #pragma unroll
            for (int j = 0; j < 4; j++) {
                int n = n0 + tx * 4 + j;
                g_h0[m * N + n] = acc[i][j] + b_fc[n];
            }
        }
    } else {
        int i = (blockIdx.x - 256) * 256 + threadIdx.x;
        bsplit(Wih_f[i], g_wihh[0][i], g_wihl[0][i]);
        bsplit(Wih_b[i], g_wihh[1][i], g_wihl[1][i]);
        if (i < 3 * NH * NH) {
            bsplit(Whh_f[i], g_whh[0][i], g_whl[0][i]);
            bsplit(Whh_b[i], g_whh[1][i], g_whl[1][i]);
        }
        if (i < NH * 2 * NH) bsplit(W1[i], g_w1h[i], g_w1l[i]);
        if (i < 2 * 16 * NT) g_sync[i] = 0;
    }
}

// ---------------- batchnorm stats -------------------------------------------------
__global__ void __launch_bounds__(256) bn_stats()
{
    int c = blockIdx.x;
    float s = 0.f, s2 = 0.f;
    for (int r = threadIdx.x; r < NB; r += 256) {
        float v = g_h0[r * ND + c];
        s += v; s2 += v * v;
    }
    __shared__ float sh[256], sh2[256];
    sh[threadIdx.x] = s; sh2[threadIdx.x] = s2;
    __syncthreads();
    for (int o = 128; o > 0; o >>= 1) {
        if (threadIdx.x < o) {
            sh[threadIdx.x]  += sh[threadIdx.x + o];
            sh2[threadIdx.x] += sh2[threadIdx.x + o];
        }
        __syncthreads();
    }
    if (threadIdx.x == 0) {
        float mu = sh[0] / (float)NB;
        g_stats[c] = mu;
        g_stats[ND + c] = sh2[0] / (float)NB - mu * mu;
    }
}

// ---------------- BN + LeakyReLU + bf16 hi/lo split -------------------------------
__global__ void __launch_bounds__(256) bn_apply_split(
    const float* __restrict__ bn_g, const float* __restrict__ bn_b)
{
    int i = blockIdx.x * 256 + threadIdx.x;
    int c = i & (ND - 1);
    float mu = g_stats[c], var = g_stats[ND + c];
    float v = (g_h0[i] - mu) * rsqrtf(var + 1e-5f) * bn_g[c] + bn_b[c];
    v = (v >= 0.f) ? v : 0.2f * v;
    bsplit(v, g_xh[i], g_xl[i]);
}

// ---------------- LDSM fragment loaders (verified in GRU) ------------------------
__device__ __forceinline__ void ldsm_afrags(
    uint32_t As_u32, uint32_t afr[4][4], int wm, int lane, int kk)
{
    const int g = lane >> 3, lr = lane & 7;
    const int scol = kk * 2 + (g >> 1);
    #pragma unroll
    for (int mt = 0; mt < 4; mt++) {
        const int row = wm * 64 + mt * 16 + ((g & 1) << 3) + lr;
        const uint32_t addr = As_u32 + row * 128 + ((scol ^ (row & 7)) << 4);
        LDSM4(afr[mt][0], afr[mt][1], afr[mt][2], afr[mt][3], addr);
    }
}

__device__ __forceinline__ void ldsmB8(
    uint32_t base, uint32_t bfr[8][2], int wj, int lane, int kk)
{
    const int g = lane >> 3, lr = lane & 7;
    const int scol = kk * 2 + (g & 1);
    #pragma unroll
    for (int q = 0; q < 4; q++) {
        const int nt = 2 * q + (g >> 1);
        const int row = wj * 64 + nt * 8 + lr;
        const uint32_t addr = base + row * 128 + ((scol ^ (row & 7)) << 4);
        LDSM4(bfr[2 * q][0], bfr[2 * q][1], bfr[2 * q + 1][0], bfr[2 * q + 1][1], addr);
    }
}

__device__ __forceinline__ void mma48(
    const uint32_t afr[4][4], const uint32_t bfr[8][2], float acc[4][8][4])
{
    #pragma unroll
    for (int mt = 0; mt < 4; mt++)
        #pragma unroll
        for (int nt = 0; nt < 8; nt++)
            mma16816(acc[mt][nt][0], acc[mt][nt][1], acc[mt][nt][2], acc[mt][nt][3],
                     afr[mt][0], afr[mt][1], afr[mt][2], afr[mt][3],
                     bfr[nt][0], bfr[nt][1]);
}

// ---------------- shared 128x256 x K=512 split-MMA cores -------------------------
#define AT_AS0 0
#define AT_AS1 8192
#define AT_BS0 16384
#define AT_BS1 32768
#define AT_SMEM_ELEMS 49152

// 3-term: Ah@(Bh+Bl) + Al@Bh (gate GEMM)
__device__ __forceinline__ void split_mma_128x256(
    const __nv_bfloat16* __restrict__ ah, const __nv_bfloat16* __restrict__ al,
    const __nv_bfloat16* __restrict__ bh, const __nv_bfloat16* __restrict__ bl,
    __nv_bfloat16* smem, float acc[4][8][4], int tid)
{
    const uint32_t s_u32 = (uint32_t)__cvta_generic_to_shared(smem);
    const uint32_t As0 = s_u32 + AT_AS0 * 2;
    const uint32_t As1 = s_u32 + AT_AS1 * 2;
    const uint32_t Bs0 = s_u32 + AT_BS0 * 2;
    const uint32_t Bs1 = s_u32 + AT_BS1 * 2;
    const int warp = tid >> 5, lane = tid & 31;
    const int wm = warp >> 2, wj = warp & 3;

    for (int ksi = 0; ksi < 8; ksi++) {
        const int ks = ksi * 64;
        if (ksi > 0) __syncthreads();
        #pragma unroll
        for (int i = 0; i < 4; i++) {
            int u = tid + 256 * i;
            int r = u >> 3, c = (u & 7) << 3;
            cpasync16(&smem[AT_AS0 + swzidx(r, c)], &ah[(size_t)r * 512 + ks + c]);
            cpasync16(&smem[AT_AS1 + swzidx(r, c)], &al[(size_t)r * 512 + ks + c]);
        }
        #pragma unroll
        for (int i = 0; i < 8; i++) {
            int u = tid + 256 * i;
            int r = u >> 3, c = (u & 7) << 3;
            cpasync16(&smem[AT_BS0 + swzidx(r, c)], &bh[(size_t)r * 512 + ks + c]);
            cpasync16(&smem[AT_BS1 + swzidx(r, c)], &bl[(size_t)r * 512 + ks + c]);
        }
        CP_COMMIT();
        CP_WAIT0();
        __syncthreads();
        #pragma unroll
        for (int kk = 0; kk < 4; kk++) {
            uint32_t afr[4][4], bfr[8][2];
            ldsm_afrags(As0, afr, wm, lane, kk);
            ldsmB8(Bs1, bfr, wj, lane, kk);
            mma48(afr, bfr, acc);
            ldsmB8(Bs0, bfr, wj, lane, kk);
            mma48(afr, bfr, acc);
            ldsm_afrags(As1, afr, wm, lane, kk);
            mma48(afr, bfr, acc);
        }
    }
}

// 2-term: Ah@(Bh+Bl) — used by attention (A's lo correction dropped; ~2^-9 rel).
__device__ __forceinline__ void split_mma_128x256_2t(
    const __nv_bfloat16* __restrict__ ah,
    const __nv_bfloat16* __restrict__ bh, const __nv_bfloat16* __restrict__ bl,
    __nv_bfloat16* smem, float acc[4][8][4], int tid)
{
    const uint32_t s_u32 = (uint32_t)__cvta_generic_to_shared(smem);
    const uint32_t As0 = s_u32 + AT_AS0 * 2;
    const uint32_t Bs0 = s_u32 + AT_BS0 * 2;
    const uint32_t Bs1 = s_u32 + AT_BS1 * 2;
    const int warp = tid >> 5, lane = tid & 31;
    const int wm = warp >> 2, wj = warp & 3;

    for (int ksi = 0; ksi < 8; ksi++) {
        const int ks = ksi * 64;
        if (ksi > 0) __syncthreads();
        #pragma unroll
        for (int i = 0; i < 4; i++) {
            int u = tid + 256 * i;
            int r = u >> 3, c = (u & 7) << 3;
            cpasync16(&smem[AT_AS0 + swzidx(r, c)], &ah[(size_t)r * 512 + ks + c]);
        }
        #pragma unroll
        for (int i = 0; i < 8; i++) {
            int u = tid + 256 * i;
            int r = u >> 3, c = (u & 7) << 3;
            cpasync16(&smem[AT_BS0 + swzidx(r, c)], &bh[(size_t)r * 512 + ks + c]);
            cpasync16(&smem[AT_BS1 + swzidx(r, c)], &bl[(size_t)r * 512 + ks + c]);
        }
        CP_COMMIT();
        CP_WAIT0();
        __syncthreads();
        #pragma unroll
        for (int kk = 0; kk < 4; kk++) {
            uint32_t afr[4][4], bfr[8][2];
            ldsm_afrags(As0, afr, wm, lane, kk);
            ldsmB8(Bs1, bfr, wj, lane, kk);
            mma48(afr, bfr, acc);
            ldsmB8(Bs0, bfr, wj, lane, kk);
            mma48(afr, bfr, acc);
        }
    }
}

// ---------------- gate GEMM on tensor cores (128x256 tiles, 3-term) --------------
__global__ void __launch_bounds__(256) gemm_gates_mma(
    const float* __restrict__ bf, const float* __restrict__ bb)
{
    extern __shared__ __nv_bfloat16 dynsm[];
    const int tid = threadIdx.x;
    const int ct = blockIdx.x;
    const int m0 = blockIdx.y * 128;
    const int dir = blockIdx.z;
    const float* bias = dir ? bb : bf;
    float* C = g_gates[dir];

    float acc[4][8][4];
    #pragma unroll
    for (int a = 0; a < 4; a++)
        #pragma unroll
        for (int b = 0; b < 8; b++)
            #pragma unroll
            for (int q = 0; q < 4; q++) acc[a][b][q] = 0.f;

    split_mma_128x256(g_xh + (size_t)m0 * 512, g_xl + (size_t)m0 * 512,
                      g_wihh[dir] + (size_t)ct * 256 * 512,
                      g_wihl[dir] + (size_t)ct * 256 * 512,
                      dynsm, acc, tid);

    const int warp = tid >> 5, lane = tid & 31;
    const int wm = warp >> 2, wj = warp & 3;
    const int gID = lane >> 2, tig = lane & 3;
    #pragma unroll
    for (int mt = 0; mt < 4; mt++)
        #pragma unroll
        for (int part = 0; part < 2; part++) {
            const int m = m0 + wm * 64 + mt * 16 + gID + part * 8;
            #pragma unroll
            for (int nt = 0; nt < 8; nt++)
                #pragma unroll
                for (int cc = 0; cc < 2; cc++) {
                    const int n = ct * 256 + wj * 64 + nt * 8 + tig * 2 + cc;
                    C[(size_t)m * 768 + n] = acc[mt][nt][part * 2 + cc] + bias[n];
                }
        }
}

// ---------------- attention scores (128x256 tiles, 2-term) -----------------------
__global__ void __launch_bounds__(256) attn_mma(
    const float* __restrict__ b1, const float* __restrict__ W2)
{
    extern __shared__ __nv_bfloat16 dynsm[];
    __shared__ float red[128];
    const int tid = threadIdx.x;
    const int m0 = blockIdx.x * 128;
    if (tid < 128) red[tid] = 0.f;

    float acc[4][8][4];
    #pragma unroll
    for (int a = 0; a < 4; a++)
        #pragma unroll
        for (int b = 0; b < 8; b++)
            #pragma unroll
            for (int q = 0; q < 4; q++) acc[a][b][q] = 0.f;

    split_mma_128x256_2t(g_gruh + (size_t)m0 * 512,
                         g_w1h, g_w1l, dynsm, acc, tid);

    const int warp = tid >> 5, lane = tid & 31;
    const int wm = warp >> 2, wj = warp & 3;
    const int gID = lane >> 2, tig = lane & 3;
    __syncthreads();
    #pragma unroll
    for (int mt = 0; mt < 4; mt++)
        #pragma unroll
        for (int part = 0; part < 2; part++) {
            float s = 0.f;
            #pragma unroll
            for (int nt = 0; nt < 8; nt++)
                #pragma unroll
                for (int cc = 0; cc < 2; cc++) {
                    int n = wj * 64 + nt * 8 + tig * 2 + cc;
                    s += ftanh_hw(acc[mt][nt][part * 2 + cc] + b1[n]) * W2[n];
                }
            s += __shfl_xor_sync(0xffffffffu, s, 1);
            s += __shfl_xor_sync(0xffffffffu, s, 2);
            if (tig == 0)
                atomicAdd(&red[wm * 64 + mt * 16 + gID + part * 8], s);
        }
    __syncthreads();
    if (tid < 128) g_s[m0 + tid] = red[tid];
}

// ---------------- GRU LDSM inner blocks ------------------------------------------
__device__ __forceinline__ void ldsm_bfrags(
    uint32_t Bs_u32, uint32_t bfr[6][2], int wj, int lane, int kk)
{
    const int g = lane >> 3, lr = lane & 7;
    const int scol = kk * 2 + (g & 1);
    #pragma unroll
    for (int q = 0; q < 3; q++) {
        const int nt = 2 * q + (g >> 1);
        const int row = (nt >> 1) * 64 + wj * 16 + (nt & 1) * 8 + lr;
        const uint32_t addr = Bs_u32 + row * 128 + ((scol ^ (row & 7)) << 4);
        LDSM4(bfr[2 * q][0], bfr[2 * q][1], bfr[2 * q + 1][0], bfr[2 * q + 1][1], addr);
    }
}

__device__ __forceinline__ void mma_all(
    const uint32_t afr[4][4], const uint32_t bfr[6][2], float acc[4][6][4])
{
    #pragma unroll
    for (int mt = 0; mt < 4; mt++)
        #pragma unroll
        for (int nt = 0; nt < 6; nt++)
            mma16816(acc[mt][nt][0], acc[mt][nt][1], acc[mt][nt][2], acc[mt][nt][3],
                     afr[mt][0], afr[mt][1], afr[mt][2], afr[mt][3],
                     bfr[nt][0], bfr[nt][1]);
}

__device__ __forceinline__ void mma_block2(
    uint32_t As_u32, uint32_t Bs1_u32, uint32_t Bs2_u32,
    float acc[4][6][4], int wm, int wj, int lane)
{
    #pragma unroll
    for (int kk = 0; kk < 4; kk++) {
        uint32_t afr[4][4], bfr[6][2];
        ldsm_afrags(As_u32, afr, wm, lane, kk);
        ldsm_bfrags(Bs1_u32, bfr, wj, lane, kk);
        mma_all(afr, bfr, acc);
        ldsm_bfrags(Bs2_u32, bfr, wj, lane, kk);
        mma_all(afr, bfr, acc);
    }
}

__device__ __forceinline__ void mma_block1(
    uint32_t As_u32, uint32_t Bs_u32,
    float acc[4][6][4], int wm, int wj, int lane)
{
    #pragma unroll
    for (int kk = 0; kk < 4; kk++) {
        uint32_t afr[4][4], bfr[6][2];
        ldsm_afrags(As_u32, afr, wm, lane, kk);
        ldsm_bfrags(Bs_u32, bfr, wj, lane, kk);
        mma_all(afr, bfr, acc);
    }
}

// ---------------- persistent GRU (ksl permuted so hold ends in smem) -------------
#define SLAB (192 * 64)
#define ATILE (128 * 64)
__global__ void __launch_bounds__(256) gru_persist(
    const float* __restrict__ bhh_f, const float* __restrict__ bhh_b)
{
    extern __shared__ __nv_bfloat16 smem[];
    __nv_bfloat16* Bsh = smem;
    __nv_bfloat16* Bsl = smem + 4 * SLAB;
    __nv_bfloat16* A0  = smem + 8 * SLAB;
    __nv_bfloat16* A1  = A0 + ATILE;
    const uint32_t Bsh_u32 = (uint32_t)__cvta_generic_to_shared(Bsh);
    const uint32_t Bsl_u32 = (uint32_t)__cvta_generic_to_shared(Bsl);
    const uint32_t A0_u32  = (uint32_t)__cvta_generic_to_shared(A0);
    const uint32_t A1_u32  = (uint32_t)__cvta_generic_to_shared(A1);
    const uint32_t SLAB_B  = SLAB * 2;

    const int bid = blockIdx.x;
    const int dir = bid >> 6;
    const int sub = bid & 63;
    const int j0 = (sub & 3) * 64;
    const int jslab = j0 >> 6;
    const int mtile = sub >> 2;
    const int m0 = mtile * 128;
    int* const flag = &g_sync[(dir * 16 + mtile) * NT];

    const float* bhh = dir ? bhh_b : bhh_f;
    const float* gin = g_gates[dir];
    const __nv_bfloat16* __restrict__ wh = g_whh[dir];
    const __nv_bfloat16* __restrict__ wl = g_whl[dir];

    const int tid = threadIdx.x;
    const int warp = tid >> 5, lane = tid & 31;
    const int wm = warp >> 2, wj = warp & 3;
    const int gID = lane >> 2, tig = lane & 3;

    int lr[4], lc[4];
    #pragma unroll
    for (int i = 0; i < 4; i++) {
        int u = tid + 256 * i;
        lr[i] = u >> 3; lc[i] = (u & 7) * 8;
    }

    #pragma unroll
    for (int i = 0; i < 24; i++) {
        int u = tid + 256 * i;
        int r = u >> 5;
        int c = (u & 31) * 8;
        int slab = c >> 6, cs = c & 63;
        int g = r >> 6, j = j0 + (r & 63);
        *(uint4*)&Bsh[slab * SLAB + swzidx(r, cs)] =
            *(const uint4*)&wh[(g * NH + j) * NH + c];
        *(uint4*)&Bsl[slab * SLAB + swzidx(r, cs)] =
            *(const uint4*)&wl[(g * NH + j) * NH + c];
    }
    __syncthreads();

    for (int t = 0; t < NT; t++) {
        const int tt  = dir ? (NT - 1 - t) : t;
        const int ttp = dir ? (NT - t) : (t - 1);

        float acc[4][6][4];
        #pragma unroll
        for (int a = 0; a < 4; a++)
            #pragma unroll
            for (int b = 0; b < 6; b++)
                #pragma unroll
                for (int q = 0; q < 4; q++) acc[a][b][q] = 0.f;

        if (t > 0) {
            if (tid == 0) {
                while (*(volatile int*)&flag[t - 1] < 4) { }
                __threadfence();
            }
            __syncthreads();

            const int ks0 = (((jslab + 1) & 3)) * 64;
            #pragma unroll
            for (int i = 0; i < 4; i++)
                cpasync16(&A0[swzidx(lr[i], lc[i])],
                          &g_gruh[((size_t)(m0 + lr[i]) * NT + ttp) * 512 + dir * NH + ks0 + lc[i]]);
            CP_COMMIT();
            for (int it = 0; it < 4; it++) {
                const int ksl = (jslab + 1 + it) & 3;
                const int ks = ksl * 64;
                CP_WAIT0(); __syncthreads();
                #pragma unroll
                for (int i = 0; i < 4; i++)
                    cpasync16(&A1[swzidx(lr[i], lc[i])],
                              &g_grul[((size_t)(m0 + lr[i]) * NT + ttp) * 512 + dir * NH + ks + lc[i]]);
                CP_COMMIT();
                mma_block2(A0_u32, Bsl_u32 + ksl * SLAB_B, Bsh_u32 + ksl * SLAB_B,
                           acc, wm, wj, lane);
                CP_WAIT0(); __syncthreads();
                if (it < 3) {
                    const int ksn = ((jslab + 2 + it) & 3) * 64;
                    #pragma unroll
                    for (int i = 0; i < 4; i++)
                        cpasync16(&A0[swzidx(lr[i], lc[i])],
                                  &g_gruh[((size_t)(m0 + lr[i]) * NT + ttp) * 512 + dir * NH + ksn + lc[i]]);
                    CP_COMMIT();
                }
                mma_block1(A1_u32, Bsh_u32 + ksl * SLAB_B, acc, wm, wj, lane);
            }
        }

        #pragma unroll
        for (int mt = 0; mt < 4; mt++)
            #pragma unroll
            for (int part = 0; part < 2; part++) {
                const int m = m0 + wm * 64 + mt * 16 + gID + part * 8;
                const int mrow = m - m0;
                #pragma unroll
                for (int jn = 0; jn < 2; jn++) {
                    const int jg = j0 + wj * 16 + jn * 8 + tig * 2;
                    float hn2[2];
                    #pragma unroll
                    for (int cc = 0; cc < 2; cc++) {
                        const int j = jg + cc;
                        float ghr = acc[mt][jn][part * 2 + cc]     + bhh[j];
                        float ghz = acc[mt][2 + jn][part * 2 + cc] + bhh[NH + j];
                        float ghn = acc[mt][4 + jn][part * 2 + cc] + bhh[2 * NH + j];
                        const float* gp = gin + m * 3 * NH + j;
                        float r  = fsig_hw(gp[0] + ghr);
                        float zz = fsig_hw(gp[NH] + ghz);
                        float nn = ftanh_hw(gp[2 * NH] + r * ghn);
                        float hold = 0.f;
                        if (t > 0) {
                            const int sw = swzidx(mrow, j & 63);
                            hold = b2f(A0[sw]) + b2f(A1[sw]);
                        }
                        hn2[cc] = (1.f - zz) * nn + zz * hold;
                    }
                    __nv_bfloat16 h0, l0, h1, l1;
                    bsplit(hn2[0], h0, l0);
                    bsplit(hn2[1], h1, l1);
                    __nv_bfloat162 vh, vl;
                    vh.x = h0; vh.y = h1; vl.x = l0; vl.y = l1;
                    size_t go = ((size_t)m * NT + tt) * 512 + dir * NH + jg;
                    *(__nv_bfloat162*)(g_gruh + go) = vh;
                    *(__nv_bfloat162*)(g_grul + go) = vl;
                }
            }

        if (t < NT - 1) {
            __syncthreads();
            if (tid == 0) {
                __threadfence();
                atomicAdd(&flag[t], 1);
            }
        }
    }
}

// ---------------- fused softmax + context + joint head + FK ----------------------
__global__ void __launch_bounds__(256) ctx_fk(
    const float* __restrict__ jW, const float* __restrict__ jb,
    float* __restrict__ out)
{
    const int b = blockIdx.x;
    const int tid = threadIdx.x;
    const int warp = tid >> 5, lane = tid & 31;

    __shared__ float jWs[6][512];
    __shared__ float w[NT];
    __shared__ float csh[512];
    __shared__ float p1sh[NT][8];
    __shared__ float cJ[8];

    for (int i = tid; i < 6 * 512; i += 256) jWs[i >> 9][i & 511] = jW[i];
    for (int i = tid; i < 512; i += 256) csh[i] = 0.f;
    if (tid == 0) {
        float mx = -1e30f;
        float tmpv[NT];
        for (int t = 0; t < NT; t++) {
            tmpv[t] = g_s[b * NT + t];
            if (tmpv[t] > mx) mx = tmpv[t];
        }
        float s = 0.f;
        for (int t = 0; t < NT; t++) { tmpv[t] = __expf(tmpv[t] - mx); s += tmpv[t]; }
        float inv = __fdividef(1.f, s);
        for (int t = 0; t < NT; t++) w[t] = tmpv[t] * inv;
    }
    __syncthreads();

    float creg[16];
    #pragma unroll
    for (int k = 0; k < 16; k++) creg[k] = 0.f;

    for (int t = warp; t < NT; t += 8) {
        const __nv_bfloat16* rh = g_gruh + ((size_t)b * NT + t) * 512;
        const __nv_bfloat16* rl = g_grul + ((size_t)b * NT + t) * 512;
        const float wt = w[t];
        float pj[6];
        #pragma unroll
        for (int j = 0; j < 6; j++) pj[j] = 0.f;
        #pragma unroll
        for (int k = 0; k < 16; k++) {
            const int d = lane + 32 * k;
            float x = b2f(rh[d]) + b2f(rl[d]);
            creg[k] += wt * x;
            #pragma unroll
            for (int j = 0; j < 6; j++) pj[j] += x * jWs[j][d];
        }
        #pragma unroll
        for (int o = 16; o > 0; o >>= 1)
            #pragma unroll
            for (int j = 0; j < 6; j++)
                pj[j] += __shfl_xor_sync(0xffffffffu, pj[j], o);
        if (lane == 0) {
            #pragma unroll
            for (int j = 0; j < 6; j++) p1sh[t][j] = pj[j];
        }
    }
    #pragma unroll
    for (int k = 0; k < 16; k++)
        atomicAdd(&csh[lane + 32 * k], creg[k]);
    __syncthreads();

    if (warp == 0) {
        float pj[6];
        #pragma unroll
        for (int j = 0; j < 6; j++) pj[j] = 0.f;
        #pragma unroll
        for (int k = 0; k < 16; k++) {
            const int d = lane + 32 * k;
            float cv = csh[d];
            #pragma unroll
            for (int j = 0; j < 6; j++) pj[j] += cv * jWs[j][d];
        }
        #pragma unroll
        for (int o = 16; o > 0; o >>= 1)
            #pragma unroll
            for (int j = 0; j < 6; j++)
                pj[j] += __shfl_xor_sync(0xffffffffu, pj[j], o);
        if (lane == 0) {
            #pragma unroll
            for (int j = 0; j < 6; j++) cJ[j] = pj[j];
        }
    }
    __syncthreads();

    if (tid < NT) {
        const int t = tid;
        const float LO[6] = {-3.1416f, -1.5708f, -3.1416f, -2.6f, -1.5708f, -1.2f};
        const float UP[6] = { 3.1416f,  1.5708f,  3.1416f,  0.1f,  1.5708f,  1.2f};
        float th[6];
        #pragma unroll
        for (int j = 0; j < 6; j++)
            th[j] = (p1sh[t][j] + cJ[j] + jb[j]) * (UP[j] - LO[j]) + LO[j];

        float c0[3] = {1.f, 0.f, 0.f}, c1[3] = {0.f, 1.f, 0.f}, c2[3] = {0.f, 0.f, 1.f};
        float px = 0.f, py = 0.f, pz = 0.10f;
        const float sh2x = 0.f, sh2y = 0.f, sh2z = 0.10f;

        float c, s, tmp;
        c = cosf(th[0]); s = sinf(th[0]);
        #pragma unroll
        for (int i = 0; i < 3; i++) { tmp = c*c0[i] + s*c1[i]; c1[i] = c*c1[i] - s*c0[i]; c0[i] = tmp; }
        c = cosf(th[1]); s = sinf(th[1]);
        #pragma unroll
        for (int i = 0; i < 3; i++) { tmp = c*c1[i] + s*c2[i]; c2[i] = c*c2[i] - s*c1[i]; c1[i] = tmp; }
        c = cosf(th[2]); s = sinf(th[2]);
        #pragma unroll
        for (int i = 0; i < 3; i++) { tmp = c*c0[i] - s*c2[i]; c2[i] = c*c2[i] + s*c0[i]; c0[i] = tmp; }
        px -= 0.25f * c1[0]; py -= 0.25f * c1[1]; pz -= 0.25f * c1[2];
        float fax = px, fay = py, faz = pz;
        c = cosf(th[3]); s = sinf(th[3]);
        #pragma unroll
        for (int i = 0; i < 3; i++) { tmp = c*c1[i] + s*c2[i]; c2[i] = c*c2[i] - s*c1[i]; c1[i] = tmp; }
        c = cosf(th[4]); s = sinf(th[4]);
        #pragma unroll
        for (int i = 0; i < 3; i++) { tmp = c*c0[i] - s*c2[i]; c2[i] = c*c2[i] + s*c0[i]; c0[i] = tmp; }
        px -= 0.25f * c1[0]; py -= 0.25f * c1[1]; pz -= 0.25f * c1[2];
        float wx = px, wy = py, wz = pz;
        c = cosf(th[5]); s = sinf(th[5]);
        #pragma unroll
        for (int i = 0; i < 3; i++) { tmp = c*c1[i] + s*c2[i]; c2[i] = c*c2[i] - s*c1[i]; c1[i] = tmp; }

        float f1x = wx - 0.08f*c1[0] + 0.02f*c2[0];
        float f1y = wy - 0.08f*c1[1] + 0.02f*c2[1];
        float f1z = wz - 0.08f*c1[2] + 0.02f*c2[2];
        float f4x = wx - 0.08f*c1[0] - 0.02f*c2[0];
        float f4y = wy - 0.08f*c1[1] - 0.02f*c2[1];
        float f4z = wz - 0.08f*c1[2] - 0.02f*c2[2];

        float d1x = sh2x - fax, d1y = sh2y - fay, d1z = sh2z - faz;
        float d2x = wx - fax,   d2y = wy - fay,   d2z = wz - faz;
        float bodyL = 0.5f * (sqrtf(d1x*d1x + d1y*d1y + d1z*d1z)
                            + sqrtf(d2x*d2x + d2y*d2y + d2z*d2z));
        float inv = 1.f / bodyL;

        float* o = out + ((size_t)b * NT + t) * 9;
        o[0] = (wx  - sh2x) * inv; o[1] = (wy  - sh2y) * inv; o[2] = (wz  - sh2z) * inv;
        o[3] = (f1x - sh2x) * inv; o[4] = (f1y - sh2y) * inv; o[5] = (f1z - sh2z) * inv;
        o[6] = (f4x - sh2x) * inv; o[7] = (f4y - sh2y) * inv; o[8] = (f4z - sh2z) * inv;
    }
}

// ---------------- host launcher ---------------------------------------------------
extern "C" void kernel_launch(void* const* d_in, const int* in_sizes, int n_in,
                              void* d_out, int out_size)
{
    const float* z       = (const float*)d_in[0];
    const float* W_fc    = (const float*)d_in[1];
    const float* b_fc    = (const float*)d_in[2];
    const float* bn_g    = (const float*)d_in[3];
    const float* bn_b    = (const float*)d_in[4];
    const float* Wih_f   = (const float*)d_in[5];
    const float* Whh_f   = (const float*)d_in[6];
    const float* bih_f   = (const float*)d_in[7];
    const float* bhh_f   = (const float*)d_in[8];
    const float* Wih_b   = (const float*)d_in[9];
    const float* Whh_b   = (const float*)d_in[10];
    const float* bih_b   = (const float*)d_in[11];
    const float* bhh_b   = (const float*)d_in[12];
    const float* attn_W1 = (const float*)d_in[13];
    const float* attn_b1 = (const float*)d_in[14];
    const float* attn_W2 = (const float*)d_in[15];
    const float* joint_W = (const float*)d_in[16];
    const float* joint_b = (const float*)d_in[17];
    float* out = (float*)d_out;

    static int smem_set = 0;
    const int gru_smem = (8 * SLAB + 2 * ATILE) * 2;
    const int at_smem = AT_SMEM_ELEMS * 2;             // 98304 bytes
    if (!smem_set) {
        cudaFuncSetAttribute(gru_persist,
            cudaFuncAttributeMaxDynamicSharedMemorySize, gru_smem);
        cudaFuncSetAttribute(attn_mma,
            cudaFuncAttributeMaxDynamicSharedMemorySize, at_smem);
        cudaFuncSetAttribute(gemm_gates_mma,
            cudaFuncAttributeMaxDynamicSharedMemorySize, at_smem);
        smem_set = 1;
    }

    // 1) fc GEMM + weight splits + flag reset
    fc_prep<<<1792, 256>>>(z, W_fc, b_fc, Whh_f, Whh_b, Wih_f, Wih_b, attn_W1);
    // 2) batch stats
    bn_stats<<<ND, 256>>>();
    // 3) BN + lrelu + bf16 split of x
    bn_apply_split<<<NB * ND / 256, 256>>>(bn_g, bn_b);
    // 4) gate GEMM on tensor cores (both dirs)
    gemm_gates_mma<<<dim3(3, NB / 128, 2), 256, at_smem>>>(bih_f, bih_b);
    // 5) GRU recurrence (persistent)
    gru_persist<<<128, 256, gru_smem>>>(bhh_f, bhh_b);
    // 6) attention scores (2-term split)
    attn_mma<<<NB * NT / 128, 256, at_smem>>>(attn_b1, attn_W2);
    // 7) fused softmax + context + joints + FK
    ctx_fk<<<NB, 256>>>(joint_W, joint_b, out);
}

// round 14
// speedup vs baseline: 2.2582x; 1.0152x over previous
#include <cuda_runtime.h>
#include <cuda_bf16.h>
#include <math.h>
#include <stdint.h>

#define NB   2048
#define NT   60
#define NDL  100
#define ND   512
#define NH   256

// ---------------- scratch (device globals) ----------------
__device__ float g_h0[NB * ND];
__device__ float g_stats[2 * ND];
__device__ float g_gates[2][NB * 3 * NH];          // x@Wih^T + bih (fp32)
__device__ __nv_bfloat16 g_xh[NB * ND];            // BN+lrelu x split hi
__device__ __nv_bfloat16 g_xl[NB * ND];            // BN+lrelu x split lo
__device__ __nv_bfloat16 g_whh[2][3 * NH * NH];    // Whh split hi
__device__ __nv_bfloat16 g_whl[2][3 * NH * NH];    // Whh split lo
__device__ __nv_bfloat16 g_wihh[2][3 * NH * ND];   // Wih split hi
__device__ __nv_bfloat16 g_wihl[2][3 * NH * ND];   // Wih split lo
__device__ __nv_bfloat16 g_w1h[NH * 2 * NH];       // attn_W1 split hi
__device__ __nv_bfloat16 g_w1l[NH * 2 * NH];       // attn_W1 split lo
__device__ __nv_bfloat16 g_gruh[NB * NT * 2 * NH]; // gru out bf16 hi (= state)
__device__ __nv_bfloat16 g_grul[NB * NT * 2 * NH]; // gru out bf16 lo
__device__ float g_s[NB * NT];
__device__ int   g_sync[2 * 16 * NT];              // group flags [dir][mtile][t]

__device__ __forceinline__ void bsplit(float v, __nv_bfloat16& h, __nv_bfloat16& l) {
    h = __float2bfloat16(v);
    l = __float2bfloat16(v - __bfloat162float(h));
}

__device__ __forceinline__ void mma16816(float& d0, float& d1, float& d2, float& d3,
    uint32_t a0, uint32_t a1, uint32_t a2, uint32_t a3, uint32_t b0, uint32_t b1)
{
    asm volatile("mma.sync.aligned.m16n8k16.row.col.f32.bf16.bf16.f32 "
                 "{%0,%1,%2,%3},{%4,%5,%6,%7},{%8,%9},{%0,%1,%2,%3};"
                 : "+f"(d0), "+f"(d1), "+f"(d2), "+f"(d3)
                 : "r"(a0), "r"(a1), "r"(a2), "r"(a3), "r"(b0), "r"(b1));
}

#define LDSM4(r0, r1, r2, r3, addr) \
    asm volatile("ldmatrix.sync.aligned.m8n8.x4.shared.b16 {%0,%1,%2,%3}, [%4];" \
                 : "=r"(r0), "=r"(r1), "=r"(r2), "=r"(r3) : "r"(addr))

__device__ __forceinline__ void cpasync16(void* sdst, const void* gsrc) {
    uint32_t s = (uint32_t)__cvta_generic_to_shared(sdst);
    asm volatile("cp.async.cg.shared.global [%0], [%1], 16;" :: "r"(s), "l"(gsrc));
}
#define CP_COMMIT() asm volatile("cp.async.commit_group;")
#define CP_WAIT0()  asm volatile("cp.async.wait_group 0;")
#define CP_WAIT1()  asm volatile("cp.async.wait_group 1;")

__device__ __forceinline__ float ftanh_hw(float x) {
    float r;
    asm("tanh.approx.f32 %0, %1;" : "=f"(r) : "f"(x));
    return r;
}
__device__ __forceinline__ float fsig_hw(float x) {
    return fmaf(ftanh_hw(0.5f * x), 0.5f, 0.5f);
}
__device__ __forceinline__ float b2f(__nv_bfloat16 v) { return __bfloat162float(v); }

// swizzled smem index (elements): stride 64, XOR 8-col blocks by (row&7).
__device__ __forceinline__ int swzidx(int r, int c) {
    return r * 64 + ((((c >> 3) ^ (r & 7)) << 3) | (c & 7));
}

// ---------------- fused fc GEMM + weight splits + flag reset ---------------------
__global__ void __launch_bounds__(256) fc_prep(
    const float* __restrict__ z, const float* __restrict__ W_fc,
    const float* __restrict__ b_fc,
    const float* __restrict__ Whh_f, const float* __restrict__ Whh_b,
    const float* __restrict__ Wih_f, const float* __restrict__ Wih_b,
    const float* __restrict__ W1)
{
    __shared__ float As[16][65];
    __shared__ float Bs[16][65];
    if (blockIdx.x < 256) {
        const int N = ND, K = NDL;
        int tid = threadIdx.x;
        int tx = tid & 15, ty = tid >> 4;
        int m0 = (blockIdx.x >> 3) * 64, n0 = (blockIdx.x & 7) * 64;
        float acc[4][4] = {};
        for (int k0 = 0; k0 < K; k0 += 16) {
            #pragma unroll
            for (int i = 0; i < 4; i++) {
                int lin = tid + i * 256;
                int m = lin >> 4, k = lin & 15;
                As[k][m] = (k0 + k < K) ? z[(m0 + m) * K + k0 + k] : 0.f;
            }
            #pragma unroll
            for (int i = 0; i < 4; i++) {
                int lin = tid + i * 256;
                int n = lin >> 4, k = lin & 15;
                Bs[k][n] = (k0 + k < K) ? W_fc[(n0 + n) * K + k0 + k] : 0.f;
            }
            __syncthreads();
            #pragma unroll
            for (int kk = 0; kk < 16; kk++) {
                float a[4], b[4];
                #pragma unroll
                for (int i = 0; i < 4; i++) a[i] = As[kk][ty * 4 + i];
                #pragma unroll
                for (int j = 0; j < 4; j++) b[j] = Bs[kk][tx * 4 + j];
                #pragma unroll
                for (int i = 0; i < 4; i++)
                    #pragma unroll
                    for (int j = 0; j < 4; j++) acc[i][j] += a[i] * b[j];
            }
            __syncthreads();
        }
        #pragma unroll
        for (int i = 0; i < 4; i++) {
            int m = m0 + ty * 4 + i;
            #pragma unroll
            for (int j = 0; j < 4; j++) {
                int n = n0 + tx * 4 + j;
                g_h0[m * N + n] = acc[i][j] + b_fc[n];
            }
        }
    } else {
        int i = (blockIdx.x - 256) * 256 + threadIdx.x;
        bsplit(Wih_f[i], g_wihh[0][i], g_wihl[0][i]);
        bsplit(Wih_b[i], g_wihh[1][i], g_wihl[1][i]);
        if (i < 3 * NH * NH) {
            bsplit(Whh_f[i], g_whh[0][i], g_whl[0][i]);
            bsplit(Whh_b[i], g_whh[1][i], g_whl[1][i]);
        }
        if (i < NH * 2 * NH) bsplit(W1[i], g_w1h[i], g_w1l[i]);
        if (i < 2 * 16 * NT) g_sync[i] = 0;
    }
}

// ---------------- batchnorm stats -------------------------------------------------
__global__ void __launch_bounds__(256) bn_stats()
{
    int c = blockIdx.x;
    float s = 0.f, s2 = 0.f;
    for (int r = threadIdx.x; r < NB; r += 256) {
        float v = g_h0[r * ND + c];
        s += v; s2 += v * v;
    }
    __shared__ float sh[256], sh2[256];
    sh[threadIdx.x] = s; sh2[threadIdx.x] = s2;
    __syncthreads();
    for (int o = 128; o > 0; o >>= 1) {
        if (threadIdx.x < o) {
            sh[threadIdx.x]  += sh[threadIdx.x + o];
            sh2[threadIdx.x] += sh2[threadIdx.x + o];
        }
        __syncthreads();
    }
    if (threadIdx.x == 0) {
        float mu = sh[0] / (float)NB;
        g_stats[c] = mu;
        g_stats[ND + c] = sh2[0] / (float)NB - mu * mu;
    }
}

// ---------------- BN + LeakyReLU + bf16 hi/lo split -------------------------------
__global__ void __launch_bounds__(256) bn_apply_split(
    const float* __restrict__ bn_g, const float* __restrict__ bn_b)
{
    int i = blockIdx.x * 256 + threadIdx.x;
    int c = i & (ND - 1);
    float mu = g_stats[c], var = g_stats[ND + c];
    float v = (g_h0[i] - mu) * rsqrtf(var + 1e-5f) * bn_g[c] + bn_b[c];
    v = (v >= 0.f) ? v : 0.2f * v;
    bsplit(v, g_xh[i], g_xl[i]);
}

// ---------------- LDSM fragment loaders ------------------------------------------
__device__ __forceinline__ void ldsm_afrags(
    uint32_t As_u32, uint32_t afr[4][4], int wm, int lane, int kk)
{
    const int g = lane >> 3, lr = lane & 7;
    const int scol = kk * 2 + (g >> 1);
    #pragma unroll
    for (int mt = 0; mt < 4; mt++) {
        const int row = wm * 64 + mt * 16 + ((g & 1) << 3) + lr;
        const uint32_t addr = As_u32 + row * 128 + ((scol ^ (row & 7)) << 4);
        LDSM4(afr[mt][0], afr[mt][1], afr[mt][2], afr[mt][3], addr);
    }
}

__device__ __forceinline__ void ldsmB8(
    uint32_t base, uint32_t bfr[8][2], int wj, int lane, int kk)
{
    const int g = lane >> 3, lr = lane & 7;
    const int scol = kk * 2 + (g & 1);
    #pragma unroll
    for (int q = 0; q < 4; q++) {
        const int nt = 2 * q + (g >> 1);
        const int row = wj * 64 + nt * 8 + lr;
        const uint32_t addr = base + row * 128 + ((scol ^ (row & 7)) << 4);
        LDSM4(bfr[2 * q][0], bfr[2 * q][1], bfr[2 * q + 1][0], bfr[2 * q + 1][1], addr);
    }
}

__device__ __forceinline__ void mma48(
    const uint32_t afr[4][4], const uint32_t bfr[8][2], float acc[4][8][4])
{
    #pragma unroll
    for (int mt = 0; mt < 4; mt++)
        #pragma unroll
        for (int nt = 0; nt < 8; nt++)
            mma16816(acc[mt][nt][0], acc[mt][nt][1], acc[mt][nt][2], acc[mt][nt][3],
                     afr[mt][0], afr[mt][1], afr[mt][2], afr[mt][3],
                     bfr[nt][0], bfr[nt][1]);
}

// ---------------- double-buffered 128x256 x K=512 split-MMA cores ----------------
// 3-term stage layout (elems): As0[8192] As1[8192] Bs0[16384] Bs1[16384] = 49152
#define ST3 49152
#define SM3_BYTES (2 * ST3 * 2)     // 196608
// 2-term stage layout: As0[8192] Bs0[16384] Bs1[16384] = 40960
#define ST2 40960
#define SM2_BYTES (2 * ST2 * 2)     // 163840

// 3-term: Ah@(Bh+Bl) + Al@Bh (gate GEMM)
__device__ __forceinline__ void split_mma_128x256(
    const __nv_bfloat16* __restrict__ ah, const __nv_bfloat16* __restrict__ al,
    const __nv_bfloat16* __restrict__ bh, const __nv_bfloat16* __restrict__ bl,
    __nv_bfloat16* smem, float acc[4][8][4], int tid)
{
    const uint32_t s_u32 = (uint32_t)__cvta_generic_to_shared(smem);
    const int warp = tid >> 5, lane = tid & 31;
    const int wm = warp >> 2, wj = warp & 3;

#define LOAD3(STG, KS) {                                                          \
    __nv_bfloat16* sb = smem + (STG) * ST3;                                       \
    _Pragma("unroll")                                                             \
    for (int i = 0; i < 4; i++) {                                                 \
        int u = tid + 256 * i;                                                    \
        int r = u >> 3, c = (u & 7) << 3;                                         \
        cpasync16(&sb[swzidx(r, c)],        &ah[(size_t)r * 512 + (KS) + c]);     \
        cpasync16(&sb[8192 + swzidx(r, c)], &al[(size_t)r * 512 + (KS) + c]);     \
    }                                                                             \
    _Pragma("unroll")                                                             \
    for (int i = 0; i < 8; i++) {                                                 \
        int u = tid + 256 * i;                                                    \
        int r = u >> 3, c = (u & 7) << 3;                                         \
        cpasync16(&sb[16384 + swzidx(r, c)], &bh[(size_t)r * 512 + (KS) + c]);    \
        cpasync16(&sb[32768 + swzidx(r, c)], &bl[(size_t)r * 512 + (KS) + c]);    \
    }                                                                             \
    CP_COMMIT(); }

    LOAD3(0, 0);
    for (int ksi = 0; ksi < 8; ksi++) {
        if (ksi > 0) __syncthreads();          // reads of buf[(ksi+1)&1] done
        if (ksi < 7) { LOAD3((ksi + 1) & 1, (ksi + 1) * 64); }
        if (ksi < 7) { CP_WAIT1(); } else { CP_WAIT0(); }
        __syncthreads();
        const uint32_t sb = s_u32 + ((ksi & 1) * ST3) * 2;
        const uint32_t As0 = sb, As1 = sb + 8192 * 2;
        const uint32_t Bs0 = sb + 16384 * 2, Bs1 = sb + 32768 * 2;
        #pragma unroll
        for (int kk = 0; kk < 4; kk++) {
            uint32_t afr[4][4], bfr[8][2];
            ldsm_afrags(As0, afr, wm, lane, kk);
            ldsmB8(Bs1, bfr, wj, lane, kk);
            mma48(afr, bfr, acc);
            ldsmB8(Bs0, bfr, wj, lane, kk);
            mma48(afr, bfr, acc);
            ldsm_afrags(As1, afr, wm, lane, kk);
            mma48(afr, bfr, acc);
        }
    }
#undef LOAD3
}

// 2-term: Ah@(Bh+Bl) — attention.
__device__ __forceinline__ void split_mma_128x256_2t(
    const __nv_bfloat16* __restrict__ ah,
    const __nv_bfloat16* __restrict__ bh, const __nv_bfloat16* __restrict__ bl,
    __nv_bfloat16* smem, float acc[4][8][4], int tid)
{
    const uint32_t s_u32 = (uint32_t)__cvta_generic_to_shared(smem);
    const int warp = tid >> 5, lane = tid & 31;
    const int wm = warp >> 2, wj = warp & 3;

#define LOAD2(STG, KS) {                                                          \
    __nv_bfloat16* sb = smem + (STG) * ST2;                                       \
    _Pragma("unroll")                                                             \
    for (int i = 0; i < 4; i++) {                                                 \
        int u = tid + 256 * i;                                                    \
        int r = u >> 3, c = (u & 7) << 3;                                         \
        cpasync16(&sb[swzidx(r, c)], &ah[(size_t)r * 512 + (KS) + c]);            \
    }                                                                             \
    _Pragma("unroll")                                                             \
    for (int i = 0; i < 8; i++) {                                                 \
        int u = tid + 256 * i;                                                    \
        int r = u >> 3, c = (u & 7) << 3;                                         \
        cpasync16(&sb[8192 + swzidx(r, c)],  &bh[(size_t)r * 512 + (KS) + c]);    \
        cpasync16(&sb[24576 + swzidx(r, c)], &bl[(size_t)r * 512 + (KS) + c]);    \
    }                                                                             \
    CP_COMMIT(); }

    LOAD2(0, 0);
    for (int ksi = 0; ksi < 8; ksi++) {
        if (ksi > 0) __syncthreads();
        if (ksi < 7) { LOAD2((ksi + 1) & 1, (ksi + 1) * 64); }
        if (ksi < 7) { CP_WAIT1(); } else { CP_WAIT0(); }
        __syncthreads();
        const uint32_t sb = s_u32 + ((ksi & 1) * ST2) * 2;
        const uint32_t As0 = sb;
        const uint32_t Bs0 = sb + 8192 * 2, Bs1 = sb + 24576 * 2;
        #pragma unroll
        for (int kk = 0; kk < 4; kk++) {
            uint32_t afr[4][4], bfr[8][2];
            ldsm_afrags(As0, afr, wm, lane, kk);
            ldsmB8(Bs1, bfr, wj, lane, kk);
            mma48(afr, bfr, acc);
            ldsmB8(Bs0, bfr, wj, lane, kk);
            mma48(afr, bfr, acc);
        }
    }
#undef LOAD2
}

// ---------------- gate GEMM on tensor cores (128x256 tiles, 3-term) --------------
__global__ void __launch_bounds__(256) gemm_gates_mma(
    const float* __restrict__ bf, const float* __restrict__ bb)
{
    extern __shared__ __nv_bfloat16 dynsm[];
    const int tid = threadIdx.x;
    const int ct = blockIdx.x;
    const int m0 = blockIdx.y * 128;
    const int dir = blockIdx.z;
    const float* bias = dir ? bb : bf;
    float* C = g_gates[dir];

    float acc[4][8][4];
    #pragma unroll
    for (int a = 0; a < 4; a++)
        #pragma unroll
        for (int b = 0; b < 8; b++)
            #pragma unroll
            for (int q = 0; q < 4; q++) acc[a][b][q] = 0.f;

    split_mma_128x256(g_xh + (size_t)m0 * 512, g_xl + (size_t)m0 * 512,
                      g_wihh[dir] + (size_t)ct * 256 * 512,
                      g_wihl[dir] + (size_t)ct * 256 * 512,
                      dynsm, acc, tid);

    const int warp = tid >> 5, lane = tid & 31;
    const int wm = warp >> 2, wj = warp & 3;
    const int gID = lane >> 2, tig = lane & 3;
    #pragma unroll
    for (int mt = 0; mt < 4; mt++)
        #pragma unroll
        for (int part = 0; part < 2; part++) {
            const int m = m0 + wm * 64 + mt * 16 + gID + part * 8;
            #pragma unroll
            for (int nt = 0; nt < 8; nt++)
                #pragma unroll
                for (int cc = 0; cc < 2; cc++) {
                    const int n = ct * 256 + wj * 64 + nt * 8 + tig * 2 + cc;
                    C[(size_t)m * 768 + n] = acc[mt][nt][part * 2 + cc] + bias[n];
                }
        }
}

// ---------------- attention scores (128x256 tiles, 2-term) -----------------------
__global__ void __launch_bounds__(256) attn_mma(
    const float* __restrict__ b1, const float* __restrict__ W2)
{
    extern __shared__ __nv_bfloat16 dynsm[];
    __shared__ float red[128];
    const int tid = threadIdx.x;
    const int m0 = blockIdx.x * 128;
    if (tid < 128) red[tid] = 0.f;

    float acc[4][8][4];
    #pragma unroll
    for (int a = 0; a < 4; a++)
        #pragma unroll
        for (int b = 0; b < 8; b++)
            #pragma unroll
            for (int q = 0; q < 4; q++) acc[a][b][q] = 0.f;

    split_mma_128x256_2t(g_gruh + (size_t)m0 * 512,
                         g_w1h, g_w1l, dynsm, acc, tid);

    const int warp = tid >> 5, lane = tid & 31;
    const int wm = warp >> 2, wj = warp & 3;
    const int gID = lane >> 2, tig = lane & 3;
    __syncthreads();
    #pragma unroll
    for (int mt = 0; mt < 4; mt++)
        #pragma unroll
        for (int part = 0; part < 2; part++) {
            float s = 0.f;
            #pragma unroll
            for (int nt = 0; nt < 8; nt++)
                #pragma unroll
                for (int cc = 0; cc < 2; cc++) {
                    int n = wj * 64 + nt * 8 + tig * 2 + cc;
                    s += ftanh_hw(acc[mt][nt][part * 2 + cc] + b1[n]) * W2[n];
                }
            s += __shfl_xor_sync(0xffffffffu, s, 1);
            s += __shfl_xor_sync(0xffffffffu, s, 2);
            if (tig == 0)
                atomicAdd(&red[wm * 64 + mt * 16 + gID + part * 8], s);
        }
    __syncthreads();
    if (tid < 128) g_s[m0 + tid] = red[tid];
}

// ---------------- GRU LDSM inner blocks ------------------------------------------
__device__ __forceinline__ void ldsm_bfrags(
    uint32_t Bs_u32, uint32_t bfr[6][2], int wj, int lane, int kk)
{
    const int g = lane >> 3, lr = lane & 7;
    const int scol = kk * 2 + (g & 1);
    #pragma unroll
    for (int q = 0; q < 3; q++) {
        const int nt = 2 * q + (g >> 1);
        const int row = (nt >> 1) * 64 + wj * 16 + (nt & 1) * 8 + lr;
        const uint32_t addr = Bs_u32 + row * 128 + ((scol ^ (row & 7)) << 4);
        LDSM4(bfr[2 * q][0], bfr[2 * q][1], bfr[2 * q + 1][0], bfr[2 * q + 1][1], addr);
    }
}

__device__ __forceinline__ void mma_all(
    const uint32_t afr[4][4], const uint32_t bfr[6][2], float acc[4][6][4])
{
    #pragma unroll
    for (int mt = 0; mt < 4; mt++)
        #pragma unroll
        for (int nt = 0; nt < 6; nt++)
            mma16816(acc[mt][nt][0], acc[mt][nt][1], acc[mt][nt][2], acc[mt][nt][3],
                     afr[mt][0], afr[mt][1], afr[mt][2], afr[mt][3],
                     bfr[nt][0], bfr[nt][1]);
}

__device__ __forceinline__ void mma_block2(
    uint32_t As_u32, uint32_t Bs1_u32, uint32_t Bs2_u32,
    float acc[4][6][4], int wm, int wj, int lane)
{
    #pragma unroll
    for (int kk = 0; kk < 4; kk++) {
        uint32_t afr[4][4], bfr[6][2];
        ldsm_afrags(As_u32, afr, wm, lane, kk);
        ldsm_bfrags(Bs1_u32, bfr, wj, lane, kk);
        mma_all(afr, bfr, acc);
        ldsm_bfrags(Bs2_u32, bfr, wj, lane, kk);
        mma_all(afr, bfr, acc);
    }
}

__device__ __forceinline__ void mma_block1(
    uint32_t As_u32, uint32_t Bs_u32,
    float acc[4][6][4], int wm, int wj, int lane)
{
    #pragma unroll
    for (int kk = 0; kk < 4; kk++) {
        uint32_t afr[4][4], bfr[6][2];
        ldsm_afrags(As_u32, afr, wm, lane, kk);
        ldsm_bfrags(Bs_u32, bfr, wj, lane, kk);
        mma_all(afr, bfr, acc);
    }
}

// ---------------- persistent GRU (unchanged from R13) ----------------------------
#define SLAB (192 * 64)
#define ATILE (128 * 64)
__global__ void __launch_bounds__(256) gru_persist(
    const float* __restrict__ bhh_f, const float* __restrict__ bhh_b)
{
    extern __shared__ __nv_bfloat16 smem[];
    __nv_bfloat16* Bsh = smem;
    __nv_bfloat16* Bsl = smem + 4 * SLAB;
    __nv_bfloat16* A0  = smem + 8 * SLAB;
    __nv_bfloat16* A1  = A0 + ATILE;
    const uint32_t Bsh_u32 = (uint32_t)__cvta_generic_to_shared(Bsh);
    const uint32_t Bsl_u32 = (uint32_t)__cvta_generic_to_shared(Bsl);
    const uint32_t A0_u32  = (uint32_t)__cvta_generic_to_shared(A0);
    const uint32_t A1_u32  = (uint32_t)__cvta_generic_to_shared(A1);
    const uint32_t SLAB_B  = SLAB * 2;

    const int bid = blockIdx.x;
    const int dir = bid >> 6;
    const int sub = bid & 63;
    const int j0 = (sub & 3) * 64;
    const int jslab = j0 >> 6;
    const int mtile = sub >> 2;
    const int m0 = mtile * 128;
    int* const flag = &g_sync[(dir * 16 + mtile) * NT];

    const float* bhh = dir ? bhh_b : bhh_f;
    const float* gin = g_gates[dir];
    const __nv_bfloat16* __restrict__ wh = g_whh[dir];
    const __nv_bfloat16* __restrict__ wl = g_whl[dir];

    const int tid = threadIdx.x;
    const int warp = tid >> 5, lane = tid & 31;
    const int wm = warp >> 2, wj = warp & 3;
    const int gID = lane >> 2, tig = lane & 3;

    int lr[4], lc[4];
    #pragma unroll
    for (int i = 0; i < 4; i++) {
        int u = tid + 256 * i;
        lr[i] = u >> 3; lc[i] = (u & 7) * 8;
    }

    #pragma unroll
    for (int i = 0; i < 24; i++) {
        int u = tid + 256 * i;
        int r = u >> 5;
        int c = (u & 31) * 8;
        int slab = c >> 6, cs = c & 63;
        int g = r >> 6, j = j0 + (r & 63);
        *(uint4*)&Bsh[slab * SLAB + swzidx(r, cs)] =
            *(const uint4*)&wh[(g * NH + j) * NH + c];
        *(uint4*)&Bsl[slab * SLAB + swzidx(r, cs)] =
            *(const uint4*)&wl[(g * NH + j) * NH + c];
    }
    __syncthreads();

    for (int t = 0; t < NT; t++) {
        const int tt  = dir ? (NT - 1 - t) : t;
        const int ttp = dir ? (NT - t) : (t - 1);

        float acc[4][6][4];
        #pragma unroll
        for (int a = 0; a < 4; a++)
            #pragma unroll
            for (int b = 0; b < 6; b++)
                #pragma unroll
                for (int q = 0; q < 4; q++) acc[a][b][q] = 0.f;

        if (t > 0) {
            if (tid == 0) {
                while (*(volatile int*)&flag[t - 1] < 4) { }
                __threadfence();
            }
            __syncthreads();

            const int ks0 = (((jslab + 1) & 3)) * 64;
            #pragma unroll
            for (int i = 0; i < 4; i++)
                cpasync16(&A0[swzidx(lr[i], lc[i])],
                          &g_gruh[((size_t)(m0 + lr[i]) * NT + ttp) * 512 + dir * NH + ks0 + lc[i]]);
            CP_COMMIT();
            for (int it = 0; it < 4; it++) {
                const int ksl = (jslab + 1 + it) & 3;
                const int ks = ksl * 64;
                CP_WAIT0(); __syncthreads();
                #pragma unroll
                for (int i = 0; i < 4; i++)
                    cpasync16(&A1[swzidx(lr[i], lc[i])],
                              &g_grul[((size_t)(m0 + lr[i]) * NT + ttp) * 512 + dir * NH + ks + lc[i]]);
                CP_COMMIT();
                mma_block2(A0_u32, Bsl_u32 + ksl * SLAB_B, Bsh_u32 + ksl * SLAB_B,
                           acc, wm, wj, lane);
                CP_WAIT0(); __syncthreads();
                if (it < 3) {
                    const int ksn = ((jslab + 2 + it) & 3) * 64;
                    #pragma unroll
                    for (int i = 0; i < 4; i++)
                        cpasync16(&A0[swzidx(lr[i], lc[i])],
                                  &g_gruh[((size_t)(m0 + lr[i]) * NT + ttp) * 512 + dir * NH + ksn + lc[i]]);
                    CP_COMMIT();
                }
                mma_block1(A1_u32, Bsh_u32 + ksl * SLAB_B, acc, wm, wj, lane);
            }
        }

        #pragma unroll
        for (int mt = 0; mt < 4; mt++)
            #pragma unroll
            for (int part = 0; part < 2; part++) {
                const int m = m0 + wm * 64 + mt * 16 + gID + part * 8;
                const int mrow = m - m0;
                #pragma unroll
                for (int jn = 0; jn < 2; jn++) {
                    const int jg = j0 + wj * 16 + jn * 8 + tig * 2;
                    float hn2[2];
                    #pragma unroll
                    for (int cc = 0; cc < 2; cc++) {
                        const int j = jg + cc;
                        float ghr = acc[mt][jn][part * 2 + cc]     + bhh[j];
                        float ghz = acc[mt][2 + jn][part * 2 + cc] + bhh[NH + j];
                        float ghn = acc[mt][4 + jn][part * 2 + cc] + bhh[2 * NH + j];
                        const float* gp = gin + m * 3 * NH + j;
                        float r  = fsig_hw(gp[0] + ghr);
                        float zz = fsig_hw(gp[NH] + ghz);
                        float nn = ftanh_hw(gp[2 * NH] + r * ghn);
                        float hold = 0.f;
                        if (t > 0) {
                            const int sw = swzidx(mrow, j & 63);
                            hold = b2f(A0[sw]) + b2f(A1[sw]);
                        }
                        hn2[cc] = (1.f - zz) * nn + zz * hold;
                    }
                    __nv_bfloat16 h0, l0, h1, l1;
                    bsplit(hn2[0], h0, l0);
                    bsplit(hn2[1], h1, l1);
                    __nv_bfloat162 vh, vl;
                    vh.x = h0; vh.y = h1; vl.x = l0; vl.y = l1;
                    size_t go = ((size_t)m * NT + tt) * 512 + dir * NH + jg;
                    *(__nv_bfloat162*)(g_gruh + go) = vh;
                    *(__nv_bfloat162*)(g_grul + go) = vl;
                }
            }

        if (t < NT - 1) {
            __syncthreads();
            if (tid == 0) {
                __threadfence();
                atomicAdd(&flag[t], 1);
            }
        }
    }
}

// ---------------- fused softmax + context + joint head + FK ----------------------
__global__ void __launch_bounds__(256) ctx_fk(
    const float* __restrict__ jW, const float* __restrict__ jb,
    float* __restrict__ out)
{
    const int b = blockIdx.x;
    const int tid = threadIdx.x;
    const int warp = tid >> 5, lane = tid & 31;

    __shared__ float jWs[6][512];
    __shared__ float w[NT];
    __shared__ float csh[512];
    __shared__ float p1sh[NT][8];
    __shared__ float cJ[8];

    for (int i = tid; i < 6 * 512; i += 256) jWs[i >> 9][i & 511] = jW[i];
    for (int i = tid; i < 512; i += 256) csh[i] = 0.f;
    if (tid == 0) {
        float mx = -1e30f;
        float tmpv[NT];
        for (int t = 0; t < NT; t++) {
            tmpv[t] = g_s[b * NT + t];
            if (tmpv[t] > mx) mx = tmpv[t];
        }
        float s = 0.f;
        for (int t = 0; t < NT; t++) { tmpv[t] = __expf(tmpv[t] - mx); s += tmpv[t]; }
        float inv = __fdividef(1.f, s);
        for (int t = 0; t < NT; t++) w[t] = tmpv[t] * inv;
    }
    __syncthreads();

    float creg[16];
    #pragma unroll
    for (int k = 0; k < 16; k++) creg[k] = 0.f;

    for (int t = warp; t < NT; t += 8) {
        const __nv_bfloat16* rh = g_gruh + ((size_t)b * NT + t) * 512;
        const __nv_bfloat16* rl = g_grul + ((size_t)b * NT + t) * 512;
        const float wt = w[t];
        float pj[6];
        #pragma unroll
        for (int j = 0; j < 6; j++) pj[j] = 0.f;
        #pragma unroll
        for (int k = 0; k < 16; k++) {
            const int d = lane + 32 * k;
            float x = b2f(rh[d]) + b2f(rl[d]);
            creg[k] += wt * x;
            #pragma unroll
            for (int j = 0; j < 6; j++) pj[j] += x * jWs[j][d];
        }
        #pragma unroll
        for (int o = 16; o > 0; o >>= 1)
            #pragma unroll
            for (int j = 0; j < 6; j++)
                pj[j] += __shfl_xor_sync(0xffffffffu, pj[j], o);
        if (lane == 0) {
            #pragma unroll
            for (int j = 0; j < 6; j++) p1sh[t][j] = pj[j];
        }
    }
    #pragma unroll
    for (int k = 0; k < 16; k++)
        atomicAdd(&csh[lane + 32 * k], creg[k]);
    __syncthreads();

    if (warp == 0) {
        float pj[6];
        #pragma unroll
        for (int j = 0; j < 6; j++) pj[j] = 0.f;
        #pragma unroll
        for (int k = 0; k < 16; k++) {
            const int d = lane + 32 * k;
            float cv = csh[d];
            #pragma unroll
            for (int j = 0; j < 6; j++) pj[j] += cv * jWs[j][d];
        }
        #pragma unroll
        for (int o = 16; o > 0; o >>= 1)
            #pragma unroll
            for (int j = 0; j < 6; j++)
                pj[j] += __shfl_xor_sync(0xffffffffu, pj[j], o);
        if (lane == 0) {
            #pragma unroll
            for (int j = 0; j < 6; j++) cJ[j] = pj[j];
        }
    }
    __syncthreads();

    if (tid < NT) {
        const int t = tid;
        const float LO[6] = {-3.1416f, -1.5708f, -3.1416f, -2.6f, -1.5708f, -1.2f};
        const float UP[6] = { 3.1416f,  1.5708f,  3.1416f,  0.1f,  1.5708f,  1.2f};
        float th[6];
        #pragma unroll
        for (int j = 0; j < 6; j++)
            th[j] = (p1sh[t][j] + cJ[j] + jb[j]) * (UP[j] - LO[j]) + LO[j];

        float c0[3] = {1.f, 0.f, 0.f}, c1[3] = {0.f, 1.f, 0.f}, c2[3] = {0.f, 0.f, 1.f};
        float px = 0.f, py = 0.f, pz = 0.10f;
        const float sh2x = 0.f, sh2y = 0.f, sh2z = 0.10f;

        float c, s, tmp;
        c = cosf(th[0]); s = sinf(th[0]);
        #pragma unroll
        for (int i = 0; i < 3; i++) { tmp = c*c0[i] + s*c1[i]; c1[i] = c*c1[i] - s*c0[i]; c0[i] = tmp; }
        c = cosf(th[1]); s = sinf(th[1]);
        #pragma unroll
        for (int i = 0; i < 3; i++) { tmp = c*c1[i] + s*c2[i]; c2[i] = c*c2[i] - s*c1[i]; c1[i] = tmp; }
        c = cosf(th[2]); s = sinf(th[2]);
        #pragma unroll
        for (int i = 0; i < 3; i++) { tmp = c*c0[i] - s*c2[i]; c2[i] = c*c2[i] + s*c0[i]; c0[i] = tmp; }
        px -= 0.25f * c1[0]; py -= 0.25f * c1[1]; pz -= 0.25f * c1[2];
        float fax = px, fay = py, faz = pz;
        c = cosf(th[3]); s = sinf(th[3]);
        #pragma unroll
        for (int i = 0; i < 3; i++) { tmp = c*c1[i] + s*c2[i]; c2[i] = c*c2[i] - s*c1[i]; c1[i] = tmp; }
        c = cosf(th[4]); s = sinf(th[4]);
        #pragma unroll
        for (int i = 0; i < 3; i++) { tmp = c*c0[i] - s*c2[i]; c2[i] = c*c2[i] + s*c0[i]; c0[i] = tmp; }
        px -= 0.25f * c1[0]; py -= 0.25f * c1[1]; pz -= 0.25f * c1[2];
        float wx = px, wy = py, wz = pz;
        c = cosf(th[5]); s = sinf(th[5]);
        #pragma unroll
        for (int i = 0; i < 3; i++) { tmp = c*c1[i] + s*c2[i]; c2[i] = c*c2[i] - s*c1[i]; c1[i] = tmp; }

        float f1x = wx - 0.08f*c1[0] + 0.02f*c2[0];
        float f1y = wy - 0.08f*c1[1] + 0.02f*c2[1];
        float f1z = wz - 0.08f*c1[2] + 0.02f*c2[2];
        float f4x = wx - 0.08f*c1[0] - 0.02f*c2[0];
        float f4y = wy - 0.08f*c1[1] - 0.02f*c2[1];
        float f4z = wz - 0.08f*c1[2] - 0.02f*c2[2];

        float d1x = sh2x - fax, d1y = sh2y - fay, d1z = sh2z - faz;
        float d2x = wx - fax,   d2y = wy - fay,   d2z = wz - faz;
        float bodyL = 0.5f * (sqrtf(d1x*d1x + d1y*d1y + d1z*d1z)
                            + sqrtf(d2x*d2x + d2y*d2y + d2z*d2z));
        float inv = 1.f / bodyL;

        float* o = out + ((size_t)b * NT + t) * 9;
        o[0] = (wx  - sh2x) * inv; o[1] = (wy  - sh2y) * inv; o[2] = (wz  - sh2z) * inv;
        o[3] = (f1x - sh2x) * inv; o[4] = (f1y - sh2y) * inv; o[5] = (f1z - sh2z) * inv;
        o[6] = (f4x - sh2x) * inv; o[7] = (f4y - sh2y) * inv; o[8] = (f4z - sh2z) * inv;
    }
}

// ---------------- host launcher ---------------------------------------------------
extern "C" void kernel_launch(void* const* d_in, const int* in_sizes, int n_in,
                              void* d_out, int out_size)
{
    const float* z       = (const float*)d_in[0];
    const float* W_fc    = (const float*)d_in[1];
    const float* b_fc    = (const float*)d_in[2];
    const float* bn_g    = (const float*)d_in[3];
    const float* bn_b    = (const float*)d_in[4];
    const float* Wih_f   = (const float*)d_in[5];
    const float* Whh_f   = (const float*)d_in[6];
    const float* bih_f   = (const float*)d_in[7];
    const float* bhh_f   = (const float*)d_in[8];
    const float* Wih_b   = (const float*)d_in[9];
    const float* Whh_b   = (const float*)d_in[10];
    const float* bih_b   = (const float*)d_in[11];
    const float* bhh_b   = (const float*)d_in[12];
    const float* attn_W1 = (const float*)d_in[13];
    const float* attn_b1 = (const float*)d_in[14];
    const float* attn_W2 = (const float*)d_in[15];
    const float* joint_W = (const float*)d_in[16];
    const float* joint_b = (const float*)d_in[17];
    float* out = (float*)d_out;

    static int smem_set = 0;
    const int gru_smem = (8 * SLAB + 2 * ATILE) * 2;
    if (!smem_set) {
        cudaFuncSetAttribute(gru_persist,
            cudaFuncAttributeMaxDynamicSharedMemorySize, gru_smem);
        cudaFuncSetAttribute(attn_mma,
            cudaFuncAttributeMaxDynamicSharedMemorySize, SM2_BYTES);
        cudaFuncSetAttribute(gemm_gates_mma,
            cudaFuncAttributeMaxDynamicSharedMemorySize, SM3_BYTES);
        smem_set = 1;
    }

    // 1) fc GEMM + weight splits + flag reset
    fc_prep<<<1792, 256>>>(z, W_fc, b_fc, Whh_f, Whh_b, Wih_f, Wih_b, attn_W1);
    // 2) batch stats
    bn_stats<<<ND, 256>>>();
    // 3) BN + lrelu + bf16 split of x
    bn_apply_split<<<NB * ND / 256, 256>>>(bn_g, bn_b);
    // 4) gate GEMM on tensor cores (double-buffered)
    gemm_gates_mma<<<dim3(3, NB / 128, 2), 256, SM3_BYTES>>>(bih_f, bih_b);
    // 5) GRU recurrence (persistent)
    gru_persist<<<128, 256, gru_smem>>>(bhh_f, bhh_b);
    // 6) attention scores (2-term, double-buffered)
    attn_mma<<<NB * NT / 128, 256, SM2_BYTES>>>(attn_b1, attn_W2);
    // 7) fused softmax + context + joints + FK
    ctx_fk<<<NB, 256>>>(joint_W, joint_b, out);
}

// round 15
// speedup vs baseline: 2.4185x; 1.0710x over previous
#include <cuda_runtime.h>
#include <cuda_bf16.h>
#include <math.h>
#include <stdint.h>

#define NB   2048
#define NT   60
#define NDL  100
#define ND   512
#define NH   256

// ---------------- scratch (device globals) ----------------
__device__ float g_h0[NB * ND];
__device__ float g_stats[2 * ND];
__device__ float g_gates[2][NB * 3 * NH];          // x@Wih^T + bih (fp32)
__device__ __nv_bfloat16 g_xh[NB * ND];            // BN+lrelu x split hi
__device__ __nv_bfloat16 g_xl[NB * ND];            // BN+lrelu x split lo
__device__ __nv_bfloat16 g_whh[2][3 * NH * NH];    // Whh split hi
__device__ __nv_bfloat16 g_whl[2][3 * NH * NH];    // Whh split lo
__device__ __nv_bfloat16 g_wihh[2][3 * NH * ND];   // Wih split hi
__device__ __nv_bfloat16 g_wihl[2][3 * NH * ND];   // Wih split lo
__device__ __nv_bfloat16 g_w1h[NH * 2 * NH];       // attn_W1 split hi
__device__ __nv_bfloat16 g_w1l[NH * 2 * NH];       // attn_W1 split lo
__device__ __nv_bfloat16 g_gruh[NB * NT * 2 * NH]; // gru out bf16 hi (= state)
__device__ __nv_bfloat16 g_grul[NB * NT * 2 * NH]; // gru out bf16 lo
__device__ float g_s[NB * NT];
__device__ float g_p1[NB * NT * 8];                // per-(b,t) joint dots row.jW
__device__ int   g_sync[2 * 16 * NT];              // group flags [dir][mtile][t]

__device__ __forceinline__ void bsplit(float v, __nv_bfloat16& h, __nv_bfloat16& l) {
    h = __float2bfloat16(v);
    l = __float2bfloat16(v - __bfloat162float(h));
}

__device__ __forceinline__ void mma16816(float& d0, float& d1, float& d2, float& d3,
    uint32_t a0, uint32_t a1, uint32_t a2, uint32_t a3, uint32_t b0, uint32_t b1)
{
    asm volatile("mma.sync.aligned.m16n8k16.row.col.f32.bf16.bf16.f32 "
                 "{%0,%1,%2,%3},{%4,%5,%6,%7},{%8,%9},{%0,%1,%2,%3};"
                 : "+f"(d0), "+f"(d1), "+f"(d2), "+f"(d3)
                 : "r"(a0), "r"(a1), "r"(a2), "r"(a3), "r"(b0), "r"(b1));
}

#define LDSM4(r0, r1, r2, r3, addr) \
    asm volatile("ldmatrix.sync.aligned.m8n8.x4.shared.b16 {%0,%1,%2,%3}, [%4];" \
                 : "=r"(r0), "=r"(r1), "=r"(r2), "=r"(r3) : "r"(addr))

__device__ __forceinline__ void cpasync16(void* sdst, const void* gsrc) {
    uint32_t s = (uint32_t)__cvta_generic_to_shared(sdst);
    asm volatile("cp.async.cg.shared.global [%0], [%1], 16;" :: "r"(s), "l"(gsrc));
}
#define CP_COMMIT() asm volatile("cp.async.commit_group;")
#define CP_WAIT0()  asm volatile("cp.async.wait_group 0;")
#define CP_WAIT1()  asm volatile("cp.async.wait_group 1;")

__device__ __forceinline__ float ftanh_hw(float x) {
    float r;
    asm("tanh.approx.f32 %0, %1;" : "=f"(r) : "f"(x));
    return r;
}
__device__ __forceinline__ float fsig_hw(float x) {
    return fmaf(ftanh_hw(0.5f * x), 0.5f, 0.5f);
}
__device__ __forceinline__ float b2f(__nv_bfloat16 v) { return __bfloat162float(v); }

// swizzled smem index (elements): stride 64, XOR 8-col blocks by (row&7).
__device__ __forceinline__ int swzidx(int r, int c) {
    return r * 64 + ((((c >> 3) ^ (r & 7)) << 3) | (c & 7));
}

// ---------------- fused fc GEMM + weight splits + flag reset ---------------------
__global__ void __launch_bounds__(256) fc_prep(
    const float* __restrict__ z, const float* __restrict__ W_fc,
    const float* __restrict__ b_fc,
    const float* __restrict__ Whh_f, const float* __restrict__ Whh_b,
    const float* __restrict__ Wih_f, const float* __restrict__ Wih_b,
    const float* __restrict__ W1)
{
    __shared__ float As[16][65];
    __shared__ float Bs[16][65];
    if (blockIdx.x < 256) {
        const int N = ND, K = NDL;
        int tid = threadIdx.x;
        int tx = tid & 15, ty = tid >> 4;
        int m0 = (blockIdx.x >> 3) * 64, n0 = (blockIdx.x & 7) * 64;
        float acc[4][4] = {};
        for (int k0 = 0; k0 < K; k0 += 16) {
            #pragma unroll
            for (int i = 0; i < 4; i++) {
                int lin = tid + i * 256;
                int m = lin >> 4, k = lin & 15;
                As[k][m] = (k0 + k < K) ? z[(m0 + m) * K + k0 + k] : 0.f;
            }
            #pragma unroll
            for (int i = 0; i < 4; i++) {
                int lin = tid + i * 256;
                int n = lin >> 4, k = lin & 15;
                Bs[k][n] = (k0 + k < K) ? W_fc[(n0 + n) * K + k0 + k] : 0.f;
            }
            __syncthreads();
            #pragma unroll
            for (int kk = 0; kk < 16; kk++) {
                float a[4], b[4];
                #pragma unroll
                for (int i = 0; i < 4; i++) a[i] = As[kk][ty * 4 + i];
                #pragma unroll
                for (int j = 0; j < 4; j++) b[j] = Bs[kk][tx * 4 + j];
                #pragma unroll
                for (int i = 0; i < 4; i++)
                    #pragma unroll
                    for (int j = 0; j < 4; j++) acc[i][j] += a[i] * b[j];
            }
            __syncthreads();
        }
        #pragma unroll
        for (int i = 0; i < 4; i++) {
            int m = m0 + ty * 4 + i;
            #pragma unroll
            for (int j = 0; j < 4; j++) {
                int n = n0 + tx * 4 + j;
                g_h0[m * N + n] = acc[i][j] + b_fc[n];
            }
        }
    } else {
        int i = (blockIdx.x - 256) * 256 + threadIdx.x;
        bsplit(Wih_f[i], g_wihh[0][i], g_wihl[0][i]);
        bsplit(Wih_b[i], g_wihh[1][i], g_wihl[1][i]);
        if (i < 3 * NH * NH) {
            bsplit(Whh_f[i], g_whh[0][i], g_whl[0][i]);
            bsplit(Whh_b[i], g_whh[1][i], g_whl[1][i]);
        }
        if (i < NH * 2 * NH) bsplit(W1[i], g_w1h[i], g_w1l[i]);
        if (i < 2 * 16 * NT) g_sync[i] = 0;
    }
}

// ---------------- batchnorm stats -------------------------------------------------
__global__ void __launch_bounds__(256) bn_stats()
{
    int c = blockIdx.x;
    float s = 0.f, s2 = 0.f;
    for (int r = threadIdx.x; r < NB; r += 256) {
        float v = g_h0[r * ND + c];
        s += v; s2 += v * v;
    }
    __shared__ float sh[256], sh2[256];
    sh[threadIdx.x] = s; sh2[threadIdx.x] = s2;
    __syncthreads();
    for (int o = 128; o > 0; o >>= 1) {
        if (threadIdx.x < o) {
            sh[threadIdx.x]  += sh[threadIdx.x + o];
            sh2[threadIdx.x] += sh2[threadIdx.x + o];
        }
        __syncthreads();
    }
    if (threadIdx.x == 0) {
        float mu = sh[0] / (float)NB;
        g_stats[c] = mu;
        g_stats[ND + c] = sh2[0] / (float)NB - mu * mu;
    }
}

// ---------------- BN + LeakyReLU + bf16 hi/lo split -------------------------------
__global__ void __launch_bounds__(256) bn_apply_split(
    const float* __restrict__ bn_g, const float* __restrict__ bn_b)
{
    int i = blockIdx.x * 256 + threadIdx.x;
    int c = i & (ND - 1);
    float mu = g_stats[c], var = g_stats[ND + c];
    float v = (g_h0[i] - mu) * rsqrtf(var + 1e-5f) * bn_g[c] + bn_b[c];
    v = (v >= 0.f) ? v : 0.2f * v;
    bsplit(v, g_xh[i], g_xl[i]);
}

// ---------------- LDSM fragment loaders ------------------------------------------
__device__ __forceinline__ void ldsm_afrags(
    uint32_t As_u32, uint32_t afr[4][4], int wm, int lane, int kk)
{
    const int g = lane >> 3, lr = lane & 7;
    const int scol = kk * 2 + (g >> 1);
    #pragma unroll
    for (int mt = 0; mt < 4; mt++) {
        const int row = wm * 64 + mt * 16 + ((g & 1) << 3) + lr;
        const uint32_t addr = As_u32 + row * 128 + ((scol ^ (row & 7)) << 4);
        LDSM4(afr[mt][0], afr[mt][1], afr[mt][2], afr[mt][3], addr);
    }
}

__device__ __forceinline__ void ldsmB8(
    uint32_t base, uint32_t bfr[8][2], int wj, int lane, int kk)
{
    const int g = lane >> 3, lr = lane & 7;
    const int scol = kk * 2 + (g & 1);
    #pragma unroll
    for (int q = 0; q < 4; q++) {
        const int nt = 2 * q + (g >> 1);
        const int row = wj * 64 + nt * 8 + lr;
        const uint32_t addr = base + row * 128 + ((scol ^ (row & 7)) << 4);
        LDSM4(bfr[2 * q][0], bfr[2 * q][1], bfr[2 * q + 1][0], bfr[2 * q + 1][1], addr);
    }
}

__device__ __forceinline__ void mma48(
    const uint32_t afr[4][4], const uint32_t bfr[8][2], float acc[4][8][4])
{
    #pragma unroll
    for (int mt = 0; mt < 4; mt++)
        #pragma unroll
        for (int nt = 0; nt < 8; nt++)
            mma16816(acc[mt][nt][0], acc[mt][nt][1], acc[mt][nt][2], acc[mt][nt][3],
                     afr[mt][0], afr[mt][1], afr[mt][2], afr[mt][3],
                     bfr[nt][0], bfr[nt][1]);
}

// ---------------- double-buffered 128x256 x K=512 split-MMA ----------------------
// stage layout (elems): As0[8192] As1[8192] Bs0[16384] Bs1[16384] = 49152
#define ST3 49152
#define SM3_BYTES (2 * ST3 * 2)     // 196608

// 3-term: Ah@(Bh+Bl) + Al@Bh (gate GEMM)
__device__ __forceinline__ void split_mma_128x256(
    const __nv_bfloat16* __restrict__ ah, const __nv_bfloat16* __restrict__ al,
    const __nv_bfloat16* __restrict__ bh, const __nv_bfloat16* __restrict__ bl,
    __nv_bfloat16* smem, float acc[4][8][4], int tid)
{
    const uint32_t s_u32 = (uint32_t)__cvta_generic_to_shared(smem);
    const int warp = tid >> 5, lane = tid & 31;
    const int wm = warp >> 2, wj = warp & 3;

#define LOAD3(STG, KS) {                                                          \
    __nv_bfloat16* sb = smem + (STG) * ST3;                                       \
    _Pragma("unroll")                                                             \
    for (int i = 0; i < 4; i++) {                                                 \
        int u = tid + 256 * i;                                                    \
        int r = u >> 3, c = (u & 7) << 3;                                         \
        cpasync16(&sb[swzidx(r, c)],        &ah[(size_t)r * 512 + (KS) + c]);     \
        cpasync16(&sb[8192 + swzidx(r, c)], &al[(size_t)r * 512 + (KS) + c]);     \
    }                                                                             \
    _Pragma("unroll")                                                             \
    for (int i = 0; i < 8; i++) {                                                 \
        int u = tid + 256 * i;                                                    \
        int r = u >> 3, c = (u & 7) << 3;                                         \
        cpasync16(&sb[16384 + swzidx(r, c)], &bh[(size_t)r * 512 + (KS) + c]);    \
        cpasync16(&sb[32768 + swzidx(r, c)], &bl[(size_t)r * 512 + (KS) + c]);    \
    }                                                                             \
    CP_COMMIT(); }

    LOAD3(0, 0);
    for (int ksi = 0; ksi < 8; ksi++) {
        if (ksi > 0) __syncthreads();
        if (ksi < 7) { LOAD3((ksi + 1) & 1, (ksi + 1) * 64); }
        if (ksi < 7) { CP_WAIT1(); } else { CP_WAIT0(); }
        __syncthreads();
        const uint32_t sb = s_u32 + ((ksi & 1) * ST3) * 2;
        const uint32_t As0 = sb, As1 = sb + 8192 * 2;
        const uint32_t Bs0 = sb + 16384 * 2, Bs1 = sb + 32768 * 2;
        #pragma unroll
        for (int kk = 0; kk < 4; kk++) {
            uint32_t afr[4][4], bfr[8][2];
            ldsm_afrags(As0, afr, wm, lane, kk);
            ldsmB8(Bs1, bfr, wj, lane, kk);
            mma48(afr, bfr, acc);
            ldsmB8(Bs0, bfr, wj, lane, kk);
            mma48(afr, bfr, acc);
            ldsm_afrags(As1, afr, wm, lane, kk);
            mma48(afr, bfr, acc);
        }
    }
}

// ---------------- gate GEMM on tensor cores (128x256 tiles, 3-term) --------------
__global__ void __launch_bounds__(256) gemm_gates_mma(
    const float* __restrict__ bf, const float* __restrict__ bb)
{
    extern __shared__ __nv_bfloat16 dynsm[];
    const int tid = threadIdx.x;
    const int ct = blockIdx.x;
    const int m0 = blockIdx.y * 128;
    const int dir = blockIdx.z;
    const float* bias = dir ? bb : bf;
    float* C = g_gates[dir];

    float acc[4][8][4];
    #pragma unroll
    for (int a = 0; a < 4; a++)
        #pragma unroll
        for (int b = 0; b < 8; b++)
            #pragma unroll
            for (int q = 0; q < 4; q++) acc[a][b][q] = 0.f;

    split_mma_128x256(g_xh + (size_t)m0 * 512, g_xl + (size_t)m0 * 512,
                      g_wihh[dir] + (size_t)ct * 256 * 512,
                      g_wihl[dir] + (size_t)ct * 256 * 512,
                      dynsm, acc, tid);

    const int warp = tid >> 5, lane = tid & 31;
    const int wm = warp >> 2, wj = warp & 3;
    const int gID = lane >> 2, tig = lane & 3;
    #pragma unroll
    for (int mt = 0; mt < 4; mt++)
        #pragma unroll
        for (int part = 0; part < 2; part++) {
            const int m = m0 + wm * 64 + mt * 16 + gID + part * 8;
            #pragma unroll
            for (int nt = 0; nt < 8; nt++)
                #pragma unroll
                for (int cc = 0; cc < 2; cc++) {
                    const int n = ct * 256 + wj * 64 + nt * 8 + tig * 2 + cc;
                    C[(size_t)m * 768 + n] = acc[mt][nt][part * 2 + cc] + bias[n];
                }
        }
}

// ---------------- attention + fused joint dots -----------------------------------
// MMA: 2-term (Ah@(Bh+Bl)). Also computes exact p1[m] = (hi+lo row).jW per row.
__global__ void __launch_bounds__(256) attn_mma(
    const float* __restrict__ b1, const float* __restrict__ W2,
    const float* __restrict__ jW)
{
    extern __shared__ __nv_bfloat16 dynsm[];
    __shared__ float jWs[6][512];
    __shared__ float red[128];
    __shared__ float p1s[256][6];

    const int tid = threadIdx.x;
    const int m0 = blockIdx.x * 128;
    for (int i = tid; i < 6 * 512; i += 256) jWs[i >> 9][i & 511] = jW[i];
    if (tid < 128) red[tid] = 0.f;

    float acc[4][8][4];
    #pragma unroll
    for (int a = 0; a < 4; a++)
        #pragma unroll
        for (int b = 0; b < 8; b++)
            #pragma unroll
            for (int q = 0; q < 4; q++) acc[a][b][q] = 0.f;
    float p1a[6];
    #pragma unroll
    for (int j = 0; j < 6; j++) p1a[j] = 0.f;

    const uint32_t s_u32 = (uint32_t)__cvta_generic_to_shared(dynsm);
    const int warp = tid >> 5, lane = tid & 31;
    const int wm = warp >> 2, wj = warp & 3;
    const int prow = tid & 127;            // p1 pass: row
    const int pcolb = (tid >> 7) * 32;     // p1 pass: col half

    const __nv_bfloat16* __restrict__ ah = g_gruh + (size_t)m0 * 512;
    const __nv_bfloat16* __restrict__ al = g_grul + (size_t)m0 * 512;
    const __nv_bfloat16* __restrict__ bh = g_w1h;
    const __nv_bfloat16* __restrict__ bl = g_w1l;

#define ALOAD3(STG, KS) {                                                         \
    __nv_bfloat16* sb = dynsm + (STG) * ST3;                                      \
    _Pragma("unroll")                                                             \
    for (int i = 0; i < 4; i++) {                                                 \
        int u = tid + 256 * i;                                                    \
        int r = u >> 3, c = (u & 7) << 3;                                         \
        cpasync16(&sb[swzidx(r, c)],        &ah[(size_t)r * 512 + (KS) + c]);     \
        cpasync16(&sb[8192 + swzidx(r, c)], &al[(size_t)r * 512 + (KS) + c]);     \
    }                                                                             \
    _Pragma("unroll")                                                             \
    for (int i = 0; i < 8; i++) {                                                 \
        int u = tid + 256 * i;                                                    \
        int r = u >> 3, c = (u & 7) << 3;                                         \
        cpasync16(&sb[16384 + swzidx(r, c)], &bh[(size_t)r * 512 + (KS) + c]);    \
        cpasync16(&sb[32768 + swzidx(r, c)], &bl[(size_t)r * 512 + (KS) + c]);    \
    }                                                                             \
    CP_COMMIT(); }

    ALOAD3(0, 0);
    for (int ksi = 0; ksi < 8; ksi++) {
        if (ksi > 0) __syncthreads();
        if (ksi < 7) { ALOAD3((ksi + 1) & 1, (ksi + 1) * 64); }
        if (ksi < 7) { CP_WAIT1(); } else { CP_WAIT0(); }
        __syncthreads();
        const uint32_t sb = s_u32 + ((ksi & 1) * ST3) * 2;
        const uint32_t As0 = sb;
        const uint32_t Bs0 = sb + 16384 * 2, Bs1 = sb + 32768 * 2;
        #pragma unroll
        for (int kk = 0; kk < 4; kk++) {
            uint32_t afr[4][4], bfr[8][2];
            ldsm_afrags(As0, afr, wm, lane, kk);
            ldsmB8(Bs1, bfr, wj, lane, kk);
            mma48(afr, bfr, acc);
            ldsmB8(Bs0, bfr, wj, lane, kk);
            mma48(afr, bfr, acc);
        }
        // p1 pass: exact (hi+lo) row dot jW for this 64-col slab
        {
            const __nv_bfloat16* stq = dynsm + (ksi & 1) * ST3;
            const int ks = ksi * 64;
            #pragma unroll
            for (int q = 0; q < 4; q++) {
                const int cb = pcolb + q * 8;
                const int off = swzidx(prow, cb);
                uint4 vh = *(const uint4*)&stq[off];
                uint4 vl = *(const uint4*)&stq[8192 + off];
                const __nv_bfloat16* ph = (const __nv_bfloat16*)&vh;
                const __nv_bfloat16* pl = (const __nv_bfloat16*)&vl;
                #pragma unroll
                for (int e = 0; e < 8; e++) {
                    float x = b2f(ph[e]) + b2f(pl[e]);
                    const int col = ks + cb + e;
                    #pragma unroll
                    for (int j = 0; j < 6; j++) p1a[j] += x * jWs[j][col];
                }
            }
        }
    }
#undef ALOAD3

    #pragma unroll
    for (int j = 0; j < 6; j++) p1s[tid][j] = p1a[j];

    const int gID = lane >> 2, tig = lane & 3;
    __syncthreads();
    #pragma unroll
    for (int mt = 0; mt < 4; mt++)
        #pragma unroll
        for (int part = 0; part < 2; part++) {
            float s = 0.f;
            #pragma unroll
            for (int nt = 0; nt < 8; nt++)
                #pragma unroll
                for (int cc = 0; cc < 2; cc++) {
                    int n = wj * 64 + nt * 8 + tig * 2 + cc;
                    s += ftanh_hw(acc[mt][nt][part * 2 + cc] + b1[n]) * W2[n];
                }
            s += __shfl_xor_sync(0xffffffffu, s, 1);
            s += __shfl_xor_sync(0xffffffffu, s, 2);
            if (tig == 0)
                atomicAdd(&red[wm * 64 + mt * 16 + gID + part * 8], s);
        }
    __syncthreads();
    if (tid < 128) {
        g_s[m0 + tid] = red[tid];
        #pragma unroll
        for (int j = 0; j < 6; j++)
            g_p1[(size_t)(m0 + tid) * 8 + j] = p1s[tid][j] + p1s[tid + 128][j];
    }
}

// ---------------- GRU LDSM inner blocks ------------------------------------------
__device__ __forceinline__ void ldsm_bfrags(
    uint32_t Bs_u32, uint32_t bfr[6][2], int wj, int lane, int kk)
{
    const int g = lane >> 3, lr = lane & 7;
    const int scol = kk * 2 + (g & 1);
    #pragma unroll
    for (int q = 0; q < 3; q++) {
        const int nt = 2 * q + (g >> 1);
        const int row = (nt >> 1) * 64 + wj * 16 + (nt & 1) * 8 + lr;
        const uint32_t addr = Bs_u32 + row * 128 + ((scol ^ (row & 7)) << 4);
        LDSM4(bfr[2 * q][0], bfr[2 * q][1], bfr[2 * q + 1][0], bfr[2 * q + 1][1], addr);
    }
}

__device__ __forceinline__ void mma_all(
    const uint32_t afr[4][4], const uint32_t bfr[6][2], float acc[4][6][4])
{
    #pragma unroll
    for (int mt = 0; mt < 4; mt++)
        #pragma unroll
        for (int nt = 0; nt < 6; nt++)
            mma16816(acc[mt][nt][0], acc[mt][nt][1], acc[mt][nt][2], acc[mt][nt][3],
                     afr[mt][0], afr[mt][1], afr[mt][2], afr[mt][3],
                     bfr[nt][0], bfr[nt][1]);
}

__device__ __forceinline__ void mma_block2(
    uint32_t As_u32, uint32_t Bs1_u32, uint32_t Bs2_u32,
    float acc[4][6][4], int wm, int wj, int lane)
{
    #pragma unroll
    for (int kk = 0; kk < 4; kk++) {
        uint32_t afr[4][4], bfr[6][2];
        ldsm_afrags(As_u32, afr, wm, lane, kk);
        ldsm_bfrags(Bs1_u32, bfr, wj, lane, kk);
        mma_all(afr, bfr, acc);
        ldsm_bfrags(Bs2_u32, bfr, wj, lane, kk);
        mma_all(afr, bfr, acc);
    }
}

__device__ __forceinline__ void mma_block1(
    uint32_t As_u32, uint32_t Bs_u32,
    float acc[4][6][4], int wm, int wj, int lane)
{
    #pragma unroll
    for (int kk = 0; kk < 4; kk++) {
        uint32_t afr[4][4], bfr[6][2];
        ldsm_afrags(As_u32, afr, wm, lane, kk);
        ldsm_bfrags(Bs_u32, bfr, wj, lane, kk);
        mma_all(afr, bfr, acc);
    }
}

// ---------------- persistent GRU (unchanged) -------------------------------------
#define SLAB (192 * 64)
#define ATILE (128 * 64)
__global__ void __launch_bounds__(256) gru_persist(
    const float* __restrict__ bhh_f, const float* __restrict__ bhh_b)
{
    extern __shared__ __nv_bfloat16 smem[];
    __nv_bfloat16* Bsh = smem;
    __nv_bfloat16* Bsl = smem + 4 * SLAB;
    __nv_bfloat16* A0  = smem + 8 * SLAB;
    __nv_bfloat16* A1  = A0 + ATILE;
    const uint32_t Bsh_u32 = (uint32_t)__cvta_generic_to_shared(Bsh);
    const uint32_t Bsl_u32 = (uint32_t)__cvta_generic_to_shared(Bsl);
    const uint32_t A0_u32  = (uint32_t)__cvta_generic_to_shared(A0);
    const uint32_t A1_u32  = (uint32_t)__cvta_generic_to_shared(A1);
    const uint32_t SLAB_B  = SLAB * 2;

    const int bid = blockIdx.x;
    const int dir = bid >> 6;
    const int sub = bid & 63;
    const int j0 = (sub & 3) * 64;
    const int jslab = j0 >> 6;
    const int mtile = sub >> 2;
    const int m0 = mtile * 128;
    int* const flag = &g_sync[(dir * 16 + mtile) * NT];

    const float* bhh = dir ? bhh_b : bhh_f;
    const float* gin = g_gates[dir];
    const __nv_bfloat16* __restrict__ wh = g_whh[dir];
    const __nv_bfloat16* __restrict__ wl = g_whl[dir];

    const int tid = threadIdx.x;
    const int warp = tid >> 5, lane = tid & 31;
    const int wm = warp >> 2, wj = warp & 3;
    const int gID = lane >> 2, tig = lane & 3;

    int lr[4], lc[4];
    #pragma unroll
    for (int i = 0; i < 4; i++) {
        int u = tid + 256 * i;
        lr[i] = u >> 3; lc[i] = (u & 7) * 8;
    }

    #pragma unroll
    for (int i = 0; i < 24; i++) {
        int u = tid + 256 * i;
        int r = u >> 5;
        int c = (u & 31) * 8;
        int slab = c >> 6, cs = c & 63;
        int g = r >> 6, j = j0 + (r & 63);
        *(uint4*)&Bsh[slab * SLAB + swzidx(r, cs)] =
            *(const uint4*)&wh[(g * NH + j) * NH + c];
        *(uint4*)&Bsl[slab * SLAB + swzidx(r, cs)] =
            *(const uint4*)&wl[(g * NH + j) * NH + c];
    }
    __syncthreads();

    for (int t = 0; t < NT; t++) {
        const int tt  = dir ? (NT - 1 - t) : t;
        const int ttp = dir ? (NT - t) : (t - 1);

        float acc[4][6][4];
        #pragma unroll
        for (int a = 0; a < 4; a++)
            #pragma unroll
            for (int b = 0; b < 6; b++)
                #pragma unroll
                for (int q = 0; q < 4; q++) acc[a][b][q] = 0.f;

        if (t > 0) {
            if (tid == 0) {
                while (*(volatile int*)&flag[t - 1] < 4) { }
                __threadfence();
            }
            __syncthreads();

            const int ks0 = (((jslab + 1) & 3)) * 64;
            #pragma unroll
            for (int i = 0; i < 4; i++)
                cpasync16(&A0[swzidx(lr[i], lc[i])],
                          &g_gruh[((size_t)(m0 + lr[i]) * NT + ttp) * 512 + dir * NH + ks0 + lc[i]]);
            CP_COMMIT();
            for (int it = 0; it < 4; it++) {
                const int ksl = (jslab + 1 + it) & 3;
                const int ks = ksl * 64;
                CP_WAIT0(); __syncthreads();
                #pragma unroll
                for (int i = 0; i < 4; i++)
                    cpasync16(&A1[swzidx(lr[i], lc[i])],
                              &g_grul[((size_t)(m0 + lr[i]) * NT + ttp) * 512 + dir * NH + ks + lc[i]]);
                CP_COMMIT();
                mma_block2(A0_u32, Bsl_u32 + ksl * SLAB_B, Bsh_u32 + ksl * SLAB_B,
                           acc, wm, wj, lane);
                CP_WAIT0(); __syncthreads();
                if (it < 3) {
                    const int ksn = ((jslab + 2 + it) & 3) * 64;
                    #pragma unroll
                    for (int i = 0; i < 4; i++)
                        cpasync16(&A0[swzidx(lr[i], lc[i])],
                                  &g_gruh[((size_t)(m0 + lr[i]) * NT + ttp) * 512 + dir * NH + ksn + lc[i]]);
                    CP_COMMIT();
                }
                mma_block1(A1_u32, Bsh_u32 + ksl * SLAB_B, acc, wm, wj, lane);
            }
        }

        #pragma unroll
        for (int mt = 0; mt < 4; mt++)
            #pragma unroll
            for (int part = 0; part < 2; part++) {
                const int m = m0 + wm * 64 + mt * 16 + gID + part * 8;
                const int mrow = m - m0;
                #pragma unroll
                for (int jn = 0; jn < 2; jn++) {
                    const int jg = j0 + wj * 16 + jn * 8 + tig * 2;
                    float hn2[2];
                    #pragma unroll
                    for (int cc = 0; cc < 2; cc++) {
                        const int j = jg + cc;
                        float ghr = acc[mt][jn][part * 2 + cc]     + bhh[j];
                        float ghz = acc[mt][2 + jn][part * 2 + cc] + bhh[NH + j];
                        float ghn = acc[mt][4 + jn][part * 2 + cc] + bhh[2 * NH + j];
                        const float* gp = gin + m * 3 * NH + j;
                        float r  = fsig_hw(gp[0] + ghr);
                        float zz = fsig_hw(gp[NH] + ghz);
                        float nn = ftanh_hw(gp[2 * NH] + r * ghn);
                        float hold = 0.f;
                        if (t > 0) {
                            const int sw = swzidx(mrow, j & 63);
                            hold = b2f(A0[sw]) + b2f(A1[sw]);
                        }
                        hn2[cc] = (1.f - zz) * nn + zz * hold;
                    }
                    __nv_bfloat16 h0, l0, h1, l1;
                    bsplit(hn2[0], h0, l0);
                    bsplit(hn2[1], h1, l1);
                    __nv_bfloat162 vh, vl;
                    vh.x = h0; vh.y = h1; vl.x = l0; vl.y = l1;
                    size_t go = ((size_t)m * NT + tt) * 512 + dir * NH + jg;
                    *(__nv_bfloat162*)(g_gruh + go) = vh;
                    *(__nv_bfloat162*)(g_grul + go) = vl;
                }
            }

        if (t < NT - 1) {
            __syncthreads();
            if (tid == 0) {
                __threadfence();
                atomicAdd(&flag[t], 1);
            }
        }
    }
}

// ---------------- tiny tail: softmax + cJ + FK (no gru reads) --------------------
__global__ void __launch_bounds__(64) ctx_fk(
    const float* __restrict__ jb, float* __restrict__ out)
{
    const int b = blockIdx.x;
    const int tid = threadIdx.x;
    __shared__ float w[NT];
    __shared__ float cJ[6];
    if (tid < 6) cJ[tid] = 0.f;
    if (tid == 0) {
        float mx = -1e30f;
        float tmpv[NT];
        for (int t = 0; t < NT; t++) {
            tmpv[t] = g_s[b * NT + t];
            if (tmpv[t] > mx) mx = tmpv[t];
        }
        float s = 0.f;
        for (int t = 0; t < NT; t++) { tmpv[t] = __expf(tmpv[t] - mx); s += tmpv[t]; }
        float inv = __fdividef(1.f, s);
        for (int t = 0; t < NT; t++) w[t] = tmpv[t] * inv;
    }
    __syncthreads();

    float pj[6];
    if (tid < NT) {
        const float* p1 = &g_p1[(size_t)(b * NT + tid) * 8];
        #pragma unroll
        for (int j = 0; j < 6; j++) {
            pj[j] = p1[j];
            atomicAdd(&cJ[j], w[tid] * pj[j]);
        }
    }
    __syncthreads();

    if (tid < NT) {
        const float LO[6] = {-3.1416f, -1.5708f, -3.1416f, -2.6f, -1.5708f, -1.2f};
        const float UP[6] = { 3.1416f,  1.5708f,  3.1416f,  0.1f,  1.5708f,  1.2f};
        float th[6];
        #pragma unroll
        for (int j = 0; j < 6; j++)
            th[j] = (pj[j] + cJ[j] + jb[j]) * (UP[j] - LO[j]) + LO[j];

        float c0[3] = {1.f, 0.f, 0.f}, c1[3] = {0.f, 1.f, 0.f}, c2[3] = {0.f, 0.f, 1.f};
        float px = 0.f, py = 0.f, pz = 0.10f;
        const float sh2x = 0.f, sh2y = 0.f, sh2z = 0.10f;

        float c, s, tmp;
        c = cosf(th[0]); s = sinf(th[0]);
        #pragma unroll
        for (int i = 0; i < 3; i++) { tmp = c*c0[i] + s*c1[i]; c1[i] = c*c1[i] - s*c0[i]; c0[i] = tmp; }
        c = cosf(th[1]); s = sinf(th[1]);
        #pragma unroll
        for (int i = 0; i < 3; i++) { tmp = c*c1[i] + s*c2[i]; c2[i] = c*c2[i] - s*c1[i]; c1[i] = tmp; }
        c = cosf(th[2]); s = sinf(th[2]);
        #pragma unroll
        for (int i = 0; i < 3; i++) { tmp = c*c0[i] - s*c2[i]; c2[i] = c*c2[i] + s*c0[i]; c0[i] = tmp; }
        px -= 0.25f * c1[0]; py -= 0.25f * c1[1]; pz -= 0.25f * c1[2];
        float fax = px, fay = py, faz = pz;
        c = cosf(th[3]); s = sinf(th[3]);
        #pragma unroll
        for (int i = 0; i < 3; i++) { tmp = c*c1[i] + s*c2[i]; c2[i] = c*c2[i] - s*c1[i]; c1[i] = tmp; }
        c = cosf(th[4]); s = sinf(th[4]);
        #pragma unroll
        for (int i = 0; i < 3; i++) { tmp = c*c0[i] - s*c2[i]; c2[i] = c*c2[i] + s*c0[i]; c0[i] = tmp; }
        px -= 0.25f * c1[0]; py -= 0.25f * c1[1]; pz -= 0.25f * c1[2];
        float wx = px, wy = py, wz = pz;
        c = cosf(th[5]); s = sinf(th[5]);
        #pragma unroll
        for (int i = 0; i < 3; i++) { tmp = c*c1[i] + s*c2[i]; c2[i] = c*c2[i] - s*c1[i]; c1[i] = tmp; }

        float f1x = wx - 0.08f*c1[0] + 0.02f*c2[0];
        float f1y = wy - 0.08f*c1[1] + 0.02f*c2[1];
        float f1z = wz - 0.08f*c1[2] + 0.02f*c2[2];
        float f4x = wx - 0.08f*c1[0] - 0.02f*c2[0];
        float f4y = wy - 0.08f*c1[1] - 0.02f*c2[1];
        float f4z = wz - 0.08f*c1[2] - 0.02f*c2[2];

        float d1x = sh2x - fax, d1y = sh2y - fay, d1z = sh2z - faz;
        float d2x = wx - fax,   d2y = wy - fay,   d2z = wz - faz;
        float bodyL = 0.5f * (sqrtf(d1x*d1x + d1y*d1y + d1z*d1z)
                            + sqrtf(d2x*d2x + d2y*d2y + d2z*d2z));
        float inv = 1.f / bodyL;

        float* o = out + ((size_t)b * NT + tid) * 9;
        o[0] = (wx  - sh2x) * inv; o[1] = (wy  - sh2y) * inv; o[2] = (wz  - sh2z) * inv;
        o[3] = (f1x - sh2x) * inv; o[4] = (f1y - sh2y) * inv; o[5] = (f1z - sh2z) * inv;
        o[6] = (f4x - sh2x) * inv; o[7] = (f4y - sh2y) * inv; o[8] = (f4z - sh2z) * inv;
    }
}

// ---------------- host launcher ---------------------------------------------------
extern "C" void kernel_launch(void* const* d_in, const int* in_sizes, int n_in,
                              void* d_out, int out_size)
{
    const float* z       = (const float*)d_in[0];
    const float* W_fc    = (const float*)d_in[1];
    const float* b_fc    = (const float*)d_in[2];
    const float* bn_g    = (const float*)d_in[3];
    const float* bn_b    = (const float*)d_in[4];
    const float* Wih_f   = (const float*)d_in[5];
    const float* Whh_f   = (const float*)d_in[6];
    const float* bih_f   = (const float*)d_in[7];
    const float* bhh_f   = (const float*)d_in[8];
    const float* Wih_b   = (const float*)d_in[9];
    const float* Whh_b   = (const float*)d_in[10];
    const float* bih_b   = (const float*)d_in[11];
    const float* bhh_b   = (const float*)d_in[12];
    const float* attn_W1 = (const float*)d_in[13];
    const float* attn_b1 = (const float*)d_in[14];
    const float* attn_W2 = (const float*)d_in[15];
    const float* joint_W = (const float*)d_in[16];
    const float* joint_b = (const float*)d_in[17];
    float* out = (float*)d_out;

    static int smem_set = 0;
    const int gru_smem = (8 * SLAB + 2 * ATILE) * 2;
    if (!smem_set) {
        cudaFuncSetAttribute(gru_persist,
            cudaFuncAttributeMaxDynamicSharedMemorySize, gru_smem);
        cudaFuncSetAttribute(attn_mma,
            cudaFuncAttributeMaxDynamicSharedMemorySize, SM3_BYTES);
        cudaFuncSetAttribute(gemm_gates_mma,
            cudaFuncAttributeMaxDynamicSharedMemorySize, SM3_BYTES);
        smem_set = 1;
    }

    // 1) fc GEMM + weight splits + flag reset
    fc_prep<<<1792, 256>>>(z, W_fc, b_fc, Whh_f, Whh_b, Wih_f, Wih_b, attn_W1);
    // 2) batch stats
    bn_stats<<<ND, 256>>>();
    // 3) BN + lrelu + bf16 split of x
    bn_apply_split<<<NB * ND / 256, 256>>>(bn_g, bn_b);
    // 4) gate GEMM on tensor cores
    gemm_gates_mma<<<dim3(3, NB / 128, 2), 256, SM3_BYTES>>>(bih_f, bih_b);
    // 5) GRU recurrence (persistent)
    gru_persist<<<128, 256, gru_smem>>>(bhh_f, bhh_b);
    // 6) attention scores + fused joint dots (single pass over gru rows)
    attn_mma<<<NB * NT / 128, 256, SM3_BYTES>>>(attn_b1, attn_W2, joint_W);
    // 7) tiny tail: softmax + cJ + FK
    ctx_fk<<<NB, 64>>>(joint_b, out);
}